// round 9
// baseline (speedup 1.0000x reference)
#include <cuda_runtime.h>
#include <math.h>

#define IMG 96
#define PSZ 8
#define GD 12
#define CDIM 768
#define NHEAD 8
#define HD 96
#define NPATCH 1728
#define NTOK 1729
#define BQ 2
#define NCLS 3

// ---------------- scratch (device globals) ----------------
__device__ float g_pat [(size_t)BQ * NPATCH * 512];
__device__ float g_tmp [(size_t)BQ * NPATCH * CDIM];
__device__ float g_x   [(size_t)BQ * NTOK * CDIM];
__device__ float g_wqkv[(size_t)3 * CDIM * CDIM];
__device__ float g_bqkv[3 * CDIM];
__device__ float g_qkv [(size_t)BQ * NTOK * 3 * CDIM];
__device__ float g_x2  [(size_t)BQ * NTOK * CDIM];
__device__ float g_kv  [(size_t)BQ * NTOK * 2 * CDIM];
__device__ float g_q0  [BQ * CDIM];
__device__ float g_oc  [BQ * CDIM];
__device__ float g_fin [BQ * CDIM];

__device__ __forceinline__ float to_tf32(float x) {
    unsigned u;
    asm("cvt.rna.tf32.f32 %0, %1;" : "=r"(u) : "f"(x));
    return __uint_as_float(u);
}

__device__ __forceinline__ float4 ld4_guard(const float* __restrict__ p, int gk, int K) {
    if (gk + 3 < K) return *(const float4*)(p + gk);
    float4 v = make_float4(0.f, 0.f, 0.f, 0.f);
    if (gk     < K) v.x = p[gk];
    if (gk + 1 < K) v.y = p[gk + 1];
    if (gk + 2 < K) v.z = p[gk + 2];
    return v;
}

__device__ __forceinline__ void mma_tf32(float* c, const unsigned* a, const unsigned* b) {
    asm("mma.sync.aligned.m16n8k8.row.col.f32.tf32.tf32.f32 "
        "{%0,%1,%2,%3}, {%4,%5,%6,%7}, {%8,%9}, {%0,%1,%2,%3};"
        : "+f"(c[0]), "+f"(c[1]), "+f"(c[2]), "+f"(c[3])
        : "r"(a[0]), "r"(a[1]), "r"(a[2]), "r"(a[3]), "r"(b[0]), "r"(b[1]));
}

// ---- 128x128x16 double-buffered GEMM on tf32 mma.sync (m16n8k8), fp32 accum ----
template <int TRANS_B>
__global__ void __launch_bounds__(256, 2)
gemm_k(const float* __restrict__ A, const float* __restrict__ Bm,
       const float* __restrict__ bias, float* __restrict__ Cm,
       int M, int Nn, int K, int lda, int ldb, int ldc,
       size_t sAb, size_t sAh, size_t sBb, size_t sBh,
       size_t sCb, size_t sCh, int nh,
       float alphaC, const float* __restrict__ alphaPtr, int accum)
{
    int z = blockIdx.z;
    int bb = z / nh, hh = z % nh;
    A  += (size_t)bb * sAb + (size_t)hh * sAh;
    Bm += (size_t)bb * sBb + (size_t)hh * sBh;
    Cm += (size_t)bb * sCb + (size_t)hh * sCh;

    __shared__ __align__(16) float As[2][16][136];
    __shared__ __align__(16) float Bs[2][16][136];

    int tid = threadIdx.x;
    int m0 = blockIdx.y * 128, n0 = blockIdx.x * 128;

    int ar = tid >> 2;
    int ak = (tid & 3) * 4;
    int bk = tid >> 5;
    int bc = (tid & 31) * 4;

    int wid = tid >> 5, lane = tid & 31;
    int wm = (wid & 1) * 64, wn = (wid >> 1) * 32;
    int grp = lane >> 2, qid = lane & 3;

    float acc[4][4][4];
#pragma unroll
    for (int i = 0; i < 4; i++)
#pragma unroll
        for (int j = 0; j < 4; j++)
#pragma unroll
            for (int r = 0; r < 4; r++) acc[i][j][r] = 0.f;

    float4 pa[2], pb[2];
    int ktiles = (K + 15) / 16;

    {
        int k0 = 0;
#pragma unroll
        for (int h = 0; h < 2; h++) {
            int gm = m0 + ar + h * 64;
            pa[h] = (gm < M) ? ld4_guard(A + (size_t)gm * lda, k0 + ak, K)
                             : make_float4(0.f, 0.f, 0.f, 0.f);
        }
        if (TRANS_B) {
#pragma unroll
            for (int h = 0; h < 2; h++) {
                int gn = n0 + ar + h * 64;
                pb[h] = (gn < Nn) ? ld4_guard(Bm + (size_t)gn * ldb, k0 + ak, K)
                                  : make_float4(0.f, 0.f, 0.f, 0.f);
            }
        } else {
#pragma unroll
            for (int h = 0; h < 2; h++) {
                int gk = k0 + bk + h * 8;
                int gn = n0 + bc;
                float4 v = make_float4(0.f, 0.f, 0.f, 0.f);
                if (gk < K) {
                    const float* rp = Bm + (size_t)gk * ldb;
                    if (gn + 3 < Nn) v = *(const float4*)(rp + gn);
                    else {
                        if (gn     < Nn) v.x = rp[gn];
                        if (gn + 1 < Nn) v.y = rp[gn + 1];
                        if (gn + 2 < Nn) v.z = rp[gn + 2];
                    }
                }
                pb[h] = v;
            }
        }
#pragma unroll
        for (int h = 0; h < 2; h++) {
            int r = ar + h * 64;
            As[0][ak + 0][r] = to_tf32(pa[h].x); As[0][ak + 1][r] = to_tf32(pa[h].y);
            As[0][ak + 2][r] = to_tf32(pa[h].z); As[0][ak + 3][r] = to_tf32(pa[h].w);
        }
        if (TRANS_B) {
#pragma unroll
            for (int h = 0; h < 2; h++) {
                int r = ar + h * 64;
                Bs[0][ak + 0][r] = to_tf32(pb[h].x); Bs[0][ak + 1][r] = to_tf32(pb[h].y);
                Bs[0][ak + 2][r] = to_tf32(pb[h].z); Bs[0][ak + 3][r] = to_tf32(pb[h].w);
            }
        } else {
#pragma unroll
            for (int h = 0; h < 2; h++) {
                float4 v = pb[h];
                v.x = to_tf32(v.x); v.y = to_tf32(v.y);
                v.z = to_tf32(v.z); v.w = to_tf32(v.w);
                *(float4*)&Bs[0][bk + h * 8][bc] = v;
            }
        }
    }
    __syncthreads();

    for (int t = 0; t < ktiles; t++) {
        int cur = t & 1;
        if (t + 1 < ktiles) {
            int k0 = (t + 1) * 16;
#pragma unroll
            for (int h = 0; h < 2; h++) {
                int gm = m0 + ar + h * 64;
                pa[h] = (gm < M) ? ld4_guard(A + (size_t)gm * lda, k0 + ak, K)
                                 : make_float4(0.f, 0.f, 0.f, 0.f);
            }
            if (TRANS_B) {
#pragma unroll
                for (int h = 0; h < 2; h++) {
                    int gn = n0 + ar + h * 64;
                    pb[h] = (gn < Nn) ? ld4_guard(Bm + (size_t)gn * ldb, k0 + ak, K)
                                      : make_float4(0.f, 0.f, 0.f, 0.f);
                }
            } else {
#pragma unroll
                for (int h = 0; h < 2; h++) {
                    int gk = k0 + bk + h * 8;
                    int gn = n0 + bc;
                    float4 v = make_float4(0.f, 0.f, 0.f, 0.f);
                    if (gk < K) {
                        const float* rp = Bm + (size_t)gk * ldb;
                        if (gn + 3 < Nn) v = *(const float4*)(rp + gn);
                        else {
                            if (gn     < Nn) v.x = rp[gn];
                            if (gn + 1 < Nn) v.y = rp[gn + 1];
                            if (gn + 2 < Nn) v.z = rp[gn + 2];
                        }
                    }
                    pb[h] = v;
                }
            }
        }

#pragma unroll
        for (int ks = 0; ks < 2; ks++) {
            int kb = ks * 8;
            unsigned a[4][4], b[4][2];
#pragma unroll
            for (int i = 0; i < 4; i++) {
                int rm = wm + i * 16 + grp;
                a[i][0] = __float_as_uint(As[cur][kb + qid][rm]);
                a[i][1] = __float_as_uint(As[cur][kb + qid][rm + 8]);
                a[i][2] = __float_as_uint(As[cur][kb + qid + 4][rm]);
                a[i][3] = __float_as_uint(As[cur][kb + qid + 4][rm + 8]);
            }
#pragma unroll
            for (int j = 0; j < 4; j++) {
                int cn = wn + j * 8 + grp;
                b[j][0] = __float_as_uint(Bs[cur][kb + qid][cn]);
                b[j][1] = __float_as_uint(Bs[cur][kb + qid + 4][cn]);
            }
#pragma unroll
            for (int i = 0; i < 4; i++)
#pragma unroll
                for (int j = 0; j < 4; j++)
                    mma_tf32(acc[i][j], a[i], b[j]);
        }

        if (t + 1 < ktiles) {
            int nxt = cur ^ 1;
#pragma unroll
            for (int h = 0; h < 2; h++) {
                int r = ar + h * 64;
                As[nxt][ak + 0][r] = to_tf32(pa[h].x); As[nxt][ak + 1][r] = to_tf32(pa[h].y);
                As[nxt][ak + 2][r] = to_tf32(pa[h].z); As[nxt][ak + 3][r] = to_tf32(pa[h].w);
            }
            if (TRANS_B) {
#pragma unroll
                for (int h = 0; h < 2; h++) {
                    int r = ar + h * 64;
                    Bs[nxt][ak + 0][r] = to_tf32(pb[h].x); Bs[nxt][ak + 1][r] = to_tf32(pb[h].y);
                    Bs[nxt][ak + 2][r] = to_tf32(pb[h].z); Bs[nxt][ak + 3][r] = to_tf32(pb[h].w);
                }
            } else {
#pragma unroll
                for (int h = 0; h < 2; h++) {
                    float4 v = pb[h];
                    v.x = to_tf32(v.x); v.y = to_tf32(v.y);
                    v.z = to_tf32(v.z); v.w = to_tf32(v.w);
                    *(float4*)&Bs[nxt][bk + h * 8][bc] = v;
                }
            }
            __syncthreads();
        }
    }

    float alpha = alphaC * (alphaPtr ? *alphaPtr : 1.f);
#pragma unroll
    for (int i = 0; i < 4; i++) {
#pragma unroll
        for (int j = 0; j < 4; j++) {
            int c0 = n0 + wn + j * 8 + qid * 2;
#pragma unroll
            for (int h = 0; h < 2; h++) {
                int r = m0 + wm + i * 16 + grp + h * 8;
                if (r >= M) continue;
                float v0 = acc[i][j][h * 2], v1 = acc[i][j][h * 2 + 1];
                if (bias) {
                    if (c0     < Nn) v0 += bias[c0];
                    if (c0 + 1 < Nn) v1 += bias[c0 + 1];
                }
                v0 *= alpha; v1 *= alpha;
                size_t off = (size_t)r * ldc + c0;
                if (c0 + 1 < Nn && ((ldc & 1) == 0)) {
                    if (accum) { v0 += Cm[off]; v1 += Cm[off + 1]; }
                    *(float2*)(Cm + off) = make_float2(v0, v1);
                } else {
                    if (c0 < Nn) {
                        if (accum) v0 += Cm[off];
                        Cm[off] = v0;
                    }
                    if (c0 + 1 < Nn) {
                        if (accum) v1 += Cm[off + 1];
                        Cm[off + 1] = v1;
                    }
                }
            }
        }
    }
}

// =============== two-pass fused flash attention (64q x 64k tiles) ===============
// Pass 1: exact row max m and sum l (online l, exact m).  Pass 2: P=exp(s-m)/l
// rounded to tf32 (identical value chain to the unfused pipeline), O += P@V in
// the same key order.  No S tensor ever touches global memory.
#define FQ 64
#define FK 64
#define NKT 28               // ceil(1729/64)
#define QKS 72               // Qs/Ks col stride (=8 mod 32 -> conflict-free frags)
#define PSS 72
#define VSS 104
#define OFF_QS 0
#define OFF_KS (OFF_QS + 96 * QKS)
#define OFF_PS (OFF_KS + 96 * QKS)
#define OFF_VS (OFF_PS + FK * PSS)
#define OFF_M  (OFF_VS + FK * VSS)
#define OFF_L  (OFF_M + FQ)
#define OFF_AL (OFF_L + FQ)
#define OFF_PM (OFF_AL + FQ)
#define OFF_PSUM (OFF_PM + 4 * FQ)
#define FLASH_FLOATS (OFF_PSUM + 4 * FQ)

__device__ __forceinline__ unsigned ldsw(const float* base, int d, int col) {
    return __float_as_uint(base[d * QKS + (col ^ (((d >> 2) & 7) << 2))]);
}

__global__ void __launch_bounds__(256, 2)
flash_k(const float* __restrict__ qkv, float* __restrict__ x2)
{
    extern __shared__ float sm[];
    float* Qs = sm + OFF_QS;
    float* Ks = sm + OFF_KS;
    float* Ps = sm + OFF_PS;
    float* Vs = sm + OFF_VS;

    int tid = threadIdx.x;
    int wid = tid >> 5, lane = tid & 31;
    int grp = lane >> 2, qid = lane & 3;
    int wmS = (wid & 1) * 32;
    int wnS = (wid >> 1) * 16;
    int wnO = (wid >> 1) * 24;
    int nw = wid >> 1;

    int qb = blockIdx.x;
    int bb = blockIdx.y >> 3, hh = blockIdx.y & 7;
    const float scale = 0.10206207261596577f;   // 1/sqrt(96)
    size_t base = (size_t)bb * NTOK * (3 * CDIM) + (size_t)hh * HD;

    // ---- load Q tile (64 rows x 96 d), swizzled d-major ----
#pragma unroll
    for (int it = 0; it < 6; it++) {
        int idx = tid + it * 256;
        int r = idx / 24, d4 = (idx % 24) * 4;
        int gq = qb * FQ + r;
        float4 v = make_float4(0.f, 0.f, 0.f, 0.f);
        if (gq < NTOK) v = *(const float4*)(qkv + base + (size_t)gq * (3 * CDIM) + d4);
#pragma unroll
        for (int u = 0; u < 4; u++) {
            int d = d4 + u;
            float val = u == 0 ? v.x : u == 1 ? v.y : u == 2 ? v.z : v.w;
            Qs[d * QKS + (r ^ (((d >> 2) & 7) << 2))] = to_tf32(val);
        }
    }
    if (tid < FQ) { sm[OFF_M + tid] = -1e30f; sm[OFF_L + tid] = 0.f; }
    __syncthreads();

    // ================= PASS 1: exact m, online l =================
    for (int t = 0; t < NKT; t++) {
        int t0 = t * FK;
#pragma unroll
        for (int it = 0; it < 6; it++) {
            int idx = tid + it * 256;
            int r = idx / 24, d4 = (idx % 24) * 4;
            int gk = t0 + r;
            float4 v = make_float4(0.f, 0.f, 0.f, 0.f);
            if (gk < NTOK) v = *(const float4*)(qkv + base + (size_t)gk * (3 * CDIM) + CDIM + d4);
#pragma unroll
            for (int u = 0; u < 4; u++) {
                int d = d4 + u;
                float val = u == 0 ? v.x : u == 1 ? v.y : u == 2 ? v.z : v.w;
                Ks[d * QKS + (r ^ (((d >> 2) & 7) << 2))] = to_tf32(val);
            }
        }
        __syncthreads();

        float sacc[2][2][4];
#pragma unroll
        for (int i = 0; i < 2; i++)
#pragma unroll
            for (int j = 0; j < 2; j++)
#pragma unroll
                for (int r = 0; r < 4; r++) sacc[i][j][r] = 0.f;
#pragma unroll
        for (int ks = 0; ks < 12; ks++) {
            int kb = ks * 8;
            unsigned a[2][4], b[2][2];
#pragma unroll
            for (int i = 0; i < 2; i++) {
                int rm = wmS + i * 16 + grp;
                a[i][0] = ldsw(Qs, kb + qid, rm);
                a[i][1] = ldsw(Qs, kb + qid, rm + 8);
                a[i][2] = ldsw(Qs, kb + qid + 4, rm);
                a[i][3] = ldsw(Qs, kb + qid + 4, rm + 8);
            }
#pragma unroll
            for (int j = 0; j < 2; j++) {
                int cn = wnS + j * 8 + grp;
                b[j][0] = ldsw(Ks, kb + qid, cn);
                b[j][1] = ldsw(Ks, kb + qid + 4, cn);
            }
#pragma unroll
            for (int i = 0; i < 2; i++)
#pragma unroll
                for (int j = 0; j < 2; j++)
                    mma_tf32(sacc[i][j], a[i], b[j]);
        }

        // partial row max (masked, scaled)
#pragma unroll
        for (int i = 0; i < 2; i++)
#pragma unroll
            for (int h = 0; h < 2; h++) {
                int row = wmS + i * 16 + grp + h * 8;
                float vm = -1e30f;
#pragma unroll
                for (int j = 0; j < 2; j++)
#pragma unroll
                    for (int u = 0; u < 2; u++) {
                        int c = wnS + j * 8 + qid * 2 + u;
                        if (t0 + c < NTOK) vm = fmaxf(vm, sacc[i][j][h * 2 + u] * scale);
                    }
                vm = fmaxf(vm, __shfl_xor_sync(0xffffffffu, vm, 1));
                vm = fmaxf(vm, __shfl_xor_sync(0xffffffffu, vm, 2));
                if (qid == 0) sm[OFF_PM + nw * FQ + row] = vm;
            }
        __syncthreads();

        if (tid < FQ) {
            float mt = fmaxf(fmaxf(sm[OFF_PM + tid], sm[OFF_PM + FQ + tid]),
                             fmaxf(sm[OFF_PM + 2 * FQ + tid], sm[OFF_PM + 3 * FQ + tid]));
            float mo = sm[OFF_M + tid];
            float mn = fmaxf(mo, mt);
            sm[OFF_AL + tid] = __expf(mo - mn);
            sm[OFF_M + tid] = mn;
        }
        __syncthreads();

#pragma unroll
        for (int i = 0; i < 2; i++)
#pragma unroll
            for (int h = 0; h < 2; h++) {
                int row = wmS + i * 16 + grp + h * 8;
                float mrow = sm[OFF_M + row];
                float rs = 0.f;
#pragma unroll
                for (int j = 0; j < 2; j++)
#pragma unroll
                    for (int u = 0; u < 2; u++) {
                        int c = wnS + j * 8 + qid * 2 + u;
                        if (t0 + c < NTOK) rs += __expf(sacc[i][j][h * 2 + u] * scale - mrow);
                    }
                rs += __shfl_xor_sync(0xffffffffu, rs, 1);
                rs += __shfl_xor_sync(0xffffffffu, rs, 2);
                if (qid == 0) sm[OFF_PSUM + nw * FQ + row] = rs;
            }
        __syncthreads();

        if (tid < FQ)
            sm[OFF_L + tid] = sm[OFF_L + tid] * sm[OFF_AL + tid]
                            + sm[OFF_PSUM + tid] + sm[OFF_PSUM + FQ + tid]
                            + sm[OFF_PSUM + 2 * FQ + tid] + sm[OFF_PSUM + 3 * FQ + tid];
        __syncthreads();
    }

    // inv l (reuse AL slot)
    if (tid < FQ) sm[OFF_AL + tid] = 1.f / sm[OFF_L + tid];
    __syncthreads();

    // ================= PASS 2: P = exp(s-m)/l (tf32), O += P@V =================
    float oacc[2][3][4];
#pragma unroll
    for (int i = 0; i < 2; i++)
#pragma unroll
        for (int j = 0; j < 3; j++)
#pragma unroll
            for (int r = 0; r < 4; r++) oacc[i][j][r] = 0.f;

    for (int t = 0; t < NKT; t++) {
        int t0 = t * FK;
#pragma unroll
        for (int it = 0; it < 6; it++) {
            int idx = tid + it * 256;
            int r = idx / 24, d4 = (idx % 24) * 4;
            int gk = t0 + r;
            float4 kv4 = make_float4(0.f, 0.f, 0.f, 0.f);
            float4 vv4 = make_float4(0.f, 0.f, 0.f, 0.f);
            if (gk < NTOK) {
                const float* rp = qkv + base + (size_t)gk * (3 * CDIM);
                kv4 = *(const float4*)(rp + CDIM + d4);
                vv4 = *(const float4*)(rp + 2 * CDIM + d4);
            }
#pragma unroll
            for (int u = 0; u < 4; u++) {
                int d = d4 + u;
                float val = u == 0 ? kv4.x : u == 1 ? kv4.y : u == 2 ? kv4.z : kv4.w;
                Ks[d * QKS + (r ^ (((d >> 2) & 7) << 2))] = to_tf32(val);
            }
            vv4.x = to_tf32(vv4.x); vv4.y = to_tf32(vv4.y);
            vv4.z = to_tf32(vv4.z); vv4.w = to_tf32(vv4.w);
            *(float4*)&Vs[r * VSS + d4] = vv4;
        }
        __syncthreads();

        float sacc[2][2][4];
#pragma unroll
        for (int i = 0; i < 2; i++)
#pragma unroll
            for (int j = 0; j < 2; j++)
#pragma unroll
                for (int r = 0; r < 4; r++) sacc[i][j][r] = 0.f;
#pragma unroll
        for (int ks = 0; ks < 12; ks++) {
            int kb = ks * 8;
            unsigned a[2][4], b[2][2];
#pragma unroll
            for (int i = 0; i < 2; i++) {
                int rm = wmS + i * 16 + grp;
                a[i][0] = ldsw(Qs, kb + qid, rm);
                a[i][1] = ldsw(Qs, kb + qid, rm + 8);
                a[i][2] = ldsw(Qs, kb + qid + 4, rm);
                a[i][3] = ldsw(Qs, kb + qid + 4, rm + 8);
            }
#pragma unroll
            for (int j = 0; j < 2; j++) {
                int cn = wnS + j * 8 + grp;
                b[j][0] = ldsw(Ks, kb + qid, cn);
                b[j][1] = ldsw(Ks, kb + qid + 4, cn);
            }
#pragma unroll
            for (int i = 0; i < 2; i++)
#pragma unroll
                for (int j = 0; j < 2; j++)
                    mma_tf32(sacc[i][j], a[i], b[j]);
        }

        // normalized P -> smem (tf32)
#pragma unroll
        for (int i = 0; i < 2; i++)
#pragma unroll
            for (int h = 0; h < 2; h++) {
                int row = wmS + i * 16 + grp + h * 8;
                float mrow = sm[OFF_M + row];
                float invl = sm[OFF_AL + row];
#pragma unroll
                for (int j = 0; j < 2; j++)
#pragma unroll
                    for (int u = 0; u < 2; u++) {
                        int c = wnS + j * 8 + qid * 2 + u;
                        float p = 0.f;
                        if (t0 + c < NTOK)
                            p = __expf(sacc[i][j][h * 2 + u] * scale - mrow) * invl;
                        Ps[c * PSS + row] = to_tf32(p);
                    }
            }
        __syncthreads();

        // O += P @ V
#pragma unroll
        for (int ks = 0; ks < 8; ks++) {
            int kb = ks * 8;
            unsigned a[2][4], b[3][2];
#pragma unroll
            for (int i = 0; i < 2; i++) {
                int rm = wmS + i * 16 + grp;
                a[i][0] = __float_as_uint(Ps[(kb + qid) * PSS + rm]);
                a[i][1] = __float_as_uint(Ps[(kb + qid) * PSS + rm + 8]);
                a[i][2] = __float_as_uint(Ps[(kb + qid + 4) * PSS + rm]);
                a[i][3] = __float_as_uint(Ps[(kb + qid + 4) * PSS + rm + 8]);
            }
#pragma unroll
            for (int j = 0; j < 3; j++) {
                int cn = wnO + j * 8 + grp;
                b[j][0] = __float_as_uint(Vs[(kb + qid) * VSS + cn]);
                b[j][1] = __float_as_uint(Vs[(kb + qid + 4) * VSS + cn]);
            }
#pragma unroll
            for (int i = 0; i < 2; i++)
#pragma unroll
                for (int j = 0; j < 3; j++)
                    mma_tf32(oacc[i][j], a[i], b[j]);
        }
        __syncthreads();
    }

    // ---- store O ----
#pragma unroll
    for (int i = 0; i < 2; i++)
#pragma unroll
        for (int h = 0; h < 2; h++) {
            int row = wmS + i * 16 + grp + h * 8;
            int gq = qb * FQ + row;
            if (gq >= NTOK) continue;
            float* op = x2 + (size_t)bb * NTOK * CDIM + (size_t)gq * CDIM + hh * HD;
#pragma unroll
            for (int j = 0; j < 3; j++) {
                int cn = wnO + j * 8 + qid * 2;
                *(float2*)(op + cn) = make_float2(oacc[i][j][h * 2], oacc[i][j][h * 2 + 1]);
            }
        }
}

// ---------------- pack QKV weights/bias into one matrix ----------------
__global__ void pack_qkv_k(const float* __restrict__ qw, const float* __restrict__ kw,
                           const float* __restrict__ vw, const float* __restrict__ qb,
                           const float* __restrict__ kb, const float* __restrict__ vb,
                           float* __restrict__ w, float* __restrict__ bias)
{
    int idx = blockIdx.x * 256 + threadIdx.x;
    int tot = 3 * CDIM * CDIM / 4;
    if (idx < tot) {
        int e = idx * 4;
        int which = e / (CDIM * CDIM);
        int off = e - which * (CDIM * CDIM);
        const float* src = which == 0 ? qw : which == 1 ? kw : vw;
        *(float4*)(w + e) = *(const float4*)(src + off);
    }
    if (idx < 3 * CDIM) {
        int which = idx / CDIM, off = idx % CDIM;
        bias[idx] = (which == 0 ? qb : which == 1 ? kb : vb)[off];
    }
}

// ---------------- im2col patch gather (float4) ----------------
__global__ void gather_k(const float* __restrict__ smri, float* __restrict__ pat) {
    int idx = blockIdx.x * 256 + threadIdx.x;
    if (idx >= BQ * NPATCH * 512 / 4) return;
    int e  = idx * 4;
    int kk = e & 511;
    int m  = e >> 9;
    int bb = m / NPATCH, p = m % NPATCH;
    int gx = p / (GD * GD), gy = (p / GD) % GD, gz = p % GD;
    int i = kk >> 6, j = (kk >> 3) & 7, kq = kk & 7;
    const float* src = smri + (((size_t)bb * IMG + gx * PSZ + i) * IMG + gy * PSZ + j) * IMG
                       + gz * PSZ + kq;
    *(float4*)(pat + e) = *(const float4*)src;
}

// ---------------- LN(patch embed) + cls + pos_embed ----------------
__global__ void ln_pos_k(const float* __restrict__ tmp, const float* __restrict__ g,
                         const float* __restrict__ b, const float* __restrict__ cls,
                         const float* __restrict__ pos, float* __restrict__ x)
{
    int bt = blockIdx.x;
    int bb = bt / NTOK, t = bt % NTOK;
    int tid = threadIdx.x;
    float* out = x + (size_t)bt * CDIM;
    const float* pp = pos + (size_t)t * CDIM;
    if (t == 0) {
        for (int c = tid; c < CDIM; c += 256) out[c] = cls[c] + pp[c];
        return;
    }
    const float* row = tmp + ((size_t)bb * NPATCH + (t - 1)) * CDIM;
    __shared__ float red[256];
    float s = 0.f, s2 = 0.f;
    for (int c = tid; c < CDIM; c += 256) { float v = row[c]; s += v; s2 += v * v; }
    red[tid] = s; __syncthreads();
    for (int st = 128; st > 0; st >>= 1) { if (tid < st) red[tid] += red[tid + st]; __syncthreads(); }
    float mean = red[0] / CDIM; __syncthreads();
    red[tid] = s2; __syncthreads();
    for (int st = 128; st > 0; st >>= 1) { if (tid < st) red[tid] += red[tid + st]; __syncthreads(); }
    float var = red[0] / CDIM - mean * mean;
    float inv = rsqrtf(var + 1e-5f);
    for (int c = tid; c < CDIM; c += 256)
        out[c] = (row[c] - mean) * inv * g[c] + b[c] + pp[c];
}

// ---------------- CLS-query attention for a branch ----------------
__global__ void cls_attn_k(const float* __restrict__ q0, const float* __restrict__ kv,
                           float* __restrict__ oc)
{
    int z = blockIdx.x;
    int bb = z / NHEAD, hh = z % NHEAD;
    __shared__ float sS[NTOK];
    __shared__ float sq[HD];
    __shared__ float red[128];
    int tid = threadIdx.x;
    for (int j = tid; j < HD; j += 128) sq[j] = q0[bb * CDIM + hh * HD + j];
    __syncthreads();
    const float scale = 0.10206207261596577f;
    float mx = -1e30f;
    for (int t = tid; t < NTOK; t += 128) {
        const float* kr = kv + ((size_t)(bb * NTOK + t)) * (2 * CDIM) + hh * HD;
        float s = 0.f;
        for (int j = 0; j < HD; j++) s += sq[j] * kr[j];
        s *= scale;
        sS[t] = s;
        mx = fmaxf(mx, s);
    }
    red[tid] = mx; __syncthreads();
    for (int st = 64; st > 0; st >>= 1) { if (tid < st) red[tid] = fmaxf(red[tid], red[tid + st]); __syncthreads(); }
    mx = red[0]; __syncthreads();
    float sm = 0.f;
    for (int t = tid; t < NTOK; t += 128) { float e = __expf(sS[t] - mx); sS[t] = e; sm += e; }
    red[tid] = sm; __syncthreads();
    for (int st = 64; st > 0; st >>= 1) { if (tid < st) red[tid] += red[tid + st]; __syncthreads(); }
    float inv = 1.f / red[0];
    __syncthreads();
    if (tid < HD) {
        float acc = 0.f;
        for (int t = 0; t < NTOK; t++)
            acc += sS[t] * kv[((size_t)(bb * NTOK + t)) * (2 * CDIM) + CDIM + hh * HD + tid];
        oc[bb * CDIM + hh * HD + tid] = acc * inv;
    }
}

// ---------------- LN + head on CLS ----------------
__global__ void head_k(const float* __restrict__ fin, const float* __restrict__ g,
                       const float* __restrict__ b, const float* __restrict__ hw,
                       const float* __restrict__ hb, float* __restrict__ out)
{
    int bb = blockIdx.x;
    const float* row = fin + bb * CDIM;
    __shared__ float red[256];
    __shared__ float sn[CDIM];
    int tid = threadIdx.x;
    float s = 0.f, s2 = 0.f;
    for (int c = tid; c < CDIM; c += 256) { float v = row[c]; s += v; s2 += v * v; }
    red[tid] = s; __syncthreads();
    for (int st = 128; st > 0; st >>= 1) { if (tid < st) red[tid] += red[tid + st]; __syncthreads(); }
    float mean = red[0] / CDIM; __syncthreads();
    red[tid] = s2; __syncthreads();
    for (int st = 128; st > 0; st >>= 1) { if (tid < st) red[tid] += red[tid + st]; __syncthreads(); }
    float var = red[0] / CDIM - mean * mean;
    float inv = rsqrtf(var + 1e-5f);
    for (int c = tid; c < CDIM; c += 256) sn[c] = (row[c] - mean) * inv * g[c] + b[c];
    __syncthreads();
    if (tid < NCLS) {
        float acc = hb[tid];
        for (int c = 0; c < CDIM; c++) acc += sn[c] * hw[tid * CDIM + c];
        out[bb * NCLS + tid] = acc;
    }
}

// ---------------- host ----------------
static inline int cdiv(int a, int b) { return (a + b - 1) / b; }

static void gemm_nt(const float* A, const float* B, const float* bias, float* C,
                    int M, int Nn, int K, int lda, int ldb, int ldc,
                    size_t sAb = 0, size_t sAh = 0, size_t sBb = 0, size_t sBh = 0,
                    size_t sCb = 0, size_t sCh = 0, int nh = 1, int batches = 1,
                    float alphaC = 1.f, const float* alphaPtr = nullptr, int accum = 0)
{
    dim3 grid(cdiv(Nn, 128), cdiv(M, 128), batches);
    gemm_k<1><<<grid, 256>>>(A, B, bias, C, M, Nn, K, lda, ldb, ldc,
                             sAb, sAh, sBb, sBh, sCb, sCh, nh, alphaC, alphaPtr, accum);
}

extern "C" void kernel_launch(void* const* d_in, const int* in_sizes, int n_in,
                              void* d_out, int out_size)
{
    const float* smri     = (const float*)d_in[0];
    const float* conv_w   = (const float*)d_in[2];
    const float* conv_b   = (const float*)d_in[3];
    const float* pe_ln_g  = (const float*)d_in[4];
    const float* pe_ln_b  = (const float*)d_in[5];
    const float* q_w      = (const float*)d_in[6];
    const float* q_b      = (const float*)d_in[7];
    const float* k_w      = (const float*)d_in[8];
    const float* k_b      = (const float*)d_in[9];
    const float* v_w      = (const float*)d_in[10];
    const float* v_b      = (const float*)d_in[11];
    const float* loc_in_w = (const float*)d_in[13];
    const float* loc_in_b = (const float*)d_in[14];
    const float* loc_out_w= (const float*)d_in[15];
    const float* loc_out_b= (const float*)d_in[16];
    const float* glob_in_w = (const float*)d_in[17];
    const float* glob_in_b = (const float*)d_in[18];
    const float* glob_out_w= (const float*)d_in[19];
    const float* glob_out_b= (const float*)d_in[20];
    const float* w_local  = (const float*)d_in[21];
    const float* w_global = (const float*)d_in[22];
    const float* cls_tok  = (const float*)d_in[23];
    const float* pos_emb  = (const float*)d_in[24];
    const float* head_ln_g= (const float*)d_in[25];
    const float* head_ln_b= (const float*)d_in[26];
    const float* head_w   = (const float*)d_in[27];
    const float* head_b   = (const float*)d_in[28];
    float* out = (float*)d_out;

    float *pat, *tmp, *x, *wqkv, *bqkv, *qkv, *x2, *kv, *q0, *oc, *fin;
    cudaGetSymbolAddress((void**)&pat,  g_pat);
    cudaGetSymbolAddress((void**)&tmp,  g_tmp);
    cudaGetSymbolAddress((void**)&x,    g_x);
    cudaGetSymbolAddress((void**)&wqkv, g_wqkv);
    cudaGetSymbolAddress((void**)&bqkv, g_bqkv);
    cudaGetSymbolAddress((void**)&qkv,  g_qkv);
    cudaGetSymbolAddress((void**)&x2,   g_x2);
    cudaGetSymbolAddress((void**)&kv,   g_kv);
    cudaGetSymbolAddress((void**)&q0,   g_q0);
    cudaGetSymbolAddress((void**)&oc,   g_oc);
    cudaGetSymbolAddress((void**)&fin,  g_fin);

    const size_t sT  = (size_t)NTOK * CDIM;

    static int flash_init = 0;
    if (!flash_init) {
        cudaFuncSetAttribute(flash_k, cudaFuncAttributeMaxDynamicSharedMemorySize,
                             FLASH_FLOATS * 4);
        flash_init = 1;
    }

    // 0) pack QKV weights
    pack_qkv_k<<<cdiv(3 * CDIM * CDIM / 4, 256), 256>>>(q_w, k_w, v_w, q_b, k_b, v_b,
                                                        wqkv, bqkv);

    // 1) patch im2col + embed GEMM
    gather_k<<<cdiv(BQ * NPATCH * 512 / 4, 256), 256>>>(smri, pat);
    gemm_nt(pat, conv_w, conv_b, tmp, BQ * NPATCH, CDIM, 512, 512, 512, CDIM);

    // 2) LN + cls + pos
    ln_pos_k<<<BQ * NTOK, 256>>>(tmp, pe_ln_g, pe_ln_b, cls_tok, pos_emb, x);

    // 3) fused QKV projection
    gemm_nt(x, wqkv, bqkv, qkv, BQ * NTOK, 3 * CDIM, CDIM, CDIM, CDIM, 3 * CDIM);

    // 4-6) fused two-pass flash attention (region bias softmax-invariant -> dropped)
    flash_k<<<dim3(cdiv(NTOK, FQ), BQ * NHEAD), 256, FLASH_FLOATS * 4>>>(qkv, x2);

    // 7) branches (only CLS row used downstream)
    gemm_nt(x2, loc_in_w + (size_t)CDIM * CDIM, loc_in_b + CDIM, kv,
            BQ * NTOK, 2 * CDIM, CDIM, CDIM, CDIM, 2 * CDIM);
    gemm_nt(x2, loc_in_w, loc_in_b, q0, BQ, CDIM, CDIM, (int)sT, CDIM, CDIM);
    cls_attn_k<<<BQ * NHEAD, 128>>>(q0, kv, oc);
    gemm_nt(oc, loc_out_w, loc_out_b, fin, BQ, CDIM, CDIM, CDIM, CDIM, CDIM,
            0, 0, 0, 0, 0, 0, 1, 1, 1.f, w_local, 0);
    gemm_nt(x2, glob_in_w + (size_t)CDIM * CDIM, glob_in_b + CDIM, kv,
            BQ * NTOK, 2 * CDIM, CDIM, CDIM, CDIM, 2 * CDIM);
    gemm_nt(x2, glob_in_w, glob_in_b, q0, BQ, CDIM, CDIM, (int)sT, CDIM, CDIM);
    cls_attn_k<<<BQ * NHEAD, 128>>>(q0, kv, oc);
    gemm_nt(oc, glob_out_w, glob_out_b, fin, BQ, CDIM, CDIM, CDIM, CDIM, CDIM,
            0, 0, 0, 0, 0, 0, 1, 1, 1.f, w_global, 1);

    // 8) head on CLS
    head_k<<<BQ, 256>>>(fin, head_ln_g, head_ln_b, head_w, head_b, out);
}

// round 10
// speedup vs baseline: 1.0580x; 1.0580x over previous
#include <cuda_runtime.h>
#include <math.h>

#define IMG 96
#define PSZ 8
#define GD 12
#define CDIM 768
#define NHEAD 8
#define HD 96
#define NPATCH 1728
#define NTOK 1729
#define BQ 2
#define NCLS 3

// ---------------- scratch (device globals) ----------------
__device__ float g_pat [(size_t)BQ * NPATCH * 512];
__device__ float g_tmp [(size_t)BQ * NPATCH * CDIM];
__device__ float g_x   [(size_t)BQ * NTOK * CDIM];
__device__ float g_wqkv[(size_t)3 * CDIM * CDIM];
__device__ float g_bqkv[3 * CDIM];
__device__ float g_qkv [(size_t)BQ * NTOK * 3 * CDIM];
__device__ float g_x2  [(size_t)BQ * NTOK * CDIM];
__device__ float g_kv  [(size_t)BQ * NTOK * 2 * CDIM];
__device__ float g_q0  [BQ * CDIM];
__device__ float g_oc  [BQ * CDIM];
__device__ float g_fin [BQ * CDIM];

__device__ __forceinline__ float to_tf32(float x) {
    unsigned u;
    asm("cvt.rna.tf32.f32 %0, %1;" : "=r"(u) : "f"(x));
    return __uint_as_float(u);
}

__device__ __forceinline__ float4 ld4_guard(const float* __restrict__ p, int gk, int K) {
    if (gk + 3 < K) return *(const float4*)(p + gk);
    float4 v = make_float4(0.f, 0.f, 0.f, 0.f);
    if (gk     < K) v.x = p[gk];
    if (gk + 1 < K) v.y = p[gk + 1];
    if (gk + 2 < K) v.z = p[gk + 2];
    return v;
}

__device__ __forceinline__ void mma_tf32(float* c, const unsigned* a, const unsigned* b) {
    asm("mma.sync.aligned.m16n8k8.row.col.f32.tf32.tf32.f32 "
        "{%0,%1,%2,%3}, {%4,%5,%6,%7}, {%8,%9}, {%0,%1,%2,%3};"
        : "+f"(c[0]), "+f"(c[1]), "+f"(c[2]), "+f"(c[3])
        : "r"(a[0]), "r"(a[1]), "r"(a[2]), "r"(a[3]), "r"(b[0]), "r"(b[1]));
}

// ---- 128x128x16 double-buffered GEMM on tf32 mma.sync (m16n8k8), fp32 accum ----
template <int TRANS_B>
__global__ void __launch_bounds__(256, 2)
gemm_k(const float* __restrict__ A, const float* __restrict__ Bm,
       const float* __restrict__ bias, float* __restrict__ Cm,
       int M, int Nn, int K, int lda, int ldb, int ldc,
       size_t sAb, size_t sAh, size_t sBb, size_t sBh,
       size_t sCb, size_t sCh, int nh,
       float alphaC, const float* __restrict__ alphaPtr, int accum)
{
    int z = blockIdx.z;
    int bb = z / nh, hh = z % nh;
    A  += (size_t)bb * sAb + (size_t)hh * sAh;
    Bm += (size_t)bb * sBb + (size_t)hh * sBh;
    Cm += (size_t)bb * sCb + (size_t)hh * sCh;

    __shared__ __align__(16) float As[2][16][136];
    __shared__ __align__(16) float Bs[2][16][136];

    int tid = threadIdx.x;
    int m0 = blockIdx.y * 128, n0 = blockIdx.x * 128;

    int ar = tid >> 2;
    int ak = (tid & 3) * 4;
    int bk = tid >> 5;
    int bc = (tid & 31) * 4;

    int wid = tid >> 5, lane = tid & 31;
    int wm = (wid & 1) * 64, wn = (wid >> 1) * 32;
    int grp = lane >> 2, qid = lane & 3;

    float acc[4][4][4];
#pragma unroll
    for (int i = 0; i < 4; i++)
#pragma unroll
        for (int j = 0; j < 4; j++)
#pragma unroll
            for (int r = 0; r < 4; r++) acc[i][j][r] = 0.f;

    float4 pa[2], pb[2];
    int ktiles = (K + 15) / 16;

    {
        int k0 = 0;
#pragma unroll
        for (int h = 0; h < 2; h++) {
            int gm = m0 + ar + h * 64;
            pa[h] = (gm < M) ? ld4_guard(A + (size_t)gm * lda, k0 + ak, K)
                             : make_float4(0.f, 0.f, 0.f, 0.f);
        }
        if (TRANS_B) {
#pragma unroll
            for (int h = 0; h < 2; h++) {
                int gn = n0 + ar + h * 64;
                pb[h] = (gn < Nn) ? ld4_guard(Bm + (size_t)gn * ldb, k0 + ak, K)
                                  : make_float4(0.f, 0.f, 0.f, 0.f);
            }
        } else {
#pragma unroll
            for (int h = 0; h < 2; h++) {
                int gk = k0 + bk + h * 8;
                int gn = n0 + bc;
                float4 v = make_float4(0.f, 0.f, 0.f, 0.f);
                if (gk < K) {
                    const float* rp = Bm + (size_t)gk * ldb;
                    if (gn + 3 < Nn) v = *(const float4*)(rp + gn);
                    else {
                        if (gn     < Nn) v.x = rp[gn];
                        if (gn + 1 < Nn) v.y = rp[gn + 1];
                        if (gn + 2 < Nn) v.z = rp[gn + 2];
                    }
                }
                pb[h] = v;
            }
        }
#pragma unroll
        for (int h = 0; h < 2; h++) {
            int r = ar + h * 64;
            As[0][ak + 0][r] = to_tf32(pa[h].x); As[0][ak + 1][r] = to_tf32(pa[h].y);
            As[0][ak + 2][r] = to_tf32(pa[h].z); As[0][ak + 3][r] = to_tf32(pa[h].w);
        }
        if (TRANS_B) {
#pragma unroll
            for (int h = 0; h < 2; h++) {
                int r = ar + h * 64;
                Bs[0][ak + 0][r] = to_tf32(pb[h].x); Bs[0][ak + 1][r] = to_tf32(pb[h].y);
                Bs[0][ak + 2][r] = to_tf32(pb[h].z); Bs[0][ak + 3][r] = to_tf32(pb[h].w);
            }
        } else {
#pragma unroll
            for (int h = 0; h < 2; h++) {
                float4 v = pb[h];
                v.x = to_tf32(v.x); v.y = to_tf32(v.y);
                v.z = to_tf32(v.z); v.w = to_tf32(v.w);
                *(float4*)&Bs[0][bk + h * 8][bc] = v;
            }
        }
    }
    __syncthreads();

    for (int t = 0; t < ktiles; t++) {
        int cur = t & 1;
        if (t + 1 < ktiles) {
            int k0 = (t + 1) * 16;
#pragma unroll
            for (int h = 0; h < 2; h++) {
                int gm = m0 + ar + h * 64;
                pa[h] = (gm < M) ? ld4_guard(A + (size_t)gm * lda, k0 + ak, K)
                                 : make_float4(0.f, 0.f, 0.f, 0.f);
            }
            if (TRANS_B) {
#pragma unroll
                for (int h = 0; h < 2; h++) {
                    int gn = n0 + ar + h * 64;
                    pb[h] = (gn < Nn) ? ld4_guard(Bm + (size_t)gn * ldb, k0 + ak, K)
                                      : make_float4(0.f, 0.f, 0.f, 0.f);
                }
            } else {
#pragma unroll
                for (int h = 0; h < 2; h++) {
                    int gk = k0 + bk + h * 8;
                    int gn = n0 + bc;
                    float4 v = make_float4(0.f, 0.f, 0.f, 0.f);
                    if (gk < K) {
                        const float* rp = Bm + (size_t)gk * ldb;
                        if (gn + 3 < Nn) v = *(const float4*)(rp + gn);
                        else {
                            if (gn     < Nn) v.x = rp[gn];
                            if (gn + 1 < Nn) v.y = rp[gn + 1];
                            if (gn + 2 < Nn) v.z = rp[gn + 2];
                        }
                    }
                    pb[h] = v;
                }
            }
        }

#pragma unroll
        for (int ks = 0; ks < 2; ks++) {
            int kb = ks * 8;
            unsigned a[4][4], b[4][2];
#pragma unroll
            for (int i = 0; i < 4; i++) {
                int rm = wm + i * 16 + grp;
                a[i][0] = __float_as_uint(As[cur][kb + qid][rm]);
                a[i][1] = __float_as_uint(As[cur][kb + qid][rm + 8]);
                a[i][2] = __float_as_uint(As[cur][kb + qid + 4][rm]);
                a[i][3] = __float_as_uint(As[cur][kb + qid + 4][rm + 8]);
            }
#pragma unroll
            for (int j = 0; j < 4; j++) {
                int cn = wn + j * 8 + grp;
                b[j][0] = __float_as_uint(Bs[cur][kb + qid][cn]);
                b[j][1] = __float_as_uint(Bs[cur][kb + qid + 4][cn]);
            }
#pragma unroll
            for (int i = 0; i < 4; i++)
#pragma unroll
                for (int j = 0; j < 4; j++)
                    mma_tf32(acc[i][j], a[i], b[j]);
        }

        if (t + 1 < ktiles) {
            int nxt = cur ^ 1;
#pragma unroll
            for (int h = 0; h < 2; h++) {
                int r = ar + h * 64;
                As[nxt][ak + 0][r] = to_tf32(pa[h].x); As[nxt][ak + 1][r] = to_tf32(pa[h].y);
                As[nxt][ak + 2][r] = to_tf32(pa[h].z); As[nxt][ak + 3][r] = to_tf32(pa[h].w);
            }
            if (TRANS_B) {
#pragma unroll
                for (int h = 0; h < 2; h++) {
                    int r = ar + h * 64;
                    Bs[nxt][ak + 0][r] = to_tf32(pb[h].x); Bs[nxt][ak + 1][r] = to_tf32(pb[h].y);
                    Bs[nxt][ak + 2][r] = to_tf32(pb[h].z); Bs[nxt][ak + 3][r] = to_tf32(pb[h].w);
                }
            } else {
#pragma unroll
                for (int h = 0; h < 2; h++) {
                    float4 v = pb[h];
                    v.x = to_tf32(v.x); v.y = to_tf32(v.y);
                    v.z = to_tf32(v.z); v.w = to_tf32(v.w);
                    *(float4*)&Bs[nxt][bk + h * 8][bc] = v;
                }
            }
            __syncthreads();
        }
    }

    float alpha = alphaC * (alphaPtr ? *alphaPtr : 1.f);
#pragma unroll
    for (int i = 0; i < 4; i++) {
#pragma unroll
        for (int j = 0; j < 4; j++) {
            int c0 = n0 + wn + j * 8 + qid * 2;
#pragma unroll
            for (int h = 0; h < 2; h++) {
                int r = m0 + wm + i * 16 + grp + h * 8;
                if (r >= M) continue;
                float v0 = acc[i][j][h * 2], v1 = acc[i][j][h * 2 + 1];
                if (bias) {
                    if (c0     < Nn) v0 += bias[c0];
                    if (c0 + 1 < Nn) v1 += bias[c0 + 1];
                }
                v0 *= alpha; v1 *= alpha;
                size_t off = (size_t)r * ldc + c0;
                if (c0 + 1 < Nn && ((ldc & 1) == 0)) {
                    if (accum) { v0 += Cm[off]; v1 += Cm[off + 1]; }
                    *(float2*)(Cm + off) = make_float2(v0, v1);
                } else {
                    if (c0 < Nn) {
                        if (accum) v0 += Cm[off];
                        Cm[off] = v0;
                    }
                    if (c0 + 1 < Nn) {
                        if (accum) v1 += Cm[off + 1];
                        Cm[off + 1] = v1;
                    }
                }
            }
        }
    }
}

// ====== single-pass fused flash attention (64q x 64k tiles, online softmax) ======
// Register-prefetch double buffering of K/V (gemm_k pattern). O rescaled by
// alpha = exp(m_old - m_new) per tile; final normalize by 1/l. All rescales fp32.
#define FQ 64
#define FK 64
#define NKT 28               // ceil(1729/64)
#define QKS 72               // Qs/Ks col stride (=8 mod 32 -> conflict-free frags)
#define PSS 72
#define VSS 104
#define OFF_QS 0
#define OFF_KS (OFF_QS + 96 * QKS)
#define OFF_PS (OFF_KS + 96 * QKS)
#define OFF_VS (OFF_PS + FK * PSS)
#define OFF_M  (OFF_VS + FK * VSS)
#define OFF_L  (OFF_M + FQ)
#define OFF_AL (OFF_L + FQ)
#define OFF_PM (OFF_AL + FQ)
#define OFF_PSUM (OFF_PM + 4 * FQ)
#define FLASH_FLOATS (OFF_PSUM + 4 * FQ)

__device__ __forceinline__ unsigned ldsw(const float* base, int d, int col) {
    return __float_as_uint(base[d * QKS + (col ^ (((d >> 2) & 7) << 2))]);
}

__global__ void __launch_bounds__(256, 2)
flash_k(const float* __restrict__ qkv, float* __restrict__ x2)
{
    extern __shared__ float sm[];
    float* Qs = sm + OFF_QS;
    float* Ks = sm + OFF_KS;
    float* Ps = sm + OFF_PS;
    float* Vs = sm + OFF_VS;

    int tid = threadIdx.x;
    int wid = tid >> 5, lane = tid & 31;
    int grp = lane >> 2, qid = lane & 3;
    int wmS = (wid & 1) * 32;
    int wnS = (wid >> 1) * 16;
    int wnO = (wid >> 1) * 24;
    int nw = wid >> 1;

    int qb = blockIdx.x;
    int bb = blockIdx.y >> 3, hh = blockIdx.y & 7;
    const float scale = 0.10206207261596577f;   // 1/sqrt(96)
    size_t base = (size_t)bb * NTOK * (3 * CDIM) + (size_t)hh * HD;

    // ---- load Q tile (64 rows x 96 d), swizzled d-major ----
#pragma unroll
    for (int it = 0; it < 6; it++) {
        int idx = tid + it * 256;
        int r = idx / 24, d4 = (idx % 24) * 4;
        int gq = qb * FQ + r;
        float4 v = make_float4(0.f, 0.f, 0.f, 0.f);
        if (gq < NTOK) v = *(const float4*)(qkv + base + (size_t)gq * (3 * CDIM) + d4);
#pragma unroll
        for (int u = 0; u < 4; u++) {
            int d = d4 + u;
            float val = u == 0 ? v.x : u == 1 ? v.y : u == 2 ? v.z : v.w;
            Qs[d * QKS + (r ^ (((d >> 2) & 7) << 2))] = to_tf32(val);
        }
    }
    if (tid < FQ) { sm[OFF_M + tid] = -1e30f; sm[OFF_L + tid] = 0.f; }

    // ---- prologue: prefetch K/V tile 0 into regs, store to smem ----
    float4 kreg[6], vreg[6];
#pragma unroll
    for (int it = 0; it < 6; it++) {
        int idx = tid + it * 256;
        int r = idx / 24, d4 = (idx % 24) * 4;
        kreg[it] = make_float4(0.f, 0.f, 0.f, 0.f);
        vreg[it] = make_float4(0.f, 0.f, 0.f, 0.f);
        if (r < NTOK) {  // tile 0: gk = r, always < NTOK for r < 64
            const float* rp = qkv + base + (size_t)r * (3 * CDIM);
            kreg[it] = *(const float4*)(rp + CDIM + d4);
            vreg[it] = *(const float4*)(rp + 2 * CDIM + d4);
        }
    }
#pragma unroll
    for (int it = 0; it < 6; it++) {
        int idx = tid + it * 256;
        int r = idx / 24, d4 = (idx % 24) * 4;
        float kvv[4] = {kreg[it].x, kreg[it].y, kreg[it].z, kreg[it].w};
#pragma unroll
        for (int u = 0; u < 4; u++) {
            int d = d4 + u;
            Ks[d * QKS + (r ^ (((d >> 2) & 7) << 2))] = to_tf32(kvv[u]);
        }
        float4 vv = vreg[it];
        vv.x = to_tf32(vv.x); vv.y = to_tf32(vv.y);
        vv.z = to_tf32(vv.z); vv.w = to_tf32(vv.w);
        *(float4*)&Vs[r * VSS + d4] = vv;
    }
    __syncthreads();

    float oacc[2][3][4];
#pragma unroll
    for (int i = 0; i < 2; i++)
#pragma unroll
        for (int j = 0; j < 3; j++)
#pragma unroll
            for (int r = 0; r < 4; r++) oacc[i][j][r] = 0.f;

    for (int t = 0; t < NKT; t++) {
        int t0 = t * FK;

        // ---- prefetch tile t+1 into regs ----
        if (t + 1 < NKT) {
            int t1 = t0 + FK;
#pragma unroll
            for (int it = 0; it < 6; it++) {
                int idx = tid + it * 256;
                int r = idx / 24, d4 = (idx % 24) * 4;
                int gk = t1 + r;
                kreg[it] = make_float4(0.f, 0.f, 0.f, 0.f);
                vreg[it] = make_float4(0.f, 0.f, 0.f, 0.f);
                if (gk < NTOK) {
                    const float* rp = qkv + base + (size_t)gk * (3 * CDIM);
                    kreg[it] = *(const float4*)(rp + CDIM + d4);
                    vreg[it] = *(const float4*)(rp + 2 * CDIM + d4);
                }
            }
        }

        // ---- S = Q K^T ----
        float sacc[2][2][4];
#pragma unroll
        for (int i = 0; i < 2; i++)
#pragma unroll
            for (int j = 0; j < 2; j++)
#pragma unroll
                for (int r = 0; r < 4; r++) sacc[i][j][r] = 0.f;
#pragma unroll
        for (int ks = 0; ks < 12; ks++) {
            int kb = ks * 8;
            unsigned a[2][4], b[2][2];
#pragma unroll
            for (int i = 0; i < 2; i++) {
                int rm = wmS + i * 16 + grp;
                a[i][0] = ldsw(Qs, kb + qid, rm);
                a[i][1] = ldsw(Qs, kb + qid, rm + 8);
                a[i][2] = ldsw(Qs, kb + qid + 4, rm);
                a[i][3] = ldsw(Qs, kb + qid + 4, rm + 8);
            }
#pragma unroll
            for (int j = 0; j < 2; j++) {
                int cn = wnS + j * 8 + grp;
                b[j][0] = ldsw(Ks, kb + qid, cn);
                b[j][1] = ldsw(Ks, kb + qid + 4, cn);
            }
#pragma unroll
            for (int i = 0; i < 2; i++)
#pragma unroll
                for (int j = 0; j < 2; j++)
                    mma_tf32(sacc[i][j], a[i], b[j]);
        }

        // ---- partial row max (masked, scaled) ----
#pragma unroll
        for (int i = 0; i < 2; i++)
#pragma unroll
            for (int h = 0; h < 2; h++) {
                int row = wmS + i * 16 + grp + h * 8;
                float vm = -1e30f;
#pragma unroll
                for (int j = 0; j < 2; j++)
#pragma unroll
                    for (int u = 0; u < 2; u++) {
                        int c = wnS + j * 8 + qid * 2 + u;
                        if (t0 + c < NTOK) vm = fmaxf(vm, sacc[i][j][h * 2 + u] * scale);
                    }
                vm = fmaxf(vm, __shfl_xor_sync(0xffffffffu, vm, 1));
                vm = fmaxf(vm, __shfl_xor_sync(0xffffffffu, vm, 2));
                if (qid == 0) sm[OFF_PM + nw * FQ + row] = vm;
            }
        __syncthreads();

        if (tid < FQ) {
            float mt = fmaxf(fmaxf(sm[OFF_PM + tid], sm[OFF_PM + FQ + tid]),
                             fmaxf(sm[OFF_PM + 2 * FQ + tid], sm[OFF_PM + 3 * FQ + tid]));
            float mo = sm[OFF_M + tid];
            float mn = fmaxf(mo, mt);
            sm[OFF_AL + tid] = __expf(mo - mn);
            sm[OFF_M + tid] = mn;
        }
        __syncthreads();

        // ---- rescale O, write unnormalized P, accumulate row sums ----
#pragma unroll
        for (int i = 0; i < 2; i++)
#pragma unroll
            for (int h = 0; h < 2; h++) {
                int row = wmS + i * 16 + grp + h * 8;
                float mrow = sm[OFF_M + row];
                float alpha = sm[OFF_AL + row];
#pragma unroll
                for (int j = 0; j < 3; j++) {
                    oacc[i][j][h * 2]     *= alpha;
                    oacc[i][j][h * 2 + 1] *= alpha;
                }
                float rs = 0.f;
#pragma unroll
                for (int j = 0; j < 2; j++)
#pragma unroll
                    for (int u = 0; u < 2; u++) {
                        int c = wnS + j * 8 + qid * 2 + u;
                        float p = 0.f;
                        if (t0 + c < NTOK)
                            p = __expf(sacc[i][j][h * 2 + u] * scale - mrow);
                        Ps[c * PSS + row] = to_tf32(p);
                        rs += p;
                    }
                rs += __shfl_xor_sync(0xffffffffu, rs, 1);
                rs += __shfl_xor_sync(0xffffffffu, rs, 2);
                if (qid == 0) sm[OFF_PSUM + nw * FQ + row] = rs;
            }
        __syncthreads();

        if (tid < FQ)
            sm[OFF_L + tid] = sm[OFF_L + tid] * sm[OFF_AL + tid]
                            + sm[OFF_PSUM + tid] + sm[OFF_PSUM + FQ + tid]
                            + sm[OFF_PSUM + 2 * FQ + tid] + sm[OFF_PSUM + 3 * FQ + tid];

        // ---- O += P @ V ----
#pragma unroll
        for (int ks = 0; ks < 8; ks++) {
            int kb = ks * 8;
            unsigned a[2][4], b[3][2];
#pragma unroll
            for (int i = 0; i < 2; i++) {
                int rm = wmS + i * 16 + grp;
                a[i][0] = __float_as_uint(Ps[(kb + qid) * PSS + rm]);
                a[i][1] = __float_as_uint(Ps[(kb + qid) * PSS + rm + 8]);
                a[i][2] = __float_as_uint(Ps[(kb + qid + 4) * PSS + rm]);
                a[i][3] = __float_as_uint(Ps[(kb + qid + 4) * PSS + rm + 8]);
            }
#pragma unroll
            for (int j = 0; j < 3; j++) {
                int cn = wnO + j * 8 + grp;
                b[j][0] = __float_as_uint(Vs[(kb + qid) * VSS + cn]);
                b[j][1] = __float_as_uint(Vs[(kb + qid + 4) * VSS + cn]);
            }
#pragma unroll
            for (int i = 0; i < 2; i++)
#pragma unroll
                for (int j = 0; j < 3; j++)
                    mma_tf32(oacc[i][j], a[i], b[j]);
        }
        __syncthreads();

        // ---- store prefetched tile t+1 into smem ----
        if (t + 1 < NKT) {
#pragma unroll
            for (int it = 0; it < 6; it++) {
                int idx = tid + it * 256;
                int r = idx / 24, d4 = (idx % 24) * 4;
                float kvv[4] = {kreg[it].x, kreg[it].y, kreg[it].z, kreg[it].w};
#pragma unroll
                for (int u = 0; u < 4; u++) {
                    int d = d4 + u;
                    Ks[d * QKS + (r ^ (((d >> 2) & 7) << 2))] = to_tf32(kvv[u]);
                }
                float4 vv = vreg[it];
                vv.x = to_tf32(vv.x); vv.y = to_tf32(vv.y);
                vv.z = to_tf32(vv.z); vv.w = to_tf32(vv.w);
                *(float4*)&Vs[r * VSS + d4] = vv;
            }
        }
        __syncthreads();
    }

    // ---- final normalize + store O ----
    if (tid < FQ) sm[OFF_AL + tid] = 1.f / sm[OFF_L + tid];
    __syncthreads();

#pragma unroll
    for (int i = 0; i < 2; i++)
#pragma unroll
        for (int h = 0; h < 2; h++) {
            int row = wmS + i * 16 + grp + h * 8;
            int gq = qb * FQ + row;
            if (gq >= NTOK) continue;
            float invl = sm[OFF_AL + row];
            float* op = x2 + (size_t)bb * NTOK * CDIM + (size_t)gq * CDIM + hh * HD;
#pragma unroll
            for (int j = 0; j < 3; j++) {
                int cn = wnO + j * 8 + qid * 2;
                *(float2*)(op + cn) = make_float2(oacc[i][j][h * 2] * invl,
                                                  oacc[i][j][h * 2 + 1] * invl);
            }
        }
}

// ---------------- pack QKV weights/bias into one matrix ----------------
__global__ void pack_qkv_k(const float* __restrict__ qw, const float* __restrict__ kw,
                           const float* __restrict__ vw, const float* __restrict__ qb,
                           const float* __restrict__ kb, const float* __restrict__ vb,
                           float* __restrict__ w, float* __restrict__ bias)
{
    int idx = blockIdx.x * 256 + threadIdx.x;
    int tot = 3 * CDIM * CDIM / 4;
    if (idx < tot) {
        int e = idx * 4;
        int which = e / (CDIM * CDIM);
        int off = e - which * (CDIM * CDIM);
        const float* src = which == 0 ? qw : which == 1 ? kw : vw;
        *(float4*)(w + e) = *(const float4*)(src + off);
    }
    if (idx < 3 * CDIM) {
        int which = idx / CDIM, off = idx % CDIM;
        bias[idx] = (which == 0 ? qb : which == 1 ? kb : vb)[off];
    }
}

// ---------------- im2col patch gather (float4) ----------------
__global__ void gather_k(const float* __restrict__ smri, float* __restrict__ pat) {
    int idx = blockIdx.x * 256 + threadIdx.x;
    if (idx >= BQ * NPATCH * 512 / 4) return;
    int e  = idx * 4;
    int kk = e & 511;
    int m  = e >> 9;
    int bb = m / NPATCH, p = m % NPATCH;
    int gx = p / (GD * GD), gy = (p / GD) % GD, gz = p % GD;
    int i = kk >> 6, j = (kk >> 3) & 7, kq = kk & 7;
    const float* src = smri + (((size_t)bb * IMG + gx * PSZ + i) * IMG + gy * PSZ + j) * IMG
                       + gz * PSZ + kq;
    *(float4*)(pat + e) = *(const float4*)src;
}

// ---------------- LN(patch embed) + cls + pos_embed ----------------
__global__ void ln_pos_k(const float* __restrict__ tmp, const float* __restrict__ g,
                         const float* __restrict__ b, const float* __restrict__ cls,
                         const float* __restrict__ pos, float* __restrict__ x)
{
    int bt = blockIdx.x;
    int bb = bt / NTOK, t = bt % NTOK;
    int tid = threadIdx.x;
    float* out = x + (size_t)bt * CDIM;
    const float* pp = pos + (size_t)t * CDIM;
    if (t == 0) {
        for (int c = tid; c < CDIM; c += 256) out[c] = cls[c] + pp[c];
        return;
    }
    const float* row = tmp + ((size_t)bb * NPATCH + (t - 1)) * CDIM;
    __shared__ float red[256];
    float s = 0.f, s2 = 0.f;
    for (int c = tid; c < CDIM; c += 256) { float v = row[c]; s += v; s2 += v * v; }
    red[tid] = s; __syncthreads();
    for (int st = 128; st > 0; st >>= 1) { if (tid < st) red[tid] += red[tid + st]; __syncthreads(); }
    float mean = red[0] / CDIM; __syncthreads();
    red[tid] = s2; __syncthreads();
    for (int st = 128; st > 0; st >>= 1) { if (tid < st) red[tid] += red[tid + st]; __syncthreads(); }
    float var = red[0] / CDIM - mean * mean;
    float inv = rsqrtf(var + 1e-5f);
    for (int c = tid; c < CDIM; c += 256)
        out[c] = (row[c] - mean) * inv * g[c] + b[c] + pp[c];
}

// ---------------- CLS-query attention for a branch ----------------
__global__ void cls_attn_k(const float* __restrict__ q0, const float* __restrict__ kv,
                           float* __restrict__ oc)
{
    int z = blockIdx.x;
    int bb = z / NHEAD, hh = z % NHEAD;
    __shared__ float sS[NTOK];
    __shared__ float sq[HD];
    __shared__ float red[128];
    int tid = threadIdx.x;
    for (int j = tid; j < HD; j += 128) sq[j] = q0[bb * CDIM + hh * HD + j];
    __syncthreads();
    const float scale = 0.10206207261596577f;
    float mx = -1e30f;
    for (int t = tid; t < NTOK; t += 128) {
        const float* kr = kv + ((size_t)(bb * NTOK + t)) * (2 * CDIM) + hh * HD;
        float s = 0.f;
        for (int j = 0; j < HD; j++) s += sq[j] * kr[j];
        s *= scale;
        sS[t] = s;
        mx = fmaxf(mx, s);
    }
    red[tid] = mx; __syncthreads();
    for (int st = 64; st > 0; st >>= 1) { if (tid < st) red[tid] = fmaxf(red[tid], red[tid + st]); __syncthreads(); }
    mx = red[0]; __syncthreads();
    float sm = 0.f;
    for (int t = tid; t < NTOK; t += 128) { float e = __expf(sS[t] - mx); sS[t] = e; sm += e; }
    red[tid] = sm; __syncthreads();
    for (int st = 64; st > 0; st >>= 1) { if (tid < st) red[tid] += red[tid + st]; __syncthreads(); }
    float inv = 1.f / red[0];
    __syncthreads();
    if (tid < HD) {
        float acc = 0.f;
        for (int t = 0; t < NTOK; t++)
            acc += sS[t] * kv[((size_t)(bb * NTOK + t)) * (2 * CDIM) + CDIM + hh * HD + tid];
        oc[bb * CDIM + hh * HD + tid] = acc * inv;
    }
}

// ---------------- LN + head on CLS ----------------
__global__ void head_k(const float* __restrict__ fin, const float* __restrict__ g,
                       const float* __restrict__ b, const float* __restrict__ hw,
                       const float* __restrict__ hb, float* __restrict__ out)
{
    int bb = blockIdx.x;
    const float* row = fin + bb * CDIM;
    __shared__ float red[256];
    __shared__ float sn[CDIM];
    int tid = threadIdx.x;
    float s = 0.f, s2 = 0.f;
    for (int c = tid; c < CDIM; c += 256) { float v = row[c]; s += v; s2 += v * v; }
    red[tid] = s; __syncthreads();
    for (int st = 128; st > 0; st >>= 1) { if (tid < st) red[tid] += red[tid + st]; __syncthreads(); }
    float mean = red[0] / CDIM; __syncthreads();
    red[tid] = s2; __syncthreads();
    for (int st = 128; st > 0; st >>= 1) { if (tid < st) red[tid] += red[tid + st]; __syncthreads(); }
    float var = red[0] / CDIM - mean * mean;
    float inv = rsqrtf(var + 1e-5f);
    for (int c = tid; c < CDIM; c += 256) sn[c] = (row[c] - mean) * inv * g[c] + b[c];
    __syncthreads();
    if (tid < NCLS) {
        float acc = hb[tid];
        for (int c = 0; c < CDIM; c++) acc += sn[c] * hw[tid * CDIM + c];
        out[bb * NCLS + tid] = acc;
    }
}

// ---------------- host ----------------
static inline int cdiv(int a, int b) { return (a + b - 1) / b; }

static void gemm_nt(const float* A, const float* B, const float* bias, float* C,
                    int M, int Nn, int K, int lda, int ldb, int ldc,
                    size_t sAb = 0, size_t sAh = 0, size_t sBb = 0, size_t sBh = 0,
                    size_t sCb = 0, size_t sCh = 0, int nh = 1, int batches = 1,
                    float alphaC = 1.f, const float* alphaPtr = nullptr, int accum = 0)
{
    dim3 grid(cdiv(Nn, 128), cdiv(M, 128), batches);
    gemm_k<1><<<grid, 256>>>(A, B, bias, C, M, Nn, K, lda, ldb, ldc,
                             sAb, sAh, sBb, sBh, sCb, sCh, nh, alphaC, alphaPtr, accum);
}

extern "C" void kernel_launch(void* const* d_in, const int* in_sizes, int n_in,
                              void* d_out, int out_size)
{
    const float* smri     = (const float*)d_in[0];
    const float* conv_w   = (const float*)d_in[2];
    const float* conv_b   = (const float*)d_in[3];
    const float* pe_ln_g  = (const float*)d_in[4];
    const float* pe_ln_b  = (const float*)d_in[5];
    const float* q_w      = (const float*)d_in[6];
    const float* q_b      = (const float*)d_in[7];
    const float* k_w      = (const float*)d_in[8];
    const float* k_b      = (const float*)d_in[9];
    const float* v_w      = (const float*)d_in[10];
    const float* v_b      = (const float*)d_in[11];
    const float* loc_in_w = (const float*)d_in[13];
    const float* loc_in_b = (const float*)d_in[14];
    const float* loc_out_w= (const float*)d_in[15];
    const float* loc_out_b= (const float*)d_in[16];
    const float* glob_in_w = (const float*)d_in[17];
    const float* glob_in_b = (const float*)d_in[18];
    const float* glob_out_w= (const float*)d_in[19];
    const float* glob_out_b= (const float*)d_in[20];
    const float* w_local  = (const float*)d_in[21];
    const float* w_global = (const float*)d_in[22];
    const float* cls_tok  = (const float*)d_in[23];
    const float* pos_emb  = (const float*)d_in[24];
    const float* head_ln_g= (const float*)d_in[25];
    const float* head_ln_b= (const float*)d_in[26];
    const float* head_w   = (const float*)d_in[27];
    const float* head_b   = (const float*)d_in[28];
    float* out = (float*)d_out;

    float *pat, *tmp, *x, *wqkv, *bqkv, *qkv, *x2, *kv, *q0, *oc, *fin;
    cudaGetSymbolAddress((void**)&pat,  g_pat);
    cudaGetSymbolAddress((void**)&tmp,  g_tmp);
    cudaGetSymbolAddress((void**)&x,    g_x);
    cudaGetSymbolAddress((void**)&wqkv, g_wqkv);
    cudaGetSymbolAddress((void**)&bqkv, g_bqkv);
    cudaGetSymbolAddress((void**)&qkv,  g_qkv);
    cudaGetSymbolAddress((void**)&x2,   g_x2);
    cudaGetSymbolAddress((void**)&kv,   g_kv);
    cudaGetSymbolAddress((void**)&q0,   g_q0);
    cudaGetSymbolAddress((void**)&oc,   g_oc);
    cudaGetSymbolAddress((void**)&fin,  g_fin);

    const size_t sT  = (size_t)NTOK * CDIM;

    static int flash_init = 0;
    if (!flash_init) {
        cudaFuncSetAttribute(flash_k, cudaFuncAttributeMaxDynamicSharedMemorySize,
                             FLASH_FLOATS * 4);
        flash_init = 1;
    }

    // 0) pack QKV weights
    pack_qkv_k<<<cdiv(3 * CDIM * CDIM / 4, 256), 256>>>(q_w, k_w, v_w, q_b, k_b, v_b,
                                                        wqkv, bqkv);

    // 1) patch im2col + embed GEMM
    gather_k<<<cdiv(BQ * NPATCH * 512 / 4, 256), 256>>>(smri, pat);
    gemm_nt(pat, conv_w, conv_b, tmp, BQ * NPATCH, CDIM, 512, 512, 512, CDIM);

    // 2) LN + cls + pos
    ln_pos_k<<<BQ * NTOK, 256>>>(tmp, pe_ln_g, pe_ln_b, cls_tok, pos_emb, x);

    // 3) fused QKV projection
    gemm_nt(x, wqkv, bqkv, qkv, BQ * NTOK, 3 * CDIM, CDIM, CDIM, CDIM, 3 * CDIM);

    // 4-6) single-pass fused flash attention (region bias softmax-invariant -> dropped)
    flash_k<<<dim3(cdiv(NTOK, FQ), BQ * NHEAD), 256, FLASH_FLOATS * 4>>>(qkv, x2);

    // 7) branches (only CLS row used downstream)
    gemm_nt(x2, loc_in_w + (size_t)CDIM * CDIM, loc_in_b + CDIM, kv,
            BQ * NTOK, 2 * CDIM, CDIM, CDIM, CDIM, 2 * CDIM);
    gemm_nt(x2, loc_in_w, loc_in_b, q0, BQ, CDIM, CDIM, (int)sT, CDIM, CDIM);
    cls_attn_k<<<BQ * NHEAD, 128>>>(q0, kv, oc);
    gemm_nt(oc, loc_out_w, loc_out_b, fin, BQ, CDIM, CDIM, CDIM, CDIM, CDIM,
            0, 0, 0, 0, 0, 0, 1, 1, 1.f, w_local, 0);
    gemm_nt(x2, glob_in_w + (size_t)CDIM * CDIM, glob_in_b + CDIM, kv,
            BQ * NTOK, 2 * CDIM, CDIM, CDIM, CDIM, 2 * CDIM);
    gemm_nt(x2, glob_in_w, glob_in_b, q0, BQ, CDIM, CDIM, (int)sT, CDIM, CDIM);
    cls_attn_k<<<BQ * NHEAD, 128>>>(q0, kv, oc);
    gemm_nt(oc, glob_out_w, glob_out_b, fin, BQ, CDIM, CDIM, CDIM, CDIM, CDIM,
            0, 0, 0, 0, 0, 0, 1, 1, 1.f, w_global, 1);

    // 8) head on CLS
    head_k<<<BQ, 256>>>(fin, head_ln_g, head_ln_b, head_w, head_b, out);
}

// round 13
// speedup vs baseline: 1.2666x; 1.1972x over previous
#include <cuda_runtime.h>
#include <math.h>

#define IMG 96
#define PSZ 8
#define GD 12
#define CDIM 768
#define NHEAD 8
#define HD 96
#define NPATCH 1728
#define NTOK 1729
#define BQ 2
#define NCLS 3

// ---------------- scratch (device globals) ----------------
__device__ float g_pat [(size_t)BQ * NPATCH * 512];
__device__ float g_tmp [(size_t)BQ * NPATCH * CDIM];
__device__ float g_x   [(size_t)BQ * NTOK * CDIM];
__device__ float g_wqkv[(size_t)3 * CDIM * CDIM];
__device__ float g_bqkv[3 * CDIM];
__device__ float g_qkv [(size_t)BQ * NTOK * 3 * CDIM];
__device__ float g_x2  [(size_t)BQ * NTOK * CDIM];
__device__ float g_wkv2[(size_t)4 * CDIM * CDIM];        // [loc K|V, glob K|V] x CDIM
__device__ float g_bkv2[4 * CDIM];
__device__ float g_wq2 [(size_t)2 * CDIM * CDIM];        // [loc q | glob q] x CDIM
__device__ float g_bq2 [2 * CDIM];
__device__ float g_kv  [(size_t)BQ * NTOK * 4 * CDIM];   // ld = 4*CDIM
__device__ float g_q0  [BQ * 2 * CDIM];
__device__ float g_oc  [2 * BQ * CDIM];                  // [branch][b][C]
__device__ float g_fin [BQ * CDIM];

__device__ __forceinline__ float to_tf32(float x) {
    unsigned u;
    asm("cvt.rna.tf32.f32 %0, %1;" : "=r"(u) : "f"(x));
    return __uint_as_float(u);
}

__device__ __forceinline__ float4 ld4_guard(const float* __restrict__ p, int gk, int K) {
    if (gk + 3 < K) return *(const float4*)(p + gk);
    float4 v = make_float4(0.f, 0.f, 0.f, 0.f);
    if (gk     < K) v.x = p[gk];
    if (gk + 1 < K) v.y = p[gk + 1];
    if (gk + 2 < K) v.z = p[gk + 2];
    return v;
}

__device__ __forceinline__ void mma_tf32(float* c, const unsigned* a, const unsigned* b) {
    asm("mma.sync.aligned.m16n8k8.row.col.f32.tf32.tf32.f32 "
        "{%0,%1,%2,%3}, {%4,%5,%6,%7}, {%8,%9}, {%0,%1,%2,%3};"
        : "+f"(c[0]), "+f"(c[1]), "+f"(c[2]), "+f"(c[3])
        : "r"(a[0]), "r"(a[1]), "r"(a[2]), "r"(a[3]), "r"(b[0]), "r"(b[1]));
}

// ---- 128x128x16 double-buffered GEMM on tf32 mma.sync (m16n8k8), fp32 accum ----
// (identical to the round-10 passing kernel)
template <int TRANS_B>
__global__ void __launch_bounds__(256, 2)
gemm_k(const float* __restrict__ A, const float* __restrict__ Bm,
       const float* __restrict__ bias, float* __restrict__ Cm,
       int M, int Nn, int K, int lda, int ldb, int ldc,
       size_t sAb, size_t sAh, size_t sBb, size_t sBh,
       size_t sCb, size_t sCh, int nh,
       float alphaC, const float* __restrict__ alphaPtr, int accum)
{
    int z = blockIdx.z;
    int bb = z / nh, hh = z % nh;
    A  += (size_t)bb * sAb + (size_t)hh * sAh;
    Bm += (size_t)bb * sBb + (size_t)hh * sBh;
    Cm += (size_t)bb * sCb + (size_t)hh * sCh;

    __shared__ __align__(16) float As[2][16][136];
    __shared__ __align__(16) float Bs[2][16][136];

    int tid = threadIdx.x;
    int m0 = blockIdx.y * 128, n0 = blockIdx.x * 128;

    int ar = tid >> 2;
    int ak = (tid & 3) * 4;
    int bk = tid >> 5;
    int bc = (tid & 31) * 4;

    int wid = tid >> 5, lane = tid & 31;
    int wm = (wid & 1) * 64, wn = (wid >> 1) * 32;
    int grp = lane >> 2, qid = lane & 3;

    float acc[4][4][4];
#pragma unroll
    for (int i = 0; i < 4; i++)
#pragma unroll
        for (int j = 0; j < 4; j++)
#pragma unroll
            for (int r = 0; r < 4; r++) acc[i][j][r] = 0.f;

    float4 pa[2], pb[2];
    int ktiles = (K + 15) / 16;

    {
        int k0 = 0;
#pragma unroll
        for (int h = 0; h < 2; h++) {
            int gm = m0 + ar + h * 64;
            pa[h] = (gm < M) ? ld4_guard(A + (size_t)gm * lda, k0 + ak, K)
                             : make_float4(0.f, 0.f, 0.f, 0.f);
        }
        if (TRANS_B) {
#pragma unroll
            for (int h = 0; h < 2; h++) {
                int gn = n0 + ar + h * 64;
                pb[h] = (gn < Nn) ? ld4_guard(Bm + (size_t)gn * ldb, k0 + ak, K)
                                  : make_float4(0.f, 0.f, 0.f, 0.f);
            }
        } else {
#pragma unroll
            for (int h = 0; h < 2; h++) {
                int gk = k0 + bk + h * 8;
                int gn = n0 + bc;
                float4 v = make_float4(0.f, 0.f, 0.f, 0.f);
                if (gk < K) {
                    const float* rp = Bm + (size_t)gk * ldb;
                    if (gn + 3 < Nn) v = *(const float4*)(rp + gn);
                    else {
                        if (gn     < Nn) v.x = rp[gn];
                        if (gn + 1 < Nn) v.y = rp[gn + 1];
                        if (gn + 2 < Nn) v.z = rp[gn + 2];
                    }
                }
                pb[h] = v;
            }
        }
#pragma unroll
        for (int h = 0; h < 2; h++) {
            int r = ar + h * 64;
            As[0][ak + 0][r] = to_tf32(pa[h].x); As[0][ak + 1][r] = to_tf32(pa[h].y);
            As[0][ak + 2][r] = to_tf32(pa[h].z); As[0][ak + 3][r] = to_tf32(pa[h].w);
        }
        if (TRANS_B) {
#pragma unroll
            for (int h = 0; h < 2; h++) {
                int r = ar + h * 64;
                Bs[0][ak + 0][r] = to_tf32(pb[h].x); Bs[0][ak + 1][r] = to_tf32(pb[h].y);
                Bs[0][ak + 2][r] = to_tf32(pb[h].z); Bs[0][ak + 3][r] = to_tf32(pb[h].w);
            }
        } else {
#pragma unroll
            for (int h = 0; h < 2; h++) {
                float4 v = pb[h];
                v.x = to_tf32(v.x); v.y = to_tf32(v.y);
                v.z = to_tf32(v.z); v.w = to_tf32(v.w);
                *(float4*)&Bs[0][bk + h * 8][bc] = v;
            }
        }
    }
    __syncthreads();

    for (int t = 0; t < ktiles; t++) {
        int cur = t & 1;
        if (t + 1 < ktiles) {
            int k0 = (t + 1) * 16;
#pragma unroll
            for (int h = 0; h < 2; h++) {
                int gm = m0 + ar + h * 64;
                pa[h] = (gm < M) ? ld4_guard(A + (size_t)gm * lda, k0 + ak, K)
                                 : make_float4(0.f, 0.f, 0.f, 0.f);
            }
            if (TRANS_B) {
#pragma unroll
                for (int h = 0; h < 2; h++) {
                    int gn = n0 + ar + h * 64;
                    pb[h] = (gn < Nn) ? ld4_guard(Bm + (size_t)gn * ldb, k0 + ak, K)
                                      : make_float4(0.f, 0.f, 0.f, 0.f);
                }
            } else {
#pragma unroll
                for (int h = 0; h < 2; h++) {
                    int gk = k0 + bk + h * 8;
                    int gn = n0 + bc;
                    float4 v = make_float4(0.f, 0.f, 0.f, 0.f);
                    if (gk < K) {
                        const float* rp = Bm + (size_t)gk * ldb;
                        if (gn + 3 < Nn) v = *(const float4*)(rp + gn);
                        else {
                            if (gn     < Nn) v.x = rp[gn];
                            if (gn + 1 < Nn) v.y = rp[gn + 1];
                            if (gn + 2 < Nn) v.z = rp[gn + 2];
                        }
                    }
                    pb[h] = v;
                }
            }
        }

#pragma unroll
        for (int ks = 0; ks < 2; ks++) {
            int kb = ks * 8;
            unsigned a[4][4], b[4][2];
#pragma unroll
            for (int i = 0; i < 4; i++) {
                int rm = wm + i * 16 + grp;
                a[i][0] = __float_as_uint(As[cur][kb + qid][rm]);
                a[i][1] = __float_as_uint(As[cur][kb + qid][rm + 8]);
                a[i][2] = __float_as_uint(As[cur][kb + qid + 4][rm]);
                a[i][3] = __float_as_uint(As[cur][kb + qid + 4][rm + 8]);
            }
#pragma unroll
            for (int j = 0; j < 4; j++) {
                int cn = wn + j * 8 + grp;
                b[j][0] = __float_as_uint(Bs[cur][kb + qid][cn]);
                b[j][1] = __float_as_uint(Bs[cur][kb + qid + 4][cn]);
            }
#pragma unroll
            for (int i = 0; i < 4; i++)
#pragma unroll
                for (int j = 0; j < 4; j++)
                    mma_tf32(acc[i][j], a[i], b[j]);
        }

        if (t + 1 < ktiles) {
            int nxt = cur ^ 1;
#pragma unroll
            for (int h = 0; h < 2; h++) {
                int r = ar + h * 64;
                As[nxt][ak + 0][r] = to_tf32(pa[h].x); As[nxt][ak + 1][r] = to_tf32(pa[h].y);
                As[nxt][ak + 2][r] = to_tf32(pa[h].z); As[nxt][ak + 3][r] = to_tf32(pa[h].w);
            }
            if (TRANS_B) {
#pragma unroll
                for (int h = 0; h < 2; h++) {
                    int r = ar + h * 64;
                    Bs[nxt][ak + 0][r] = to_tf32(pb[h].x); Bs[nxt][ak + 1][r] = to_tf32(pb[h].y);
                    Bs[nxt][ak + 2][r] = to_tf32(pb[h].z); Bs[nxt][ak + 3][r] = to_tf32(pb[h].w);
                }
            } else {
#pragma unroll
                for (int h = 0; h < 2; h++) {
                    float4 v = pb[h];
                    v.x = to_tf32(v.x); v.y = to_tf32(v.y);
                    v.z = to_tf32(v.z); v.w = to_tf32(v.w);
                    *(float4*)&Bs[nxt][bk + h * 8][bc] = v;
                }
            }
            __syncthreads();
        }
    }

    float alpha = alphaC * (alphaPtr ? *alphaPtr : 1.f);
#pragma unroll
    for (int i = 0; i < 4; i++) {
#pragma unroll
        for (int j = 0; j < 4; j++) {
            int c0 = n0 + wn + j * 8 + qid * 2;
#pragma unroll
            for (int h = 0; h < 2; h++) {
                int r = m0 + wm + i * 16 + grp + h * 8;
                if (r >= M) continue;
                float v0 = acc[i][j][h * 2], v1 = acc[i][j][h * 2 + 1];
                if (bias) {
                    if (c0     < Nn) v0 += bias[c0];
                    if (c0 + 1 < Nn) v1 += bias[c0 + 1];
                }
                v0 *= alpha; v1 *= alpha;
                size_t off = (size_t)r * ldc + c0;
                if (c0 + 1 < Nn && ((ldc & 1) == 0)) {
                    if (accum) { v0 += Cm[off]; v1 += Cm[off + 1]; }
                    *(float2*)(Cm + off) = make_float2(v0, v1);
                } else {
                    if (c0 < Nn) {
                        if (accum) v0 += Cm[off];
                        Cm[off] = v0;
                    }
                    if (c0 + 1 < Nn) {
                        if (accum) v1 += Cm[off + 1];
                        Cm[off + 1] = v1;
                    }
                }
            }
        }
    }
}

// ====== single-pass fused flash attention (identical to round-10 passing) ======
#define FQ 64
#define FK 64
#define NKT 28
#define QKS 72
#define PSS 72
#define VSS 104
#define OFF_QS 0
#define OFF_KS (OFF_QS + 96 * QKS)
#define OFF_PS (OFF_KS + 96 * QKS)
#define OFF_VS (OFF_PS + FK * PSS)
#define OFF_M  (OFF_VS + FK * VSS)
#define OFF_L  (OFF_M + FQ)
#define OFF_AL (OFF_L + FQ)
#define OFF_PM (OFF_AL + FQ)
#define OFF_PSUM (OFF_PM + 4 * FQ)
#define FLASH_FLOATS (OFF_PSUM + 4 * FQ)

__device__ __forceinline__ unsigned ldsw(const float* base, int d, int col) {
    return __float_as_uint(base[d * QKS + (col ^ (((d >> 2) & 7) << 2))]);
}

__global__ void __launch_bounds__(256, 2)
flash_k(const float* __restrict__ qkv, float* __restrict__ x2)
{
    extern __shared__ float sm[];
    float* Qs = sm + OFF_QS;
    float* Ks = sm + OFF_KS;
    float* Ps = sm + OFF_PS;
    float* Vs = sm + OFF_VS;

    int tid = threadIdx.x;
    int wid = tid >> 5, lane = tid & 31;
    int grp = lane >> 2, qid = lane & 3;
    int wmS = (wid & 1) * 32;
    int wnS = (wid >> 1) * 16;
    int wnO = (wid >> 1) * 24;
    int nw = wid >> 1;

    int qb = blockIdx.x;
    int bb = blockIdx.y >> 3, hh = blockIdx.y & 7;
    const float scale = 0.10206207261596577f;
    size_t base = (size_t)bb * NTOK * (3 * CDIM) + (size_t)hh * HD;

#pragma unroll
    for (int it = 0; it < 6; it++) {
        int idx = tid + it * 256;
        int r = idx / 24, d4 = (idx % 24) * 4;
        int gq = qb * FQ + r;
        float4 v = make_float4(0.f, 0.f, 0.f, 0.f);
        if (gq < NTOK) v = *(const float4*)(qkv + base + (size_t)gq * (3 * CDIM) + d4);
#pragma unroll
        for (int u = 0; u < 4; u++) {
            int d = d4 + u;
            float val = u == 0 ? v.x : u == 1 ? v.y : u == 2 ? v.z : v.w;
            Qs[d * QKS + (r ^ (((d >> 2) & 7) << 2))] = to_tf32(val);
        }
    }
    if (tid < FQ) { sm[OFF_M + tid] = -1e30f; sm[OFF_L + tid] = 0.f; }

    float4 kreg[6], vreg[6];
#pragma unroll
    for (int it = 0; it < 6; it++) {
        int idx = tid + it * 256;
        int r = idx / 24, d4 = (idx % 24) * 4;
        const float* rp = qkv + base + (size_t)r * (3 * CDIM);
        kreg[it] = *(const float4*)(rp + CDIM + d4);
        vreg[it] = *(const float4*)(rp + 2 * CDIM + d4);
    }
#pragma unroll
    for (int it = 0; it < 6; it++) {
        int idx = tid + it * 256;
        int r = idx / 24, d4 = (idx % 24) * 4;
        float kvv[4] = {kreg[it].x, kreg[it].y, kreg[it].z, kreg[it].w};
#pragma unroll
        for (int u = 0; u < 4; u++) {
            int d = d4 + u;
            Ks[d * QKS + (r ^ (((d >> 2) & 7) << 2))] = to_tf32(kvv[u]);
        }
        float4 vv = vreg[it];
        vv.x = to_tf32(vv.x); vv.y = to_tf32(vv.y);
        vv.z = to_tf32(vv.z); vv.w = to_tf32(vv.w);
        *(float4*)&Vs[r * VSS + d4] = vv;
    }
    __syncthreads();

    float oacc[2][3][4];
#pragma unroll
    for (int i = 0; i < 2; i++)
#pragma unroll
        for (int j = 0; j < 3; j++)
#pragma unroll
            for (int r = 0; r < 4; r++) oacc[i][j][r] = 0.f;

    for (int t = 0; t < NKT; t++) {
        int t0 = t * FK;

        if (t + 1 < NKT) {
            int t1 = t0 + FK;
#pragma unroll
            for (int it = 0; it < 6; it++) {
                int idx = tid + it * 256;
                int r = idx / 24, d4 = (idx % 24) * 4;
                int gk = t1 + r;
                kreg[it] = make_float4(0.f, 0.f, 0.f, 0.f);
                vreg[it] = make_float4(0.f, 0.f, 0.f, 0.f);
                if (gk < NTOK) {
                    const float* rp = qkv + base + (size_t)gk * (3 * CDIM);
                    kreg[it] = *(const float4*)(rp + CDIM + d4);
                    vreg[it] = *(const float4*)(rp + 2 * CDIM + d4);
                }
            }
        }

        float sacc[2][2][4];
#pragma unroll
        for (int i = 0; i < 2; i++)
#pragma unroll
            for (int j = 0; j < 2; j++)
#pragma unroll
                for (int r = 0; r < 4; r++) sacc[i][j][r] = 0.f;
#pragma unroll
        for (int ks = 0; ks < 12; ks++) {
            int kb = ks * 8;
            unsigned a[2][4], b[2][2];
#pragma unroll
            for (int i = 0; i < 2; i++) {
                int rm = wmS + i * 16 + grp;
                a[i][0] = ldsw(Qs, kb + qid, rm);
                a[i][1] = ldsw(Qs, kb + qid, rm + 8);
                a[i][2] = ldsw(Qs, kb + qid + 4, rm);
                a[i][3] = ldsw(Qs, kb + qid + 4, rm + 8);
            }
#pragma unroll
            for (int j = 0; j < 2; j++) {
                int cn = wnS + j * 8 + grp;
                b[j][0] = ldsw(Ks, kb + qid, cn);
                b[j][1] = ldsw(Ks, kb + qid + 4, cn);
            }
#pragma unroll
            for (int i = 0; i < 2; i++)
#pragma unroll
                for (int j = 0; j < 2; j++)
                    mma_tf32(sacc[i][j], a[i], b[j]);
        }

#pragma unroll
        for (int i = 0; i < 2; i++)
#pragma unroll
            for (int h = 0; h < 2; h++) {
                int row = wmS + i * 16 + grp + h * 8;
                float vm = -1e30f;
#pragma unroll
                for (int j = 0; j < 2; j++)
#pragma unroll
                    for (int u = 0; u < 2; u++) {
                        int c = wnS + j * 8 + qid * 2 + u;
                        if (t0 + c < NTOK) vm = fmaxf(vm, sacc[i][j][h * 2 + u] * scale);
                    }
                vm = fmaxf(vm, __shfl_xor_sync(0xffffffffu, vm, 1));
                vm = fmaxf(vm, __shfl_xor_sync(0xffffffffu, vm, 2));
                if (qid == 0) sm[OFF_PM + nw * FQ + row] = vm;
            }
        __syncthreads();

        if (tid < FQ) {
            float mt = fmaxf(fmaxf(sm[OFF_PM + tid], sm[OFF_PM + FQ + tid]),
                             fmaxf(sm[OFF_PM + 2 * FQ + tid], sm[OFF_PM + 3 * FQ + tid]));
            float mo = sm[OFF_M + tid];
            float mn = fmaxf(mo, mt);
            sm[OFF_AL + tid] = __expf(mo - mn);
            sm[OFF_M + tid] = mn;
        }
        __syncthreads();

#pragma unroll
        for (int i = 0; i < 2; i++)
#pragma unroll
            for (int h = 0; h < 2; h++) {
                int row = wmS + i * 16 + grp + h * 8;
                float mrow = sm[OFF_M + row];
                float alpha = sm[OFF_AL + row];
#pragma unroll
                for (int j = 0; j < 3; j++) {
                    oacc[i][j][h * 2]     *= alpha;
                    oacc[i][j][h * 2 + 1] *= alpha;
                }
                float rs = 0.f;
#pragma unroll
                for (int j = 0; j < 2; j++)
#pragma unroll
                    for (int u = 0; u < 2; u++) {
                        int c = wnS + j * 8 + qid * 2 + u;
                        float p = 0.f;
                        if (t0 + c < NTOK)
                            p = __expf(sacc[i][j][h * 2 + u] * scale - mrow);
                        Ps[c * PSS + row] = to_tf32(p);
                        rs += p;
                    }
                rs += __shfl_xor_sync(0xffffffffu, rs, 1);
                rs += __shfl_xor_sync(0xffffffffu, rs, 2);
                if (qid == 0) sm[OFF_PSUM + nw * FQ + row] = rs;
            }
        __syncthreads();

        if (tid < FQ)
            sm[OFF_L + tid] = sm[OFF_L + tid] * sm[OFF_AL + tid]
                            + sm[OFF_PSUM + tid] + sm[OFF_PSUM + FQ + tid]
                            + sm[OFF_PSUM + 2 * FQ + tid] + sm[OFF_PSUM + 3 * FQ + tid];

#pragma unroll
        for (int ks = 0; ks < 8; ks++) {
            int kb = ks * 8;
            unsigned a[2][4], b[3][2];
#pragma unroll
            for (int i = 0; i < 2; i++) {
                int rm = wmS + i * 16 + grp;
                a[i][0] = __float_as_uint(Ps[(kb + qid) * PSS + rm]);
                a[i][1] = __float_as_uint(Ps[(kb + qid) * PSS + rm + 8]);
                a[i][2] = __float_as_uint(Ps[(kb + qid + 4) * PSS + rm]);
                a[i][3] = __float_as_uint(Ps[(kb + qid + 4) * PSS + rm + 8]);
            }
#pragma unroll
            for (int j = 0; j < 3; j++) {
                int cn = wnO + j * 8 + grp;
                b[j][0] = __float_as_uint(Vs[(kb + qid) * VSS + cn]);
                b[j][1] = __float_as_uint(Vs[(kb + qid + 4) * VSS + cn]);
            }
#pragma unroll
            for (int i = 0; i < 2; i++)
#pragma unroll
                for (int j = 0; j < 3; j++)
                    mma_tf32(oacc[i][j], a[i], b[j]);
        }
        __syncthreads();

        if (t + 1 < NKT) {
#pragma unroll
            for (int it = 0; it < 6; it++) {
                int idx = tid + it * 256;
                int r = idx / 24, d4 = (idx % 24) * 4;
                float kvv[4] = {kreg[it].x, kreg[it].y, kreg[it].z, kreg[it].w};
#pragma unroll
                for (int u = 0; u < 4; u++) {
                    int d = d4 + u;
                    Ks[d * QKS + (r ^ (((d >> 2) & 7) << 2))] = to_tf32(kvv[u]);
                }
                float4 vv = vreg[it];
                vv.x = to_tf32(vv.x); vv.y = to_tf32(vv.y);
                vv.z = to_tf32(vv.z); vv.w = to_tf32(vv.w);
                *(float4*)&Vs[r * VSS + d4] = vv;
            }
        }
        __syncthreads();
    }

    if (tid < FQ) sm[OFF_AL + tid] = 1.f / sm[OFF_L + tid];
    __syncthreads();

#pragma unroll
    for (int i = 0; i < 2; i++)
#pragma unroll
        for (int h = 0; h < 2; h++) {
            int row = wmS + i * 16 + grp + h * 8;
            int gq = qb * FQ + row;
            if (gq >= NTOK) continue;
            float invl = sm[OFF_AL + row];
            float* op = x2 + (size_t)bb * NTOK * CDIM + (size_t)gq * CDIM + hh * HD;
#pragma unroll
            for (int j = 0; j < 3; j++) {
                int cn = wnO + j * 8 + qid * 2;
                *(float2*)(op + cn) = make_float2(oacc[i][j][h * 2] * invl,
                                                  oacc[i][j][h * 2 + 1] * invl);
            }
        }
}

// ---------------- pack QKV weights/bias (proven) ----------------
__global__ void pack_qkv_k(const float* __restrict__ qw, const float* __restrict__ kw,
                           const float* __restrict__ vw, const float* __restrict__ qb,
                           const float* __restrict__ kb, const float* __restrict__ vb,
                           float* __restrict__ w, float* __restrict__ bias)
{
    int idx = blockIdx.x * 256 + threadIdx.x;
    int tot = 3 * CDIM * CDIM / 4;
    if (idx < tot) {
        int e = idx * 4;
        int which = e / (CDIM * CDIM);
        int off = e - which * (CDIM * CDIM);
        const float* src = which == 0 ? qw : which == 1 ? kw : vw;
        *(float4*)(w + e) = *(const float4*)(src + off);
    }
    if (idx < 3 * CDIM) {
        int which = idx / CDIM, off = idx % CDIM;
        bias[idx] = (which == 0 ? qb : which == 1 ? kb : vb)[off];
    }
}

// ---------------- pack branch weights: wkv2 (4C x C), wq2 (2C x C) ----------------
__global__ void pack_branch_k(const float* __restrict__ lw, const float* __restrict__ lb,
                              const float* __restrict__ gw, const float* __restrict__ gb,
                              float* __restrict__ wkv2, float* __restrict__ bkv2,
                              float* __restrict__ wq2, float* __restrict__ bq2)
{
    int idx = blockIdx.x * 256 + threadIdx.x;
    const int W1 = 4 * CDIM * CDIM / 4;          // wkv2 float4 count
    const int W2 = 2 * CDIM * CDIM / 4;          // wq2 float4 count
    if (idx < W1) {
        int e = idx * 4;
        int row = e / CDIM, col = e % CDIM;
        const float* src = row < 2 * CDIM
            ? lw + (size_t)(CDIM + row) * CDIM
            : gw + (size_t)(CDIM + row - 2 * CDIM) * CDIM;
        *(float4*)(wkv2 + e) = *(const float4*)(src + col);
    } else if (idx < W1 + W2) {
        int e = (idx - W1) * 4;
        int row = e / CDIM, col = e % CDIM;
        const float* src = row < CDIM ? lw + (size_t)row * CDIM
                                      : gw + (size_t)(row - CDIM) * CDIM;
        *(float4*)(wq2 + e) = *(const float4*)(src + col);
    }
    if (idx < 4 * CDIM)
        bkv2[idx] = idx < 2 * CDIM ? lb[CDIM + idx] : gb[CDIM + idx - 2 * CDIM];
    if (idx < 2 * CDIM)
        bq2[idx] = idx < CDIM ? lb[idx] : gb[idx - CDIM];
}

// ---------------- im2col patch gather (proven) ----------------
__global__ void gather_k(const float* __restrict__ smri, float* __restrict__ pat) {
    int idx = blockIdx.x * 256 + threadIdx.x;
    if (idx >= BQ * NPATCH * 512 / 4) return;
    int e  = idx * 4;
    int kk = e & 511;
    int m  = e >> 9;
    int bb = m / NPATCH, p = m % NPATCH;
    int gx = p / (GD * GD), gy = (p / GD) % GD, gz = p % GD;
    int i = kk >> 6, j = (kk >> 3) & 7, kq = kk & 7;
    const float* src = smri + (((size_t)bb * IMG + gx * PSZ + i) * IMG + gy * PSZ + j) * IMG
                       + gz * PSZ + kq;
    *(float4*)(pat + e) = *(const float4*)src;
}

// ---------------- LN(patch embed) + cls + pos_embed ----------------
__global__ void ln_pos_k(const float* __restrict__ tmp, const float* __restrict__ g,
                         const float* __restrict__ b, const float* __restrict__ cls,
                         const float* __restrict__ pos, float* __restrict__ x)
{
    int bt = blockIdx.x;
    int bb = bt / NTOK, t = bt % NTOK;
    int tid = threadIdx.x;
    float* out = x + (size_t)bt * CDIM;
    const float* pp = pos + (size_t)t * CDIM;
    if (t == 0) {
        for (int c = tid; c < CDIM; c += 256) out[c] = cls[c] + pp[c];
        return;
    }
    const float* row = tmp + ((size_t)bb * NPATCH + (t - 1)) * CDIM;
    __shared__ float red[256];
    float s = 0.f, s2 = 0.f;
    for (int c = tid; c < CDIM; c += 256) { float v = row[c]; s += v; s2 += v * v; }
    red[tid] = s; __syncthreads();
    for (int st = 128; st > 0; st >>= 1) { if (tid < st) red[tid] += red[tid + st]; __syncthreads(); }
    float mean = red[0] / CDIM; __syncthreads();
    red[tid] = s2; __syncthreads();
    for (int st = 128; st > 0; st >>= 1) { if (tid < st) red[tid] += red[tid + st]; __syncthreads(); }
    float var = red[0] / CDIM - mean * mean;
    float inv = rsqrtf(var + 1e-5f);
    for (int c = tid; c < CDIM; c += 256)
        out[c] = (row[c] - mean) * inv * g[c] + b[c] + pp[c];
}

// ---------------- CLS-query attention: both branches, one launch ----------------
// kv ld = 4*CDIM: [loc K | loc V | glob K | glob V]
__global__ void cls_attn_k(const float* __restrict__ q0, const float* __restrict__ kv,
                           float* __restrict__ oc)
{
    int z = blockIdx.x;                // 0..31
    int br = z >> 4;
    int bb = (z >> 3) & 1;
    int hh = z & 7;
    __shared__ float sS[NTOK];
    __shared__ float sq[HD];
    __shared__ float red[128];
    int tid = threadIdx.x;
    for (int j = tid; j < HD; j += 128)
        sq[j] = q0[bb * 2 * CDIM + br * CDIM + hh * HD + j];
    __syncthreads();
    const float scale = 0.10206207261596577f;
    float mx = -1e30f;
    for (int t = tid; t < NTOK; t += 128) {
        const float* kr = kv + (size_t)(bb * NTOK + t) * (4 * CDIM) + br * 2 * CDIM + hh * HD;
        float s = 0.f;
        for (int j = 0; j < HD; j++) s += sq[j] * kr[j];
        s *= scale;
        sS[t] = s;
        mx = fmaxf(mx, s);
    }
    red[tid] = mx; __syncthreads();
    for (int st = 64; st > 0; st >>= 1) { if (tid < st) red[tid] = fmaxf(red[tid], red[tid + st]); __syncthreads(); }
    mx = red[0]; __syncthreads();
    float sm = 0.f;
    for (int t = tid; t < NTOK; t += 128) { float e = __expf(sS[t] - mx); sS[t] = e; sm += e; }
    red[tid] = sm; __syncthreads();
    for (int st = 64; st > 0; st >>= 1) { if (tid < st) red[tid] += red[tid + st]; __syncthreads(); }
    float inv = 1.f / red[0];
    __syncthreads();
    if (tid < HD) {
        float acc = 0.f;
        for (int t = 0; t < NTOK; t++)
            acc += sS[t] * kv[(size_t)(bb * NTOK + t) * (4 * CDIM) + br * 2 * CDIM + CDIM
                              + hh * HD + tid];
        oc[(br * BQ + bb) * CDIM + hh * HD + tid] = acc * inv;
    }
}

// ---------------- LN + head on CLS ----------------
__global__ void head_k(const float* __restrict__ fin, const float* __restrict__ g,
                       const float* __restrict__ b, const float* __restrict__ hw,
                       const float* __restrict__ hb, float* __restrict__ out)
{
    int bb = blockIdx.x;
    const float* row = fin + bb * CDIM;
    __shared__ float red[256];
    __shared__ float sn[CDIM];
    int tid = threadIdx.x;
    float s = 0.f, s2 = 0.f;
    for (int c = tid; c < CDIM; c += 256) { float v = row[c]; s += v; s2 += v * v; }
    red[tid] = s; __syncthreads();
    for (int st = 128; st > 0; st >>= 1) { if (tid < st) red[tid] += red[tid + st]; __syncthreads(); }
    float mean = red[0] / CDIM; __syncthreads();
    red[tid] = s2; __syncthreads();
    for (int st = 128; st > 0; st >>= 1) { if (tid < st) red[tid] += red[tid + st]; __syncthreads(); }
    float var = red[0] / CDIM - mean * mean;
    float inv = rsqrtf(var + 1e-5f);
    for (int c = tid; c < CDIM; c += 256) sn[c] = (row[c] - mean) * inv * g[c] + b[c];
    __syncthreads();
    if (tid < NCLS) {
        float acc = hb[tid];
        for (int c = 0; c < CDIM; c++) acc += sn[c] * hw[tid * CDIM + c];
        out[bb * NCLS + tid] = acc;
    }
}

// ---------------- host ----------------
static inline int cdiv(int a, int b) { return (a + b - 1) / b; }

static void gemm_nt(const float* A, const float* B, const float* bias, float* C,
                    int M, int Nn, int K, int lda, int ldb, int ldc,
                    size_t sAb = 0, size_t sAh = 0, size_t sBb = 0, size_t sBh = 0,
                    size_t sCb = 0, size_t sCh = 0, int nh = 1, int batches = 1,
                    float alphaC = 1.f, const float* alphaPtr = nullptr, int accum = 0)
{
    dim3 grid(cdiv(Nn, 128), cdiv(M, 128), batches);
    gemm_k<1><<<grid, 256>>>(A, B, bias, C, M, Nn, K, lda, ldb, ldc,
                             sAb, sAh, sBb, sBh, sCb, sCh, nh, alphaC, alphaPtr, accum);
}

extern "C" void kernel_launch(void* const* d_in, const int* in_sizes, int n_in,
                              void* d_out, int out_size)
{
    const float* smri     = (const float*)d_in[0];
    const float* conv_w   = (const float*)d_in[2];
    const float* conv_b   = (const float*)d_in[3];
    const float* pe_ln_g  = (const float*)d_in[4];
    const float* pe_ln_b  = (const float*)d_in[5];
    const float* q_w      = (const float*)d_in[6];
    const float* q_b      = (const float*)d_in[7];
    const float* k_w      = (const float*)d_in[8];
    const float* k_b      = (const float*)d_in[9];
    const float* v_w      = (const float*)d_in[10];
    const float* v_b      = (const float*)d_in[11];
    const float* loc_in_w = (const float*)d_in[13];
    const float* loc_in_b = (const float*)d_in[14];
    const float* loc_out_w= (const float*)d_in[15];
    const float* loc_out_b= (const float*)d_in[16];
    const float* glob_in_w = (const float*)d_in[17];
    const float* glob_in_b = (const float*)d_in[18];
    const float* glob_out_w= (const float*)d_in[19];
    const float* glob_out_b= (const float*)d_in[20];
    const float* w_local  = (const float*)d_in[21];
    const float* w_global = (const float*)d_in[22];
    const float* cls_tok  = (const float*)d_in[23];
    const float* pos_emb  = (const float*)d_in[24];
    const float* head_ln_g= (const float*)d_in[25];
    const float* head_ln_b= (const float*)d_in[26];
    const float* head_w   = (const float*)d_in[27];
    const float* head_b   = (const float*)d_in[28];
    float* out = (float*)d_out;

    float *pat, *tmp, *x, *wqkv, *bqkv, *qkv, *x2, *wkv2, *bkv2, *wq2, *bq2,
          *kv, *q0, *oc, *fin;
    cudaGetSymbolAddress((void**)&pat,  g_pat);
    cudaGetSymbolAddress((void**)&tmp,  g_tmp);
    cudaGetSymbolAddress((void**)&x,    g_x);
    cudaGetSymbolAddress((void**)&wqkv, g_wqkv);
    cudaGetSymbolAddress((void**)&bqkv, g_bqkv);
    cudaGetSymbolAddress((void**)&qkv,  g_qkv);
    cudaGetSymbolAddress((void**)&x2,   g_x2);
    cudaGetSymbolAddress((void**)&wkv2, g_wkv2);
    cudaGetSymbolAddress((void**)&bkv2, g_bkv2);
    cudaGetSymbolAddress((void**)&wq2,  g_wq2);
    cudaGetSymbolAddress((void**)&bq2,  g_bq2);
    cudaGetSymbolAddress((void**)&kv,   g_kv);
    cudaGetSymbolAddress((void**)&q0,   g_q0);
    cudaGetSymbolAddress((void**)&oc,   g_oc);
    cudaGetSymbolAddress((void**)&fin,  g_fin);

    const size_t sT = (size_t)NTOK * CDIM;

    static int flash_init = 0;
    if (!flash_init) {
        cudaFuncSetAttribute(flash_k, cudaFuncAttributeMaxDynamicSharedMemorySize,
                             FLASH_FLOATS * 4);
        flash_init = 1;
    }

    // 0) pack weights (QKV + both branches)
    pack_qkv_k<<<cdiv(3 * CDIM * CDIM / 4, 256), 256>>>(q_w, k_w, v_w, q_b, k_b, v_b,
                                                        wqkv, bqkv);
    pack_branch_k<<<cdiv(6 * CDIM * CDIM / 4, 256), 256>>>(loc_in_w, loc_in_b,
                                                           glob_in_w, glob_in_b,
                                                           wkv2, bkv2, wq2, bq2);

    // 1) patch im2col + embed GEMM
    gather_k<<<cdiv(BQ * NPATCH * 512 / 4, 256), 256>>>(smri, pat);
    gemm_nt(pat, conv_w, conv_b, tmp, BQ * NPATCH, CDIM, 512, 512, 512, CDIM);

    // 2) LN + cls + pos
    ln_pos_k<<<BQ * NTOK, 256>>>(tmp, pe_ln_g, pe_ln_b, cls_tok, pos_emb, x);

    // 3) fused QKV projection
    gemm_nt(x, wqkv, bqkv, qkv, BQ * NTOK, 3 * CDIM, CDIM, CDIM, CDIM, 3 * CDIM);

    // 4-6) single-pass fused flash attention (region bias softmax-invariant -> dropped)
    flash_k<<<dim3(cdiv(NTOK, FQ), BQ * NHEAD), 256, FLASH_FLOATS * 4>>>(qkv, x2);

    // 7) ONE KV GEMM for both branches (packed weights), ld=4*CDIM
    gemm_nt(x2, wkv2, bkv2, kv, BQ * NTOK, 4 * CDIM, CDIM, CDIM, CDIM, 4 * CDIM);

    // one q0 GEMM for both branches
    gemm_nt(x2, wq2, bq2, q0, BQ, 2 * CDIM, CDIM, (int)sT, CDIM, 2 * CDIM);

    // both branches' CLS attention in one launch
    cls_attn_k<<<32, 128>>>(q0, kv, oc);

    // out-projections (weighted accumulate into fin)
    gemm_nt(oc, loc_out_w, loc_out_b, fin, BQ, CDIM, CDIM, CDIM, CDIM, CDIM,
            0, 0, 0, 0, 0, 0, 1, 1, 1.f, w_local, 0);
    gemm_nt(oc + BQ * CDIM, glob_out_w, glob_out_b, fin, BQ, CDIM, CDIM, CDIM, CDIM, CDIM,
            0, 0, 0, 0, 0, 0, 1, 1, 1.f, w_global, 1);

    // 8) head on CLS
    head_k<<<BQ, 256>>>(fin, head_ln_g, head_ln_b, head_w, head_b, out);
}

// round 14
// speedup vs baseline: 1.3134x; 1.0369x over previous
#include <cuda_runtime.h>
#include <math.h>

#define IMG 96
#define PSZ 8
#define GD 12
#define CDIM 768
#define NHEAD 8
#define HD 96
#define NPATCH 1728
#define NTOK 1729
#define BQ 2
#define NCLS 3

// ---------------- scratch (device globals) ----------------
__device__ float g_pat [(size_t)BQ * NPATCH * 512];
__device__ float g_tmp [(size_t)BQ * NPATCH * CDIM];
__device__ float g_x   [(size_t)BQ * NTOK * CDIM];
__device__ float g_wqkv[(size_t)3 * CDIM * CDIM];
__device__ float g_bqkv[3 * CDIM];
__device__ float g_qkv [(size_t)BQ * NTOK * 3 * CDIM];
__device__ float g_x2  [(size_t)BQ * NTOK * CDIM];
__device__ float g_wkv2[(size_t)4 * CDIM * CDIM];
__device__ float g_bkv2[4 * CDIM];
__device__ float g_wq2 [(size_t)2 * CDIM * CDIM];
__device__ float g_bq2 [2 * CDIM];
__device__ float g_kv  [(size_t)BQ * NTOK * 4 * CDIM];
__device__ float g_q0  [BQ * 2 * CDIM];
__device__ float g_oc  [2 * BQ * CDIM];
__device__ float g_fin [BQ * CDIM];

__device__ __forceinline__ float to_tf32(float x) {
    unsigned u;
    asm("cvt.rna.tf32.f32 %0, %1;" : "=r"(u) : "f"(x));
    return __uint_as_float(u);
}

__device__ __forceinline__ float4 ld4_guard(const float* __restrict__ p, int gk, int K) {
    if (gk + 3 < K) return *(const float4*)(p + gk);
    float4 v = make_float4(0.f, 0.f, 0.f, 0.f);
    if (gk     < K) v.x = p[gk];
    if (gk + 1 < K) v.y = p[gk + 1];
    if (gk + 2 < K) v.z = p[gk + 2];
    return v;
}

__device__ __forceinline__ void mma_tf32(float* c, const unsigned* a, const unsigned* b) {
    asm("mma.sync.aligned.m16n8k8.row.col.f32.tf32.tf32.f32 "
        "{%0,%1,%2,%3}, {%4,%5,%6,%7}, {%8,%9}, {%0,%1,%2,%3};"
        : "+f"(c[0]), "+f"(c[1]), "+f"(c[2]), "+f"(c[3])
        : "r"(a[0]), "r"(a[1]), "r"(a[2]), "r"(a[3]), "r"(b[0]), "r"(b[1]));
}

// ---- 128x128x16 double-buffered GEMM on tf32 mma.sync (proven, unchanged) ----
template <int TRANS_B>
__global__ void __launch_bounds__(256, 2)
gemm_k(const float* __restrict__ A, const float* __restrict__ Bm,
       const float* __restrict__ bias, float* __restrict__ Cm,
       int M, int Nn, int K, int lda, int ldb, int ldc,
       size_t sAb, size_t sAh, size_t sBb, size_t sBh,
       size_t sCb, size_t sCh, int nh,
       float alphaC, const float* __restrict__ alphaPtr, int accum)
{
    int z = blockIdx.z;
    int bb = z / nh, hh = z % nh;
    A  += (size_t)bb * sAb + (size_t)hh * sAh;
    Bm += (size_t)bb * sBb + (size_t)hh * sBh;
    Cm += (size_t)bb * sCb + (size_t)hh * sCh;

    __shared__ __align__(16) float As[2][16][136];
    __shared__ __align__(16) float Bs[2][16][136];

    int tid = threadIdx.x;
    int m0 = blockIdx.y * 128, n0 = blockIdx.x * 128;

    int ar = tid >> 2;
    int ak = (tid & 3) * 4;
    int bk = tid >> 5;
    int bc = (tid & 31) * 4;

    int wid = tid >> 5, lane = tid & 31;
    int wm = (wid & 1) * 64, wn = (wid >> 1) * 32;
    int grp = lane >> 2, qid = lane & 3;

    float acc[4][4][4];
#pragma unroll
    for (int i = 0; i < 4; i++)
#pragma unroll
        for (int j = 0; j < 4; j++)
#pragma unroll
            for (int r = 0; r < 4; r++) acc[i][j][r] = 0.f;

    float4 pa[2], pb[2];
    int ktiles = (K + 15) / 16;

    {
        int k0 = 0;
#pragma unroll
        for (int h = 0; h < 2; h++) {
            int gm = m0 + ar + h * 64;
            pa[h] = (gm < M) ? ld4_guard(A + (size_t)gm * lda, k0 + ak, K)
                             : make_float4(0.f, 0.f, 0.f, 0.f);
        }
        if (TRANS_B) {
#pragma unroll
            for (int h = 0; h < 2; h++) {
                int gn = n0 + ar + h * 64;
                pb[h] = (gn < Nn) ? ld4_guard(Bm + (size_t)gn * ldb, k0 + ak, K)
                                  : make_float4(0.f, 0.f, 0.f, 0.f);
            }
        } else {
#pragma unroll
            for (int h = 0; h < 2; h++) {
                int gk = k0 + bk + h * 8;
                int gn = n0 + bc;
                float4 v = make_float4(0.f, 0.f, 0.f, 0.f);
                if (gk < K) {
                    const float* rp = Bm + (size_t)gk * ldb;
                    if (gn + 3 < Nn) v = *(const float4*)(rp + gn);
                    else {
                        if (gn     < Nn) v.x = rp[gn];
                        if (gn + 1 < Nn) v.y = rp[gn + 1];
                        if (gn + 2 < Nn) v.z = rp[gn + 2];
                    }
                }
                pb[h] = v;
            }
        }
#pragma unroll
        for (int h = 0; h < 2; h++) {
            int r = ar + h * 64;
            As[0][ak + 0][r] = to_tf32(pa[h].x); As[0][ak + 1][r] = to_tf32(pa[h].y);
            As[0][ak + 2][r] = to_tf32(pa[h].z); As[0][ak + 3][r] = to_tf32(pa[h].w);
        }
        if (TRANS_B) {
#pragma unroll
            for (int h = 0; h < 2; h++) {
                int r = ar + h * 64;
                Bs[0][ak + 0][r] = to_tf32(pb[h].x); Bs[0][ak + 1][r] = to_tf32(pb[h].y);
                Bs[0][ak + 2][r] = to_tf32(pb[h].z); Bs[0][ak + 3][r] = to_tf32(pb[h].w);
            }
        } else {
#pragma unroll
            for (int h = 0; h < 2; h++) {
                float4 v = pb[h];
                v.x = to_tf32(v.x); v.y = to_tf32(v.y);
                v.z = to_tf32(v.z); v.w = to_tf32(v.w);
                *(float4*)&Bs[0][bk + h * 8][bc] = v;
            }
        }
    }
    __syncthreads();

    for (int t = 0; t < ktiles; t++) {
        int cur = t & 1;
        if (t + 1 < ktiles) {
            int k0 = (t + 1) * 16;
#pragma unroll
            for (int h = 0; h < 2; h++) {
                int gm = m0 + ar + h * 64;
                pa[h] = (gm < M) ? ld4_guard(A + (size_t)gm * lda, k0 + ak, K)
                                 : make_float4(0.f, 0.f, 0.f, 0.f);
            }
            if (TRANS_B) {
#pragma unroll
                for (int h = 0; h < 2; h++) {
                    int gn = n0 + ar + h * 64;
                    pb[h] = (gn < Nn) ? ld4_guard(Bm + (size_t)gn * ldb, k0 + ak, K)
                                      : make_float4(0.f, 0.f, 0.f, 0.f);
                }
            } else {
#pragma unroll
                for (int h = 0; h < 2; h++) {
                    int gk = k0 + bk + h * 8;
                    int gn = n0 + bc;
                    float4 v = make_float4(0.f, 0.f, 0.f, 0.f);
                    if (gk < K) {
                        const float* rp = Bm + (size_t)gk * ldb;
                        if (gn + 3 < Nn) v = *(const float4*)(rp + gn);
                        else {
                            if (gn     < Nn) v.x = rp[gn];
                            if (gn + 1 < Nn) v.y = rp[gn + 1];
                            if (gn + 2 < Nn) v.z = rp[gn + 2];
                        }
                    }
                    pb[h] = v;
                }
            }
        }

#pragma unroll
        for (int ks = 0; ks < 2; ks++) {
            int kb = ks * 8;
            unsigned a[4][4], b[4][2];
#pragma unroll
            for (int i = 0; i < 4; i++) {
                int rm = wm + i * 16 + grp;
                a[i][0] = __float_as_uint(As[cur][kb + qid][rm]);
                a[i][1] = __float_as_uint(As[cur][kb + qid][rm + 8]);
                a[i][2] = __float_as_uint(As[cur][kb + qid + 4][rm]);
                a[i][3] = __float_as_uint(As[cur][kb + qid + 4][rm + 8]);
            }
#pragma unroll
            for (int j = 0; j < 4; j++) {
                int cn = wn + j * 8 + grp;
                b[j][0] = __float_as_uint(Bs[cur][kb + qid][cn]);
                b[j][1] = __float_as_uint(Bs[cur][kb + qid + 4][cn]);
            }
#pragma unroll
            for (int i = 0; i < 4; i++)
#pragma unroll
                for (int j = 0; j < 4; j++)
                    mma_tf32(acc[i][j], a[i], b[j]);
        }

        if (t + 1 < ktiles) {
            int nxt = cur ^ 1;
#pragma unroll
            for (int h = 0; h < 2; h++) {
                int r = ar + h * 64;
                As[nxt][ak + 0][r] = to_tf32(pa[h].x); As[nxt][ak + 1][r] = to_tf32(pa[h].y);
                As[nxt][ak + 2][r] = to_tf32(pa[h].z); As[nxt][ak + 3][r] = to_tf32(pa[h].w);
            }
            if (TRANS_B) {
#pragma unroll
                for (int h = 0; h < 2; h++) {
                    int r = ar + h * 64;
                    Bs[nxt][ak + 0][r] = to_tf32(pb[h].x); Bs[nxt][ak + 1][r] = to_tf32(pb[h].y);
                    Bs[nxt][ak + 2][r] = to_tf32(pb[h].z); Bs[nxt][ak + 3][r] = to_tf32(pb[h].w);
                }
            } else {
#pragma unroll
                for (int h = 0; h < 2; h++) {
                    float4 v = pb[h];
                    v.x = to_tf32(v.x); v.y = to_tf32(v.y);
                    v.z = to_tf32(v.z); v.w = to_tf32(v.w);
                    *(float4*)&Bs[nxt][bk + h * 8][bc] = v;
                }
            }
            __syncthreads();
        }
    }

    float alpha = alphaC * (alphaPtr ? *alphaPtr : 1.f);
#pragma unroll
    for (int i = 0; i < 4; i++) {
#pragma unroll
        for (int j = 0; j < 4; j++) {
            int c0 = n0 + wn + j * 8 + qid * 2;
#pragma unroll
            for (int h = 0; h < 2; h++) {
                int r = m0 + wm + i * 16 + grp + h * 8;
                if (r >= M) continue;
                float v0 = acc[i][j][h * 2], v1 = acc[i][j][h * 2 + 1];
                if (bias) {
                    if (c0     < Nn) v0 += bias[c0];
                    if (c0 + 1 < Nn) v1 += bias[c0 + 1];
                }
                v0 *= alpha; v1 *= alpha;
                size_t off = (size_t)r * ldc + c0;
                if (c0 + 1 < Nn && ((ldc & 1) == 0)) {
                    if (accum) { v0 += Cm[off]; v1 += Cm[off + 1]; }
                    *(float2*)(Cm + off) = make_float2(v0, v1);
                } else {
                    if (c0 < Nn) {
                        if (accum) v0 += Cm[off];
                        Cm[off] = v0;
                    }
                    if (c0 + 1 < Nn) {
                        if (accum) v1 += Cm[off + 1];
                        Cm[off + 1] = v1;
                    }
                }
            }
        }
    }
}

// ====== FA2-style flash: warp-row ownership, register softmax stats ======
// FQ=64, 4 warps x 16 rows; Q frags in regs; K/V single-buffered smem;
// 2 block syncs/tile; softmax entirely in registers + quad shuffles.
#define FQ 64
#define FK 64
#define NKT 28
#define KSS 72                       // Ks [d][key] stride (72%32==8)
#define VSS 104                      // Vs [key][d] stride (104%32==8)
#define PSS2 24                      // P slab [c][row] stride (24*qid%32 distinct)
#define OFF_KS 0
#define OFF_VS (96 * KSS)            // 6912
#define OFF_PS (OFF_VS + 64 * VSS)   // 13568
#define FLASH_FLOATS (OFF_PS + 4 * 32 * PSS2)   // 16640 floats = 65.0KB

__device__ __forceinline__ unsigned ldsw(const float* base, int d, int col) {
    return __float_as_uint(base[d * KSS + (col ^ (((d >> 2) & 7) << 2))]);
}

__global__ void __launch_bounds__(128, 3)
flash_k(const float* __restrict__ qkv, float* __restrict__ x2)
{
    extern __shared__ float sm[];
    float* Ks = sm + OFF_KS;
    float* Vs = sm + OFF_VS;

    int tid = threadIdx.x;
    int wid = tid >> 5, lane = tid & 31;
    int grp = lane >> 2, qid = lane & 3;
    float* Pw = sm + OFF_PS + wid * 32 * PSS2;

    int qb = blockIdx.x;
    int bb = blockIdx.y >> 3, hh = blockIdx.y & 7;
    const float scale = 0.10206207261596577f;   // 1/sqrt(96)
    size_t base = (size_t)bb * NTOK * (3 * CDIM) + (size_t)hh * HD;
    int wrow = qb * FQ + wid * 16;

    // ---- Q fragments in registers (loaded once) ----
    unsigned qf[12][4];
    {
        int r0 = wrow + grp, r1 = wrow + grp + 8;
        const float* q0p = qkv + base + (size_t)(r0 < NTOK ? r0 : 0) * (3 * CDIM);
        const float* q1p = qkv + base + (size_t)(r1 < NTOK ? r1 : 0) * (3 * CDIM);
        bool v0 = r0 < NTOK, v1 = r1 < NTOK;
#pragma unroll
        for (int ks = 0; ks < 12; ks++) {
            int c0 = ks * 8 + qid, c1 = c0 + 4;
            qf[ks][0] = __float_as_uint(v0 ? to_tf32(q0p[c0]) : 0.f);
            qf[ks][1] = __float_as_uint(v1 ? to_tf32(q1p[c0]) : 0.f);
            qf[ks][2] = __float_as_uint(v0 ? to_tf32(q0p[c1]) : 0.f);
            qf[ks][3] = __float_as_uint(v1 ? to_tf32(q1p[c1]) : 0.f);
        }
    }

    float mrow[2] = {-1e30f, -1e30f};
    float lrow[2] = {0.f, 0.f};
    float oacc[12][4];
#pragma unroll
    for (int j = 0; j < 12; j++)
#pragma unroll
        for (int r = 0; r < 4; r++) oacc[j][r] = 0.f;

    for (int t = 0; t < NKT; t++) {
        int t0 = t * FK;
        __syncthreads();          // prior tile's K/V reads complete

        // ---- stage K (transposed+swizzled) and V (tf32) ----
#pragma unroll
        for (int it = 0; it < 12; it++) {
            int idx = tid + it * 128;            // 0..1535
            int r = idx / 24, d4 = (idx % 24) * 4;
            int gk = t0 + r;
            float4 kv4 = make_float4(0.f, 0.f, 0.f, 0.f);
            float4 vv4 = make_float4(0.f, 0.f, 0.f, 0.f);
            if (gk < NTOK) {
                const float* rp = qkv + base + (size_t)gk * (3 * CDIM);
                kv4 = *(const float4*)(rp + CDIM + d4);
                vv4 = *(const float4*)(rp + 2 * CDIM + d4);
            }
            float kvv[4] = {kv4.x, kv4.y, kv4.z, kv4.w};
#pragma unroll
            for (int u = 0; u < 4; u++) {
                int d = d4 + u;
                Ks[d * KSS + (r ^ (((d >> 2) & 7) << 2))] = to_tf32(kvv[u]);
            }
            vv4.x = to_tf32(vv4.x); vv4.y = to_tf32(vv4.y);
            vv4.z = to_tf32(vv4.z); vv4.w = to_tf32(vv4.w);
            *(float4*)&Vs[r * VSS + d4] = vv4;
        }
        __syncthreads();

        // ---- S = Q K^T (warp covers its 16 rows x all 64 keys) ----
        float sacc[8][4];
#pragma unroll
        for (int j = 0; j < 8; j++)
#pragma unroll
            for (int r = 0; r < 4; r++) sacc[j][r] = 0.f;
#pragma unroll
        for (int ks = 0; ks < 12; ks++) {
            int kb = ks * 8;
            unsigned b[8][2];
#pragma unroll
            for (int j = 0; j < 8; j++) {
                int cn = j * 8 + grp;
                b[j][0] = ldsw(Ks, kb + qid, cn);
                b[j][1] = ldsw(Ks, kb + qid + 4, cn);
            }
#pragma unroll
            for (int j = 0; j < 8; j++)
                mma_tf32(sacc[j], qf[ks], b[j]);
        }

        // ---- register softmax stats per row-half (quad shuffles only) ----
#pragma unroll
        for (int h = 0; h < 2; h++) {
            float vm = -1e30f;
#pragma unroll
            for (int j = 0; j < 8; j++)
#pragma unroll
                for (int u = 0; u < 2; u++) {
                    int c = t0 + j * 8 + qid * 2 + u;
                    if (c < NTOK) vm = fmaxf(vm, sacc[j][h * 2 + u] * scale);
                }
            vm = fmaxf(vm, __shfl_xor_sync(0xffffffffu, vm, 1));
            vm = fmaxf(vm, __shfl_xor_sync(0xffffffffu, vm, 2));
            float mn = fmaxf(mrow[h], vm);
            float al = __expf(mrow[h] - mn);
            mrow[h] = mn;
            float rs = 0.f;
#pragma unroll
            for (int j = 0; j < 8; j++)
#pragma unroll
                for (int u = 0; u < 2; u++) {
                    int c = t0 + j * 8 + qid * 2 + u;
                    float p = 0.f;
                    if (c < NTOK) p = __expf(sacc[j][h * 2 + u] * scale - mn);
                    sacc[j][h * 2 + u] = p;
                    rs += p;
                }
            rs += __shfl_xor_sync(0xffffffffu, rs, 1);
            rs += __shfl_xor_sync(0xffffffffu, rs, 2);
            lrow[h] = lrow[h] * al + rs;
#pragma unroll
            for (int j = 0; j < 12; j++) {
                oacc[j][h * 2]     *= al;
                oacc[j][h * 2 + 1] *= al;
            }
        }

        // ---- O += P @ V, two 32-key halves through per-warp P slab ----
#pragma unroll
        for (int hf = 0; hf < 2; hf++) {
            __syncwarp();
#pragma unroll
            for (int jj = 0; jj < 4; jj++)
#pragma unroll
                for (int u = 0; u < 2; u++) {
                    int cl = jj * 8 + qid * 2 + u;
                    Pw[cl * PSS2 + grp]     = to_tf32(sacc[hf * 4 + jj][u]);
                    Pw[cl * PSS2 + grp + 8] = to_tf32(sacc[hf * 4 + jj][2 + u]);
                }
            __syncwarp();
#pragma unroll
            for (int ks = 0; ks < 4; ks++) {
                int kb = ks * 8;
                unsigned a[4];
                a[0] = __float_as_uint(Pw[(kb + qid) * PSS2 + grp]);
                a[1] = __float_as_uint(Pw[(kb + qid) * PSS2 + grp + 8]);
                a[2] = __float_as_uint(Pw[(kb + qid + 4) * PSS2 + grp]);
                a[3] = __float_as_uint(Pw[(kb + qid + 4) * PSS2 + grp + 8]);
                int kv0 = hf * 32 + kb;
#pragma unroll
                for (int j = 0; j < 12; j++) {
                    int cn = j * 8 + grp;
                    unsigned b[2];
                    b[0] = __float_as_uint(Vs[(kv0 + qid) * VSS + cn]);
                    b[1] = __float_as_uint(Vs[(kv0 + qid + 4) * VSS + cn]);
                    mma_tf32(oacc[j], a, b);
                }
            }
        }
    }

    // ---- normalize + store ----
#pragma unroll
    for (int h = 0; h < 2; h++) {
        int gq = wrow + grp + h * 8;
        if (gq >= NTOK) continue;
        float invl = 1.f / lrow[h];
        float* op = x2 + (size_t)bb * NTOK * CDIM + (size_t)gq * CDIM + hh * HD;
#pragma unroll
        for (int j = 0; j < 12; j++) {
            int cn = j * 8 + qid * 2;
            *(float2*)(op + cn) = make_float2(oacc[j][h * 2] * invl,
                                              oacc[j][h * 2 + 1] * invl);
        }
    }
}

// ---------------- pack QKV weights/bias (proven) ----------------
__global__ void pack_qkv_k(const float* __restrict__ qw, const float* __restrict__ kw,
                           const float* __restrict__ vw, const float* __restrict__ qb,
                           const float* __restrict__ kb, const float* __restrict__ vb,
                           float* __restrict__ w, float* __restrict__ bias)
{
    int idx = blockIdx.x * 256 + threadIdx.x;
    int tot = 3 * CDIM * CDIM / 4;
    if (idx < tot) {
        int e = idx * 4;
        int which = e / (CDIM * CDIM);
        int off = e - which * (CDIM * CDIM);
        const float* src = which == 0 ? qw : which == 1 ? kw : vw;
        *(float4*)(w + e) = *(const float4*)(src + off);
    }
    if (idx < 3 * CDIM) {
        int which = idx / CDIM, off = idx % CDIM;
        bias[idx] = (which == 0 ? qb : which == 1 ? kb : vb)[off];
    }
}

// ---------------- pack branch weights (proven) ----------------
__global__ void pack_branch_k(const float* __restrict__ lw, const float* __restrict__ lb,
                              const float* __restrict__ gw, const float* __restrict__ gb,
                              float* __restrict__ wkv2, float* __restrict__ bkv2,
                              float* __restrict__ wq2, float* __restrict__ bq2)
{
    int idx = blockIdx.x * 256 + threadIdx.x;
    const int W1 = 4 * CDIM * CDIM / 4;
    const int W2 = 2 * CDIM * CDIM / 4;
    if (idx < W1) {
        int e = idx * 4;
        int row = e / CDIM, col = e % CDIM;
        const float* src = row < 2 * CDIM
            ? lw + (size_t)(CDIM + row) * CDIM
            : gw + (size_t)(CDIM + row - 2 * CDIM) * CDIM;
        *(float4*)(wkv2 + e) = *(const float4*)(src + col);
    } else if (idx < W1 + W2) {
        int e = (idx - W1) * 4;
        int row = e / CDIM, col = e % CDIM;
        const float* src = row < CDIM ? lw + (size_t)row * CDIM
                                      : gw + (size_t)(row - CDIM) * CDIM;
        *(float4*)(wq2 + e) = *(const float4*)(src + col);
    }
    if (idx < 4 * CDIM)
        bkv2[idx] = idx < 2 * CDIM ? lb[CDIM + idx] : gb[CDIM + idx - 2 * CDIM];
    if (idx < 2 * CDIM)
        bq2[idx] = idx < CDIM ? lb[idx] : gb[idx - CDIM];
}

// ---------------- im2col patch gather (proven) ----------------
__global__ void gather_k(const float* __restrict__ smri, float* __restrict__ pat) {
    int idx = blockIdx.x * 256 + threadIdx.x;
    if (idx >= BQ * NPATCH * 512 / 4) return;
    int e  = idx * 4;
    int kk = e & 511;
    int m  = e >> 9;
    int bb = m / NPATCH, p = m % NPATCH;
    int gx = p / (GD * GD), gy = (p / GD) % GD, gz = p % GD;
    int i = kk >> 6, j = (kk >> 3) & 7, kq = kk & 7;
    const float* src = smri + (((size_t)bb * IMG + gx * PSZ + i) * IMG + gy * PSZ + j) * IMG
                       + gz * PSZ + kq;
    *(float4*)(pat + e) = *(const float4*)src;
}

// ---------------- LN(patch embed) + cls + pos_embed ----------------
__global__ void ln_pos_k(const float* __restrict__ tmp, const float* __restrict__ g,
                         const float* __restrict__ b, const float* __restrict__ cls,
                         const float* __restrict__ pos, float* __restrict__ x)
{
    int bt = blockIdx.x;
    int bb = bt / NTOK, t = bt % NTOK;
    int tid = threadIdx.x;
    float* out = x + (size_t)bt * CDIM;
    const float* pp = pos + (size_t)t * CDIM;
    if (t == 0) {
        for (int c = tid; c < CDIM; c += 256) out[c] = cls[c] + pp[c];
        return;
    }
    const float* row = tmp + ((size_t)bb * NPATCH + (t - 1)) * CDIM;
    __shared__ float red[256];
    float s = 0.f, s2 = 0.f;
    for (int c = tid; c < CDIM; c += 256) { float v = row[c]; s += v; s2 += v * v; }
    red[tid] = s; __syncthreads();
    for (int st = 128; st > 0; st >>= 1) { if (tid < st) red[tid] += red[tid + st]; __syncthreads(); }
    float mean = red[0] / CDIM; __syncthreads();
    red[tid] = s2; __syncthreads();
    for (int st = 128; st > 0; st >>= 1) { if (tid < st) red[tid] += red[tid + st]; __syncthreads(); }
    float var = red[0] / CDIM - mean * mean;
    float inv = rsqrtf(var + 1e-5f);
    for (int c = tid; c < CDIM; c += 256)
        out[c] = (row[c] - mean) * inv * g[c] + b[c] + pp[c];
}

// ---------------- CLS-query attention: both branches, one launch ----------------
__global__ void cls_attn_k(const float* __restrict__ q0, const float* __restrict__ kv,
                           float* __restrict__ oc)
{
    int z = blockIdx.x;
    int br = z >> 4;
    int bb = (z >> 3) & 1;
    int hh = z & 7;
    __shared__ float sS[NTOK];
    __shared__ float sq[HD];
    __shared__ float red[128];
    int tid = threadIdx.x;
    for (int j = tid; j < HD; j += 128)
        sq[j] = q0[bb * 2 * CDIM + br * CDIM + hh * HD + j];
    __syncthreads();
    const float scale = 0.10206207261596577f;
    float mx = -1e30f;
    for (int t = tid; t < NTOK; t += 128) {
        const float* kr = kv + (size_t)(bb * NTOK + t) * (4 * CDIM) + br * 2 * CDIM + hh * HD;
        float s = 0.f;
        for (int j = 0; j < HD; j++) s += sq[j] * kr[j];
        s *= scale;
        sS[t] = s;
        mx = fmaxf(mx, s);
    }
    red[tid] = mx; __syncthreads();
    for (int st = 64; st > 0; st >>= 1) { if (tid < st) red[tid] = fmaxf(red[tid], red[tid + st]); __syncthreads(); }
    mx = red[0]; __syncthreads();
    float sm = 0.f;
    for (int t = tid; t < NTOK; t += 128) { float e = __expf(sS[t] - mx); sS[t] = e; sm += e; }
    red[tid] = sm; __syncthreads();
    for (int st = 64; st > 0; st >>= 1) { if (tid < st) red[tid] += red[tid + st]; __syncthreads(); }
    float inv = 1.f / red[0];
    __syncthreads();
    if (tid < HD) {
        float acc = 0.f;
        for (int t = 0; t < NTOK; t++)
            acc += sS[t] * kv[(size_t)(bb * NTOK + t) * (4 * CDIM) + br * 2 * CDIM + CDIM
                              + hh * HD + tid];
        oc[(br * BQ + bb) * CDIM + hh * HD + tid] = acc * inv;
    }
}

// ---------------- LN + head on CLS ----------------
__global__ void head_k(const float* __restrict__ fin, const float* __restrict__ g,
                       const float* __restrict__ b, const float* __restrict__ hw,
                       const float* __restrict__ hb, float* __restrict__ out)
{
    int bb = blockIdx.x;
    const float* row = fin + bb * CDIM;
    __shared__ float red[256];
    __shared__ float sn[CDIM];
    int tid = threadIdx.x;
    float s = 0.f, s2 = 0.f;
    for (int c = tid; c < CDIM; c += 256) { float v = row[c]; s += v; s2 += v * v; }
    red[tid] = s; __syncthreads();
    for (int st = 128; st > 0; st >>= 1) { if (tid < st) red[tid] += red[tid + st]; __syncthreads(); }
    float mean = red[0] / CDIM; __syncthreads();
    red[tid] = s2; __syncthreads();
    for (int st = 128; st > 0; st >>= 1) { if (tid < st) red[tid] += red[tid + st]; __syncthreads(); }
    float var = red[0] / CDIM - mean * mean;
    float inv = rsqrtf(var + 1e-5f);
    for (int c = tid; c < CDIM; c += 256) sn[c] = (row[c] - mean) * inv * g[c] + b[c];
    __syncthreads();
    if (tid < NCLS) {
        float acc = hb[tid];
        for (int c = 0; c < CDIM; c++) acc += sn[c] * hw[tid * CDIM + c];
        out[bb * NCLS + tid] = acc;
    }
}

// ---------------- host ----------------
static inline int cdiv(int a, int b) { return (a + b - 1) / b; }

static void gemm_nt(const float* A, const float* B, const float* bias, float* C,
                    int M, int Nn, int K, int lda, int ldb, int ldc,
                    size_t sAb = 0, size_t sAh = 0, size_t sBb = 0, size_t sBh = 0,
                    size_t sCb = 0, size_t sCh = 0, int nh = 1, int batches = 1,
                    float alphaC = 1.f, const float* alphaPtr = nullptr, int accum = 0)
{
    dim3 grid(cdiv(Nn, 128), cdiv(M, 128), batches);
    gemm_k<1><<<grid, 256>>>(A, B, bias, C, M, Nn, K, lda, ldb, ldc,
                             sAb, sAh, sBb, sBh, sCb, sCh, nh, alphaC, alphaPtr, accum);
}

extern "C" void kernel_launch(void* const* d_in, const int* in_sizes, int n_in,
                              void* d_out, int out_size)
{
    const float* smri     = (const float*)d_in[0];
    const float* conv_w   = (const float*)d_in[2];
    const float* conv_b   = (const float*)d_in[3];
    const float* pe_ln_g  = (const float*)d_in[4];
    const float* pe_ln_b  = (const float*)d_in[5];
    const float* q_w      = (const float*)d_in[6];
    const float* q_b      = (const float*)d_in[7];
    const float* k_w      = (const float*)d_in[8];
    const float* k_b      = (const float*)d_in[9];
    const float* v_w      = (const float*)d_in[10];
    const float* v_b      = (const float*)d_in[11];
    const float* loc_in_w = (const float*)d_in[13];
    const float* loc_in_b = (const float*)d_in[14];
    const float* loc_out_w= (const float*)d_in[15];
    const float* loc_out_b= (const float*)d_in[16];
    const float* glob_in_w = (const float*)d_in[17];
    const float* glob_in_b = (const float*)d_in[18];
    const float* glob_out_w= (const float*)d_in[19];
    const float* glob_out_b= (const float*)d_in[20];
    const float* w_local  = (const float*)d_in[21];
    const float* w_global = (const float*)d_in[22];
    const float* cls_tok  = (const float*)d_in[23];
    const float* pos_emb  = (const float*)d_in[24];
    const float* head_ln_g= (const float*)d_in[25];
    const float* head_ln_b= (const float*)d_in[26];
    const float* head_w   = (const float*)d_in[27];
    const float* head_b   = (const float*)d_in[28];
    float* out = (float*)d_out;

    float *pat, *tmp, *x, *wqkv, *bqkv, *qkv, *x2, *wkv2, *bkv2, *wq2, *bq2,
          *kv, *q0, *oc, *fin;
    cudaGetSymbolAddress((void**)&pat,  g_pat);
    cudaGetSymbolAddress((void**)&tmp,  g_tmp);
    cudaGetSymbolAddress((void**)&x,    g_x);
    cudaGetSymbolAddress((void**)&wqkv, g_wqkv);
    cudaGetSymbolAddress((void**)&bqkv, g_bqkv);
    cudaGetSymbolAddress((void**)&qkv,  g_qkv);
    cudaGetSymbolAddress((void**)&x2,   g_x2);
    cudaGetSymbolAddress((void**)&wkv2, g_wkv2);
    cudaGetSymbolAddress((void**)&bkv2, g_bkv2);
    cudaGetSymbolAddress((void**)&wq2,  g_wq2);
    cudaGetSymbolAddress((void**)&bq2,  g_bq2);
    cudaGetSymbolAddress((void**)&kv,   g_kv);
    cudaGetSymbolAddress((void**)&q0,   g_q0);
    cudaGetSymbolAddress((void**)&oc,   g_oc);
    cudaGetSymbolAddress((void**)&fin,  g_fin);

    const size_t sT = (size_t)NTOK * CDIM;

    static int flash_init = 0;
    if (!flash_init) {
        cudaFuncSetAttribute(flash_k, cudaFuncAttributeMaxDynamicSharedMemorySize,
                             FLASH_FLOATS * 4);
        flash_init = 1;
    }

    // 0) pack weights
    pack_qkv_k<<<cdiv(3 * CDIM * CDIM / 4, 256), 256>>>(q_w, k_w, v_w, q_b, k_b, v_b,
                                                        wqkv, bqkv);
    pack_branch_k<<<cdiv(6 * CDIM * CDIM / 4, 256), 256>>>(loc_in_w, loc_in_b,
                                                           glob_in_w, glob_in_b,
                                                           wkv2, bkv2, wq2, bq2);

    // 1) patch im2col + embed GEMM
    gather_k<<<cdiv(BQ * NPATCH * 512 / 4, 256), 256>>>(smri, pat);
    gemm_nt(pat, conv_w, conv_b, tmp, BQ * NPATCH, CDIM, 512, 512, 512, CDIM);

    // 2) LN + cls + pos
    ln_pos_k<<<BQ * NTOK, 256>>>(tmp, pe_ln_g, pe_ln_b, cls_tok, pos_emb, x);

    // 3) fused QKV projection
    gemm_nt(x, wqkv, bqkv, qkv, BQ * NTOK, 3 * CDIM, CDIM, CDIM, CDIM, 3 * CDIM);

    // 4-6) FA2-style flash attention (region bias softmax-invariant -> dropped)
    flash_k<<<dim3(cdiv(NTOK, FQ), BQ * NHEAD), 128, FLASH_FLOATS * 4>>>(qkv, x2);

    // 7) branch KV + q0 projections (packed), CLS attention, out-projections
    gemm_nt(x2, wkv2, bkv2, kv, BQ * NTOK, 4 * CDIM, CDIM, CDIM, CDIM, 4 * CDIM);
    gemm_nt(x2, wq2, bq2, q0, BQ, 2 * CDIM, CDIM, (int)sT, CDIM, 2 * CDIM);
    cls_attn_k<<<32, 128>>>(q0, kv, oc);
    gemm_nt(oc, loc_out_w, loc_out_b, fin, BQ, CDIM, CDIM, CDIM, CDIM, CDIM,
            0, 0, 0, 0, 0, 0, 1, 1, 1.f, w_local, 0);
    gemm_nt(oc + BQ * CDIM, glob_out_w, glob_out_b, fin, BQ, CDIM, CDIM, CDIM, CDIM, CDIM,
            0, 0, 0, 0, 0, 0, 1, 1, 1.f, w_global, 1);

    // 8) head on CLS
    head_k<<<BQ, 256>>>(fin, head_ln_g, head_ln_b, head_w, head_b, out);
}

// round 15
// speedup vs baseline: 1.4947x; 1.1381x over previous
#include <cuda_runtime.h>
#include <math.h>

#define IMG 96
#define PSZ 8
#define GD 12
#define CDIM 768
#define NHEAD 8
#define HD 96
#define NPATCH 1728
#define NTOK 1729
#define BQ 2
#define NCLS 3

// ---------------- scratch (device globals) ----------------
__device__ float g_pat  [(size_t)BQ * NPATCH * 512];
__device__ float g_tmp  [(size_t)BQ * NPATCH * CDIM];
__device__ float g_x    [(size_t)BQ * NTOK * CDIM];
__device__ float g_wconv[(size_t)CDIM * 512];
__device__ float g_wqkv [(size_t)3 * CDIM * CDIM];
__device__ float g_bqkv [3 * CDIM];
__device__ float g_qkv  [(size_t)BQ * NTOK * 3 * CDIM];
__device__ float g_x2   [(size_t)BQ * NTOK * CDIM];
__device__ float g_wkv2 [(size_t)4 * CDIM * CDIM];
__device__ float g_bkv2 [4 * CDIM];
__device__ float g_wq2  [(size_t)2 * CDIM * CDIM];
__device__ float g_bq2  [2 * CDIM];
__device__ float g_wout [(size_t)2 * CDIM * CDIM];   // [loc_out | glob_out]
__device__ float g_kv   [(size_t)BQ * NTOK * 4 * CDIM];
__device__ float g_q0   [BQ * 2 * CDIM];
__device__ float g_oc   [2 * BQ * CDIM];
__device__ float g_fin  [BQ * CDIM];

__device__ __forceinline__ float to_tf32(float x) {
    unsigned u;
    asm("cvt.rna.tf32.f32 %0, %1;" : "=r"(u) : "f"(x));
    return __uint_as_float(u);
}

__device__ __forceinline__ void mma_tf32(float* c, const unsigned* a, const unsigned* b) {
    asm("mma.sync.aligned.m16n8k8.row.col.f32.tf32.tf32.f32 "
        "{%0,%1,%2,%3}, {%4,%5,%6,%7}, {%8,%9}, {%0,%1,%2,%3};"
        : "+f"(c[0]), "+f"(c[1]), "+f"(c[2]), "+f"(c[3])
        : "r"(a[0]), "r"(a[1]), "r"(a[2]), "r"(a[3]), "r"(b[0]), "r"(b[1]));
}

__device__ __forceinline__ void cp_async16(float* dst, const float* src, int sbytes) {
    unsigned d = (unsigned)__cvta_generic_to_shared(dst);
    asm volatile("cp.async.cg.shared.global [%0], [%1], 16, %2;"
                 :: "r"(d), "l"(src), "r"(sbytes));
}

// ---- 128x128x16 NT GEMM, cp.async 3-stage pipeline, tf32 mma (inputs pre-tf32) ----
// C[m,n] = alpha*(sum_k A[m,k]*B[n,k] + bias[n]) (+ C if accum).  K % 16 == 0.
#define GS 3
#define GEMM_SMEM (GS * 128 * 20 * 2 * 4)     // 61440 bytes

__global__ void __launch_bounds__(256)
gemm_k(const float* __restrict__ A, const float* __restrict__ Bm,
       const float* __restrict__ bias, float* __restrict__ Cm,
       int M, int Nn, int K, int lda, int ldb, int ldc,
       float alphaC, const float* __restrict__ alphaPtr, int accum)
{
    extern __shared__ float sh[];
    float* As = sh;
    float* Bs = sh + GS * 128 * 20;

    int tid = threadIdx.x;
    int m0 = blockIdx.y * 128, n0 = blockIdx.x * 128;

    int wid = tid >> 5, lane = tid & 31;
    int wm = (wid & 1) * 64, wn = (wid >> 1) * 32;
    int grp = lane >> 2, qid = lane & 3;

    float acc[4][4][4];
#pragma unroll
    for (int i = 0; i < 4; i++)
#pragma unroll
        for (int j = 0; j < 4; j++)
#pragma unroll
            for (int r = 0; r < 4; r++) acc[i][j][r] = 0.f;

    int ktiles = K / 16;

#define ISSUE_TILE(T) do {                                                    \
        int k0_ = (T) * 16;                                                   \
        int s_  = (T) % GS;                                                   \
        _Pragma("unroll")                                                     \
        for (int h_ = 0; h_ < 2; h_++) {                                      \
            int id_ = tid * 2 + h_;                                           \
            int r_ = id_ >> 2, kc_ = (id_ & 3) * 4;                           \
            int gm_ = m0 + r_;                                                \
            const float* ga_ = A + (size_t)(gm_ < M ? gm_ : 0) * lda + k0_ + kc_; \
            cp_async16(&As[(s_ * 128 + r_) * 20 + kc_], ga_, gm_ < M ? 16 : 0);   \
            int gn_ = n0 + r_;                                                \
            const float* gb_ = Bm + (size_t)(gn_ < Nn ? gn_ : 0) * ldb + k0_ + kc_; \
            cp_async16(&Bs[(s_ * 128 + r_) * 20 + kc_], gb_, gn_ < Nn ? 16 : 0);  \
        }                                                                     \
        asm volatile("cp.async.commit_group;");                               \
    } while (0)

    // prologue: stages 0..GS-2
    ISSUE_TILE(0);
    ISSUE_TILE(1);

    for (int t = 0; t < ktiles; t++) {
        asm volatile("cp.async.wait_group 1;");
        __syncthreads();
        int s = t % GS;
        const float* Ab = &As[(size_t)s * 128 * 20];
        const float* Bb = &Bs[(size_t)s * 128 * 20];
#pragma unroll
        for (int ks = 0; ks < 2; ks++) {
            int kb = ks * 8;
            unsigned a[4][4], b[4][2];
#pragma unroll
            for (int i = 0; i < 4; i++) {
                int rm = wm + i * 16 + grp;
                a[i][0] = __float_as_uint(Ab[rm * 20 + kb + qid]);
                a[i][1] = __float_as_uint(Ab[(rm + 8) * 20 + kb + qid]);
                a[i][2] = __float_as_uint(Ab[rm * 20 + kb + qid + 4]);
                a[i][3] = __float_as_uint(Ab[(rm + 8) * 20 + kb + qid + 4]);
            }
#pragma unroll
            for (int j = 0; j < 4; j++) {
                int cn = wn + j * 8 + grp;
                b[j][0] = __float_as_uint(Bb[cn * 20 + kb + qid]);
                b[j][1] = __float_as_uint(Bb[cn * 20 + kb + qid + 4]);
            }
#pragma unroll
            for (int i = 0; i < 4; i++)
#pragma unroll
                for (int j = 0; j < 4; j++)
                    mma_tf32(acc[i][j], a[i], b[j]);
        }
        if (t + GS - 1 < ktiles) ISSUE_TILE(t + GS - 1);
        else asm volatile("cp.async.commit_group;");
    }
#undef ISSUE_TILE

    float alpha = alphaC * (alphaPtr ? *alphaPtr : 1.f);
#pragma unroll
    for (int i = 0; i < 4; i++) {
#pragma unroll
        for (int j = 0; j < 4; j++) {
            int c0 = n0 + wn + j * 8 + qid * 2;
#pragma unroll
            for (int h = 0; h < 2; h++) {
                int r = m0 + wm + i * 16 + grp + h * 8;
                if (r >= M) continue;
                float v0 = acc[i][j][h * 2], v1 = acc[i][j][h * 2 + 1];
                if (bias) {
                    if (c0     < Nn) v0 += bias[c0];
                    if (c0 + 1 < Nn) v1 += bias[c0 + 1];
                }
                v0 *= alpha; v1 *= alpha;
                size_t off = (size_t)r * ldc + c0;
                if (c0 + 1 < Nn) {
                    if (accum) { v0 += Cm[off]; v1 += Cm[off + 1]; }
                    *(float2*)(Cm + off) = make_float2(v0, v1);
                } else if (c0 < Nn) {
                    if (accum) v0 += Cm[off];
                    Cm[off] = v0;
                }
            }
        }
    }
}

// ====== FA2-style flash (proven R14); x2 stored tf32-rounded ======
#define FQ 64
#define FK 64
#define NKT 28
#define KSS 72
#define VSS 104
#define PSS2 24
#define OFF_KS 0
#define OFF_VS (96 * KSS)
#define OFF_PS (OFF_VS + 64 * VSS)
#define FLASH_FLOATS (OFF_PS + 4 * 32 * PSS2)

__device__ __forceinline__ unsigned ldsw(const float* base, int d, int col) {
    return __float_as_uint(base[d * KSS + (col ^ (((d >> 2) & 7) << 2))]);
}

__global__ void __launch_bounds__(128, 3)
flash_k(const float* __restrict__ qkv, float* __restrict__ x2)
{
    extern __shared__ float sm[];
    float* Ks = sm + OFF_KS;
    float* Vs = sm + OFF_VS;

    int tid = threadIdx.x;
    int wid = tid >> 5, lane = tid & 31;
    int grp = lane >> 2, qid = lane & 3;
    float* Pw = sm + OFF_PS + wid * 32 * PSS2;

    int qb = blockIdx.x;
    int bb = blockIdx.y >> 3, hh = blockIdx.y & 7;
    const float scale = 0.10206207261596577f;
    size_t base = (size_t)bb * NTOK * (3 * CDIM) + (size_t)hh * HD;
    int wrow = qb * FQ + wid * 16;

    unsigned qf[12][4];
    {
        int r0 = wrow + grp, r1 = wrow + grp + 8;
        const float* q0p = qkv + base + (size_t)(r0 < NTOK ? r0 : 0) * (3 * CDIM);
        const float* q1p = qkv + base + (size_t)(r1 < NTOK ? r1 : 0) * (3 * CDIM);
        bool v0 = r0 < NTOK, v1 = r1 < NTOK;
#pragma unroll
        for (int ks = 0; ks < 12; ks++) {
            int c0 = ks * 8 + qid, c1 = c0 + 4;
            qf[ks][0] = __float_as_uint(v0 ? to_tf32(q0p[c0]) : 0.f);
            qf[ks][1] = __float_as_uint(v1 ? to_tf32(q1p[c0]) : 0.f);
            qf[ks][2] = __float_as_uint(v0 ? to_tf32(q0p[c1]) : 0.f);
            qf[ks][3] = __float_as_uint(v1 ? to_tf32(q1p[c1]) : 0.f);
        }
    }

    float mrow[2] = {-1e30f, -1e30f};
    float lrow[2] = {0.f, 0.f};
    float oacc[12][4];
#pragma unroll
    for (int j = 0; j < 12; j++)
#pragma unroll
        for (int r = 0; r < 4; r++) oacc[j][r] = 0.f;

    for (int t = 0; t < NKT; t++) {
        int t0 = t * FK;
        __syncthreads();
#pragma unroll
        for (int it = 0; it < 12; it++) {
            int idx = tid + it * 128;
            int r = idx / 24, d4 = (idx % 24) * 4;
            int gk = t0 + r;
            float4 kv4 = make_float4(0.f, 0.f, 0.f, 0.f);
            float4 vv4 = make_float4(0.f, 0.f, 0.f, 0.f);
            if (gk < NTOK) {
                const float* rp = qkv + base + (size_t)gk * (3 * CDIM);
                kv4 = *(const float4*)(rp + CDIM + d4);
                vv4 = *(const float4*)(rp + 2 * CDIM + d4);
            }
            float kvv[4] = {kv4.x, kv4.y, kv4.z, kv4.w};
#pragma unroll
            for (int u = 0; u < 4; u++) {
                int d = d4 + u;
                Ks[d * KSS + (r ^ (((d >> 2) & 7) << 2))] = to_tf32(kvv[u]);
            }
            vv4.x = to_tf32(vv4.x); vv4.y = to_tf32(vv4.y);
            vv4.z = to_tf32(vv4.z); vv4.w = to_tf32(vv4.w);
            *(float4*)&Vs[r * VSS + d4] = vv4;
        }
        __syncthreads();

        float sacc[8][4];
#pragma unroll
        for (int j = 0; j < 8; j++)
#pragma unroll
            for (int r = 0; r < 4; r++) sacc[j][r] = 0.f;
#pragma unroll
        for (int ks = 0; ks < 12; ks++) {
            int kb = ks * 8;
            unsigned b[8][2];
#pragma unroll
            for (int j = 0; j < 8; j++) {
                int cn = j * 8 + grp;
                b[j][0] = ldsw(Ks, kb + qid, cn);
                b[j][1] = ldsw(Ks, kb + qid + 4, cn);
            }
#pragma unroll
            for (int j = 0; j < 8; j++)
                mma_tf32(sacc[j], qf[ks], b[j]);
        }

#pragma unroll
        for (int h = 0; h < 2; h++) {
            float vm = -1e30f;
#pragma unroll
            for (int j = 0; j < 8; j++)
#pragma unroll
                for (int u = 0; u < 2; u++) {
                    int c = t0 + j * 8 + qid * 2 + u;
                    if (c < NTOK) vm = fmaxf(vm, sacc[j][h * 2 + u] * scale);
                }
            vm = fmaxf(vm, __shfl_xor_sync(0xffffffffu, vm, 1));
            vm = fmaxf(vm, __shfl_xor_sync(0xffffffffu, vm, 2));
            float mn = fmaxf(mrow[h], vm);
            float al = __expf(mrow[h] - mn);
            mrow[h] = mn;
            float rs = 0.f;
#pragma unroll
            for (int j = 0; j < 8; j++)
#pragma unroll
                for (int u = 0; u < 2; u++) {
                    int c = t0 + j * 8 + qid * 2 + u;
                    float p = 0.f;
                    if (c < NTOK) p = __expf(sacc[j][h * 2 + u] * scale - mn);
                    sacc[j][h * 2 + u] = p;
                    rs += p;
                }
            rs += __shfl_xor_sync(0xffffffffu, rs, 1);
            rs += __shfl_xor_sync(0xffffffffu, rs, 2);
            lrow[h] = lrow[h] * al + rs;
#pragma unroll
            for (int j = 0; j < 12; j++) {
                oacc[j][h * 2]     *= al;
                oacc[j][h * 2 + 1] *= al;
            }
        }

#pragma unroll
        for (int hf = 0; hf < 2; hf++) {
            __syncwarp();
#pragma unroll
            for (int jj = 0; jj < 4; jj++)
#pragma unroll
                for (int u = 0; u < 2; u++) {
                    int cl = jj * 8 + qid * 2 + u;
                    Pw[cl * PSS2 + grp]     = to_tf32(sacc[hf * 4 + jj][u]);
                    Pw[cl * PSS2 + grp + 8] = to_tf32(sacc[hf * 4 + jj][2 + u]);
                }
            __syncwarp();
#pragma unroll
            for (int ks = 0; ks < 4; ks++) {
                int kb = ks * 8;
                unsigned a[4];
                a[0] = __float_as_uint(Pw[(kb + qid) * PSS2 + grp]);
                a[1] = __float_as_uint(Pw[(kb + qid) * PSS2 + grp + 8]);
                a[2] = __float_as_uint(Pw[(kb + qid + 4) * PSS2 + grp]);
                a[3] = __float_as_uint(Pw[(kb + qid + 4) * PSS2 + grp + 8]);
                int kv0 = hf * 32 + kb;
#pragma unroll
                for (int j = 0; j < 12; j++) {
                    int cn = j * 8 + grp;
                    unsigned b[2];
                    b[0] = __float_as_uint(Vs[(kv0 + qid) * VSS + cn]);
                    b[1] = __float_as_uint(Vs[(kv0 + qid + 4) * VSS + cn]);
                    mma_tf32(oacc[j], a, b);
                }
            }
        }
    }

#pragma unroll
    for (int h = 0; h < 2; h++) {
        int gq = wrow + grp + h * 8;
        if (gq >= NTOK) continue;
        float invl = 1.f / lrow[h];
        float* op = x2 + (size_t)bb * NTOK * CDIM + (size_t)gq * CDIM + hh * HD;
#pragma unroll
        for (int j = 0; j < 12; j++) {
            int cn = j * 8 + qid * 2;
            *(float2*)(op + cn) = make_float2(to_tf32(oacc[j][h * 2] * invl),
                                              to_tf32(oacc[j][h * 2 + 1] * invl));
        }
    }
}

// ---------------- pack QKV weights/bias (tf32 weights) ----------------
__global__ void pack_qkv_k(const float* __restrict__ qw, const float* __restrict__ kw,
                           const float* __restrict__ vw, const float* __restrict__ qb,
                           const float* __restrict__ kb, const float* __restrict__ vb,
                           float* __restrict__ w, float* __restrict__ bias)
{
    int idx = blockIdx.x * 256 + threadIdx.x;
    int tot = 3 * CDIM * CDIM / 4;
    if (idx < tot) {
        int e = idx * 4;
        int which = e / (CDIM * CDIM);
        int off = e - which * (CDIM * CDIM);
        const float* src = which == 0 ? qw : which == 1 ? kw : vw;
        float4 v = *(const float4*)(src + off);
        v.x = to_tf32(v.x); v.y = to_tf32(v.y); v.z = to_tf32(v.z); v.w = to_tf32(v.w);
        *(float4*)(w + e) = v;
    }
    if (idx < 3 * CDIM) {
        int which = idx / CDIM, off = idx % CDIM;
        bias[idx] = (which == 0 ? qb : which == 1 ? kb : vb)[off];
    }
}

// ---------------- pack branch weights (tf32) ----------------
__global__ void pack_branch_k(const float* __restrict__ lw, const float* __restrict__ lb,
                              const float* __restrict__ gw, const float* __restrict__ gb,
                              float* __restrict__ wkv2, float* __restrict__ bkv2,
                              float* __restrict__ wq2, float* __restrict__ bq2)
{
    int idx = blockIdx.x * 256 + threadIdx.x;
    const int W1 = 4 * CDIM * CDIM / 4;
    const int W2 = 2 * CDIM * CDIM / 4;
    if (idx < W1) {
        int e = idx * 4;
        int row = e / CDIM, col = e % CDIM;
        const float* src = row < 2 * CDIM
            ? lw + (size_t)(CDIM + row) * CDIM
            : gw + (size_t)(CDIM + row - 2 * CDIM) * CDIM;
        float4 v = *(const float4*)(src + col);
        v.x = to_tf32(v.x); v.y = to_tf32(v.y); v.z = to_tf32(v.z); v.w = to_tf32(v.w);
        *(float4*)(wkv2 + e) = v;
    } else if (idx < W1 + W2) {
        int e = (idx - W1) * 4;
        int row = e / CDIM, col = e % CDIM;
        const float* src = row < CDIM ? lw + (size_t)row * CDIM
                                      : gw + (size_t)(row - CDIM) * CDIM;
        float4 v = *(const float4*)(src + col);
        v.x = to_tf32(v.x); v.y = to_tf32(v.y); v.z = to_tf32(v.z); v.w = to_tf32(v.w);
        *(float4*)(wq2 + e) = v;
    }
    if (idx < 4 * CDIM)
        bkv2[idx] = idx < 2 * CDIM ? lb[CDIM + idx] : gb[CDIM + idx - 2 * CDIM];
    if (idx < 2 * CDIM)
        bq2[idx] = idx < CDIM ? lb[idx] : gb[idx - CDIM];
}

// ---------------- pack conv + out-proj weights (tf32) ----------------
__global__ void pack_misc_k(const float* __restrict__ convw,
                            const float* __restrict__ low, const float* __restrict__ gow,
                            float* __restrict__ wconv, float* __restrict__ wout)
{
    int idx = blockIdx.x * 256 + threadIdx.x;
    const int WC = CDIM * 512 / 4;
    const int WO = 2 * CDIM * CDIM / 4;
    if (idx < WC) {
        int e = idx * 4;
        float4 v = *(const float4*)(convw + e);
        v.x = to_tf32(v.x); v.y = to_tf32(v.y); v.z = to_tf32(v.z); v.w = to_tf32(v.w);
        *(float4*)(wconv + e) = v;
    } else if (idx < WC + WO) {
        int e = (idx - WC) * 4;
        const float* src = e < CDIM * CDIM ? low + e : gow + (e - CDIM * CDIM);
        float4 v = *(const float4*)src;
        v.x = to_tf32(v.x); v.y = to_tf32(v.y); v.z = to_tf32(v.z); v.w = to_tf32(v.w);
        *(float4*)(wout + e) = v;
    }
}

// ---------------- im2col patch gather (tf32 out) ----------------
__global__ void gather_k(const float* __restrict__ smri, float* __restrict__ pat) {
    int idx = blockIdx.x * 256 + threadIdx.x;
    if (idx >= BQ * NPATCH * 512 / 4) return;
    int e  = idx * 4;
    int kk = e & 511;
    int m  = e >> 9;
    int bb = m / NPATCH, p = m % NPATCH;
    int gx = p / (GD * GD), gy = (p / GD) % GD, gz = p % GD;
    int i = kk >> 6, j = (kk >> 3) & 7, kq = kk & 7;
    const float* src = smri + (((size_t)bb * IMG + gx * PSZ + i) * IMG + gy * PSZ + j) * IMG
                       + gz * PSZ + kq;
    float4 v = *(const float4*)src;
    v.x = to_tf32(v.x); v.y = to_tf32(v.y); v.z = to_tf32(v.z); v.w = to_tf32(v.w);
    *(float4*)(pat + e) = v;
}

// ---------------- LN(patch embed) + cls + pos_embed (tf32 out) ----------------
__global__ void ln_pos_k(const float* __restrict__ tmp, const float* __restrict__ g,
                         const float* __restrict__ b, const float* __restrict__ cls,
                         const float* __restrict__ pos, float* __restrict__ x)
{
    int bt = blockIdx.x;
    int bb = bt / NTOK, t = bt % NTOK;
    int tid = threadIdx.x;
    float* out = x + (size_t)bt * CDIM;
    const float* pp = pos + (size_t)t * CDIM;
    if (t == 0) {
        for (int c = tid; c < CDIM; c += 256) out[c] = to_tf32(cls[c] + pp[c]);
        return;
    }
    const float* row = tmp + ((size_t)bb * NPATCH + (t - 1)) * CDIM;
    __shared__ float red[256];
    float s = 0.f, s2 = 0.f;
    for (int c = tid; c < CDIM; c += 256) { float v = row[c]; s += v; s2 += v * v; }
    red[tid] = s; __syncthreads();
    for (int st = 128; st > 0; st >>= 1) { if (tid < st) red[tid] += red[tid + st]; __syncthreads(); }
    float mean = red[0] / CDIM; __syncthreads();
    red[tid] = s2; __syncthreads();
    for (int st = 128; st > 0; st >>= 1) { if (tid < st) red[tid] += red[tid + st]; __syncthreads(); }
    float var = red[0] / CDIM - mean * mean;
    float inv = rsqrtf(var + 1e-5f);
    for (int c = tid; c < CDIM; c += 256)
        out[c] = to_tf32((row[c] - mean) * inv * g[c] + b[c] + pp[c]);
}

// ---------------- CLS-query attention (tf32 oc out) ----------------
__global__ void cls_attn_k(const float* __restrict__ q0, const float* __restrict__ kv,
                           float* __restrict__ oc)
{
    int z = blockIdx.x;
    int br = z >> 4;
    int bb = (z >> 3) & 1;
    int hh = z & 7;
    __shared__ float sS[NTOK];
    __shared__ float sq[HD];
    __shared__ float red[128];
    int tid = threadIdx.x;
    for (int j = tid; j < HD; j += 128)
        sq[j] = q0[bb * 2 * CDIM + br * CDIM + hh * HD + j];
    __syncthreads();
    const float scale = 0.10206207261596577f;
    float mx = -1e30f;
    for (int t = tid; t < NTOK; t += 128) {
        const float* kr = kv + (size_t)(bb * NTOK + t) * (4 * CDIM) + br * 2 * CDIM + hh * HD;
        float s = 0.f;
        for (int j = 0; j < HD; j++) s += sq[j] * kr[j];
        s *= scale;
        sS[t] = s;
        mx = fmaxf(mx, s);
    }
    red[tid] = mx; __syncthreads();
    for (int st = 64; st > 0; st >>= 1) { if (tid < st) red[tid] = fmaxf(red[tid], red[tid + st]); __syncthreads(); }
    mx = red[0]; __syncthreads();
    float sm = 0.f;
    for (int t = tid; t < NTOK; t += 128) { float e = __expf(sS[t] - mx); sS[t] = e; sm += e; }
    red[tid] = sm; __syncthreads();
    for (int st = 64; st > 0; st >>= 1) { if (tid < st) red[tid] += red[tid + st]; __syncthreads(); }
    float inv = 1.f / red[0];
    __syncthreads();
    if (tid < HD) {
        float acc = 0.f;
        for (int t = 0; t < NTOK; t++)
            acc += sS[t] * kv[(size_t)(bb * NTOK + t) * (4 * CDIM) + br * 2 * CDIM + CDIM
                              + hh * HD + tid];
        oc[(br * BQ + bb) * CDIM + hh * HD + tid] = to_tf32(acc * inv);
    }
}

// ---------------- LN + head on CLS ----------------
__global__ void head_k(const float* __restrict__ fin, const float* __restrict__ g,
                       const float* __restrict__ b, const float* __restrict__ hw,
                       const float* __restrict__ hb, float* __restrict__ out)
{
    int bb = blockIdx.x;
    const float* row = fin + bb * CDIM;
    __shared__ float red[256];
    __shared__ float sn[CDIM];
    int tid = threadIdx.x;
    float s = 0.f, s2 = 0.f;
    for (int c = tid; c < CDIM; c += 256) { float v = row[c]; s += v; s2 += v * v; }
    red[tid] = s; __syncthreads();
    for (int st = 128; st > 0; st >>= 1) { if (tid < st) red[tid] += red[tid + st]; __syncthreads(); }
    float mean = red[0] / CDIM; __syncthreads();
    red[tid] = s2; __syncthreads();
    for (int st = 128; st > 0; st >>= 1) { if (tid < st) red[tid] += red[tid + st]; __syncthreads(); }
    float var = red[0] / CDIM - mean * mean;
    float inv = rsqrtf(var + 1e-5f);
    for (int c = tid; c < CDIM; c += 256) sn[c] = (row[c] - mean) * inv * g[c] + b[c];
    __syncthreads();
    if (tid < NCLS) {
        float acc = hb[tid];
        for (int c = 0; c < CDIM; c++) acc += sn[c] * hw[tid * CDIM + c];
        out[bb * NCLS + tid] = acc;
    }
}

// ---------------- host ----------------
static inline int cdiv(int a, int b) { return (a + b - 1) / b; }

static void gemm_nt(const float* A, const float* B, const float* bias, float* C,
                    int M, int Nn, int K, int lda, int ldb, int ldc,
                    float alphaC = 1.f, const float* alphaPtr = nullptr, int accum = 0)
{
    dim3 grid(cdiv(Nn, 128), cdiv(M, 128));
    gemm_k<<<grid, 256, GEMM_SMEM>>>(A, B, bias, C, M, Nn, K, lda, ldb, ldc,
                                     alphaC, alphaPtr, accum);
}

extern "C" void kernel_launch(void* const* d_in, const int* in_sizes, int n_in,
                              void* d_out, int out_size)
{
    const float* smri     = (const float*)d_in[0];
    const float* conv_w   = (const float*)d_in[2];
    const float* conv_b   = (const float*)d_in[3];
    const float* pe_ln_g  = (const float*)d_in[4];
    const float* pe_ln_b  = (const float*)d_in[5];
    const float* q_w      = (const float*)d_in[6];
    const float* q_b      = (const float*)d_in[7];
    const float* k_w      = (const float*)d_in[8];
    const float* k_b      = (const float*)d_in[9];
    const float* v_w      = (const float*)d_in[10];
    const float* v_b      = (const float*)d_in[11];
    const float* loc_in_w = (const float*)d_in[13];
    const float* loc_in_b = (const float*)d_in[14];
    const float* loc_out_w= (const float*)d_in[15];
    const float* loc_out_b= (const float*)d_in[16];
    const float* glob_in_w = (const float*)d_in[17];
    const float* glob_in_b = (const float*)d_in[18];
    const float* glob_out_w= (const float*)d_in[19];
    const float* glob_out_b= (const float*)d_in[20];
    const float* w_local  = (const float*)d_in[21];
    const float* w_global = (const float*)d_in[22];
    const float* cls_tok  = (const float*)d_in[23];
    const float* pos_emb  = (const float*)d_in[24];
    const float* head_ln_g= (const float*)d_in[25];
    const float* head_ln_b= (const float*)d_in[26];
    const float* head_w   = (const float*)d_in[27];
    const float* head_b   = (const float*)d_in[28];
    float* out = (float*)d_out;

    float *pat, *tmp, *x, *wconv, *wqkv, *bqkv, *qkv, *x2, *wkv2, *bkv2, *wq2, *bq2,
          *wout, *kv, *q0, *oc, *fin;
    cudaGetSymbolAddress((void**)&pat,   g_pat);
    cudaGetSymbolAddress((void**)&tmp,   g_tmp);
    cudaGetSymbolAddress((void**)&x,     g_x);
    cudaGetSymbolAddress((void**)&wconv, g_wconv);
    cudaGetSymbolAddress((void**)&wqkv,  g_wqkv);
    cudaGetSymbolAddress((void**)&bqkv,  g_bqkv);
    cudaGetSymbolAddress((void**)&qkv,   g_qkv);
    cudaGetSymbolAddress((void**)&x2,    g_x2);
    cudaGetSymbolAddress((void**)&wkv2,  g_wkv2);
    cudaGetSymbolAddress((void**)&bkv2,  g_bkv2);
    cudaGetSymbolAddress((void**)&wq2,   g_wq2);
    cudaGetSymbolAddress((void**)&bq2,   g_bq2);
    cudaGetSymbolAddress((void**)&wout,  g_wout);
    cudaGetSymbolAddress((void**)&kv,    g_kv);
    cudaGetSymbolAddress((void**)&q0,    g_q0);
    cudaGetSymbolAddress((void**)&oc,    g_oc);
    cudaGetSymbolAddress((void**)&fin,   g_fin);

    const size_t sT = (size_t)NTOK * CDIM;

    static int init_done = 0;
    if (!init_done) {
        cudaFuncSetAttribute(flash_k, cudaFuncAttributeMaxDynamicSharedMemorySize,
                             FLASH_FLOATS * 4);
        cudaFuncSetAttribute(gemm_k, cudaFuncAttributeMaxDynamicSharedMemorySize,
                             GEMM_SMEM);
        init_done = 1;
    }

    // 0) pack weights (all pre-rounded to tf32)
    pack_qkv_k<<<cdiv(3 * CDIM * CDIM / 4, 256), 256>>>(q_w, k_w, v_w, q_b, k_b, v_b,
                                                        wqkv, bqkv);
    pack_branch_k<<<cdiv(6 * CDIM * CDIM / 4, 256), 256>>>(loc_in_w, loc_in_b,
                                                           glob_in_w, glob_in_b,
                                                           wkv2, bkv2, wq2, bq2);
    pack_misc_k<<<cdiv((CDIM * 512 + 2 * CDIM * CDIM) / 4, 256), 256>>>(
        conv_w, loc_out_w, glob_out_w, wconv, wout);

    // 1) patch im2col (tf32) + embed GEMM
    gather_k<<<cdiv(BQ * NPATCH * 512 / 4, 256), 256>>>(smri, pat);
    gemm_nt(pat, wconv, conv_b, tmp, BQ * NPATCH, CDIM, 512, 512, 512, CDIM);

    // 2) LN + cls + pos (tf32 out)
    ln_pos_k<<<BQ * NTOK, 256>>>(tmp, pe_ln_g, pe_ln_b, cls_tok, pos_emb, x);

    // 3) fused QKV projection
    gemm_nt(x, wqkv, bqkv, qkv, BQ * NTOK, 3 * CDIM, CDIM, CDIM, CDIM, 3 * CDIM);

    // 4-6) FA2-style flash attention (region bias softmax-invariant -> dropped)
    flash_k<<<dim3(cdiv(NTOK, FQ), BQ * NHEAD), 128, FLASH_FLOATS * 4>>>(qkv, x2);

    // 7) branch KV + q0 projections, CLS attention, out-projections
    gemm_nt(x2, wkv2, bkv2, kv, BQ * NTOK, 4 * CDIM, CDIM, CDIM, CDIM, 4 * CDIM);
    gemm_nt(x2, wq2, bq2, q0, BQ, 2 * CDIM, CDIM, (int)sT, CDIM, 2 * CDIM);
    cls_attn_k<<<32, 128>>>(q0, kv, oc);
    gemm_nt(oc, wout, loc_out_b, fin, BQ, CDIM, CDIM, CDIM, CDIM, CDIM,
            1.f, w_local, 0);
    gemm_nt(oc + BQ * CDIM, wout + (size_t)CDIM * CDIM, glob_out_b, fin,
            BQ, CDIM, CDIM, CDIM, CDIM, CDIM, 1.f, w_global, 1);

    // 8) head on CLS
    head_k<<<BQ, 256>>>(fin, head_ln_g, head_ln_b, head_w, head_b, out);
}

// round 16
// speedup vs baseline: 1.5390x; 1.0296x over previous
#include <cuda_runtime.h>
#include <math.h>

#define IMG 96
#define PSZ 8
#define GD 12
#define CDIM 768
#define NHEAD 8
#define HD 96
#define NPATCH 1728
#define NTOK 1729
#define BQ 2
#define NCLS 3

// ---------------- scratch (device globals) ----------------
__device__ float g_pat  [(size_t)BQ * NPATCH * 512];
__device__ float g_tmp  [(size_t)BQ * NPATCH * CDIM];
__device__ float g_x    [(size_t)BQ * NTOK * CDIM];
__device__ float g_wconv[(size_t)CDIM * 512];
__device__ float g_wqkv [(size_t)3 * CDIM * CDIM];
__device__ float g_bqkv [3 * CDIM];
__device__ float g_qkv  [(size_t)BQ * NTOK * 3 * CDIM];
__device__ float g_x2   [(size_t)BQ * NTOK * CDIM];
__device__ float g_wkv2 [(size_t)4 * CDIM * CDIM];
__device__ float g_bkv2 [4 * CDIM];
__device__ float g_wq2  [(size_t)2 * CDIM * CDIM];
__device__ float g_bq2  [2 * CDIM];
__device__ float g_wout [(size_t)2 * CDIM * CDIM];
__device__ float g_kv   [(size_t)BQ * NTOK * 4 * CDIM];
__device__ float g_q0   [BQ * 2 * CDIM];
__device__ float g_oc   [2 * BQ * CDIM];
__device__ float g_fin  [BQ * CDIM];

__device__ __forceinline__ float to_tf32(float x) {
    unsigned u;
    asm("cvt.rna.tf32.f32 %0, %1;" : "=r"(u) : "f"(x));
    return __uint_as_float(u);
}

__device__ __forceinline__ void mma_tf32(float* c, const unsigned* a, const unsigned* b) {
    asm("mma.sync.aligned.m16n8k8.row.col.f32.tf32.tf32.f32 "
        "{%0,%1,%2,%3}, {%4,%5,%6,%7}, {%8,%9}, {%0,%1,%2,%3};"
        : "+f"(c[0]), "+f"(c[1]), "+f"(c[2]), "+f"(c[3])
        : "r"(a[0]), "r"(a[1]), "r"(a[2]), "r"(a[3]), "r"(b[0]), "r"(b[1]));
}

__device__ __forceinline__ void cp_async16(float* dst, const float* src, int sbytes) {
    unsigned d = (unsigned)__cvta_generic_to_shared(dst);
    asm volatile("cp.async.cg.shared.global [%0], [%1], 16, %2;"
                 :: "r"(d), "l"(src), "r"(sbytes));
}

// ---- 128x128x32 NT GEMM, cp.async 3-stage pipeline, tf32 mma (inputs pre-tf32) ----
// C[m,n] = alpha*(sum_k A[m,k]*B[n,k] + bias[n]) (+ C if accum).  K % 32 == 0.
#define GS 3
#define GSTR 36
#define GEMM_SMEM (GS * 128 * GSTR * 2 * 4)   // 110592 bytes

__global__ void __launch_bounds__(256)
gemm_k(const float* __restrict__ A, const float* __restrict__ Bm,
       const float* __restrict__ bias, float* __restrict__ Cm,
       int M, int Nn, int K, int lda, int ldb, int ldc,
       float alphaC, const float* __restrict__ alphaPtr, int accum, int out_tf32)
{
    extern __shared__ float sh[];
    float* As = sh;
    float* Bs = sh + GS * 128 * GSTR;

    int tid = threadIdx.x;
    int m0 = blockIdx.y * 128, n0 = blockIdx.x * 128;

    int wid = tid >> 5, lane = tid & 31;
    int wm = (wid & 1) * 64, wn = (wid >> 1) * 32;
    int grp = lane >> 2, qid = lane & 3;

    float acc[4][4][4];
#pragma unroll
    for (int i = 0; i < 4; i++)
#pragma unroll
        for (int j = 0; j < 4; j++)
#pragma unroll
            for (int r = 0; r < 4; r++) acc[i][j][r] = 0.f;

    int ktiles = K / 32;

#define ISSUE_TILE(T) do {                                                    \
        int k0_ = (T) * 32;                                                   \
        int s_  = (T) % GS;                                                   \
        _Pragma("unroll")                                                     \
        for (int h_ = 0; h_ < 4; h_++) {                                      \
            int id_ = tid * 4 + h_;                                           \
            int r_ = id_ >> 3, kc_ = (id_ & 7) * 4;                           \
            int gm_ = m0 + r_;                                                \
            const float* ga_ = A + (size_t)(gm_ < M ? gm_ : 0) * lda + k0_ + kc_; \
            cp_async16(&As[(s_ * 128 + r_) * GSTR + kc_], ga_, gm_ < M ? 16 : 0); \
            int gn_ = n0 + r_;                                                \
            const float* gb_ = Bm + (size_t)(gn_ < Nn ? gn_ : 0) * ldb + k0_ + kc_; \
            cp_async16(&Bs[(s_ * 128 + r_) * GSTR + kc_], gb_, gn_ < Nn ? 16 : 0); \
        }                                                                     \
        asm volatile("cp.async.commit_group;");                               \
    } while (0)

    ISSUE_TILE(0);
    if (ktiles > 1) ISSUE_TILE(1);
    else asm volatile("cp.async.commit_group;");

    for (int t = 0; t < ktiles; t++) {
        asm volatile("cp.async.wait_group 1;");
        __syncthreads();
        int s = t % GS;
        const float* Ab = &As[(size_t)s * 128 * GSTR];
        const float* Bb = &Bs[(size_t)s * 128 * GSTR];
#pragma unroll
        for (int ks = 0; ks < 4; ks++) {
            int kb = ks * 8;
            unsigned a[4][4], b[4][2];
#pragma unroll
            for (int i = 0; i < 4; i++) {
                int rm = wm + i * 16 + grp;
                a[i][0] = __float_as_uint(Ab[rm * GSTR + kb + qid]);
                a[i][1] = __float_as_uint(Ab[(rm + 8) * GSTR + kb + qid]);
                a[i][2] = __float_as_uint(Ab[rm * GSTR + kb + qid + 4]);
                a[i][3] = __float_as_uint(Ab[(rm + 8) * GSTR + kb + qid + 4]);
            }
#pragma unroll
            for (int j = 0; j < 4; j++) {
                int cn = wn + j * 8 + grp;
                b[j][0] = __float_as_uint(Bb[cn * GSTR + kb + qid]);
                b[j][1] = __float_as_uint(Bb[cn * GSTR + kb + qid + 4]);
            }
#pragma unroll
            for (int i = 0; i < 4; i++)
#pragma unroll
                for (int j = 0; j < 4; j++)
                    mma_tf32(acc[i][j], a[i], b[j]);
        }
        if (t + 2 < ktiles) ISSUE_TILE(t + 2);
        else asm volatile("cp.async.commit_group;");
    }
#undef ISSUE_TILE

    float alpha = alphaC * (alphaPtr ? *alphaPtr : 1.f);
#pragma unroll
    for (int i = 0; i < 4; i++) {
#pragma unroll
        for (int j = 0; j < 4; j++) {
            int c0 = n0 + wn + j * 8 + qid * 2;
#pragma unroll
            for (int h = 0; h < 2; h++) {
                int r = m0 + wm + i * 16 + grp + h * 8;
                if (r >= M) continue;
                float v0 = acc[i][j][h * 2], v1 = acc[i][j][h * 2 + 1];
                if (bias) {
                    if (c0     < Nn) v0 += bias[c0];
                    if (c0 + 1 < Nn) v1 += bias[c0 + 1];
                }
                v0 *= alpha; v1 *= alpha;
                size_t off = (size_t)r * ldc + c0;
                if (out_tf32) { v0 = to_tf32(v0); v1 = to_tf32(v1); }
                if (c0 + 1 < Nn) {
                    if (accum) { v0 += Cm[off]; v1 += Cm[off + 1]; }
                    *(float2*)(Cm + off) = make_float2(v0, v1);
                } else if (c0 < Nn) {
                    if (accum) v0 += Cm[off];
                    Cm[off] = v0;
                }
            }
        }
    }
}

// ====== FA2-style flash; qkv is pre-tf32; K/V staged row-major via cp.async ======
#define FQ 64
#define FK 64
#define NKT 28
#define KS2 108                      // K [key][d] stride (108%32==12 -> conflict-free)
#define VS2 104                      // V [key][d] stride (104%32==8  -> conflict-free)
#define PSS2 24
#define OFF_KS 0
#define OFF_VS (64 * KS2)            // 6912
#define OFF_PS (OFF_VS + 64 * VS2)   // 13568
#define FLASH_FLOATS (OFF_PS + 4 * 32 * PSS2)   // 16640 floats = 65KB

__global__ void __launch_bounds__(128, 3)
flash_k(const float* __restrict__ qkv, float* __restrict__ x2)
{
    extern __shared__ float sm[];
    float* Ks = sm + OFF_KS;
    float* Vs = sm + OFF_VS;

    int tid = threadIdx.x;
    int wid = tid >> 5, lane = tid & 31;
    int grp = lane >> 2, qid = lane & 3;
    float* Pw = sm + OFF_PS + wid * 32 * PSS2;

    int qb = blockIdx.x;
    int bb = blockIdx.y >> 3, hh = blockIdx.y & 7;
    const float scale = 0.10206207261596577f;
    size_t base = (size_t)bb * NTOK * (3 * CDIM) + (size_t)hh * HD;
    int wrow = qb * FQ + wid * 16;

    unsigned qf[12][4];
    {
        int r0 = wrow + grp, r1 = wrow + grp + 8;
        const float* q0p = qkv + base + (size_t)(r0 < NTOK ? r0 : 0) * (3 * CDIM);
        const float* q1p = qkv + base + (size_t)(r1 < NTOK ? r1 : 0) * (3 * CDIM);
        bool v0 = r0 < NTOK, v1 = r1 < NTOK;
#pragma unroll
        for (int ks = 0; ks < 12; ks++) {
            int c0 = ks * 8 + qid, c1 = c0 + 4;
            qf[ks][0] = __float_as_uint(v0 ? q0p[c0] : 0.f);
            qf[ks][1] = __float_as_uint(v1 ? q1p[c0] : 0.f);
            qf[ks][2] = __float_as_uint(v0 ? q0p[c1] : 0.f);
            qf[ks][3] = __float_as_uint(v1 ? q1p[c1] : 0.f);
        }
    }

    float mrow[2] = {-1e30f, -1e30f};
    float lrow[2] = {0.f, 0.f};
    float oacc[12][4];
#pragma unroll
    for (int j = 0; j < 12; j++)
#pragma unroll
        for (int r = 0; r < 4; r++) oacc[j][r] = 0.f;

    for (int t = 0; t < NKT; t++) {
        int t0 = t * FK;
        __syncthreads();              // prior tile's K/V reads complete

        // ---- cp.async stage K and V (row-major, already tf32) ----
#pragma unroll
        for (int it = 0; it < 12; it++) {
            int idx = tid + it * 128;            // 0..1535 quads
            int r = idx / 24, d4 = (idx % 24) * 4;
            int gk = t0 + r;
            const float* rp = qkv + base + (size_t)(gk < NTOK ? gk : 0) * (3 * CDIM);
            int sz = gk < NTOK ? 16 : 0;
            cp_async16(&Ks[r * KS2 + d4], rp + CDIM + d4, sz);
            cp_async16(&Vs[r * VS2 + d4], rp + 2 * CDIM + d4, sz);
        }
        asm volatile("cp.async.commit_group;");
        asm volatile("cp.async.wait_group 0;");
        __syncthreads();

        // ---- S = Q K^T ----
        float sacc[8][4];
#pragma unroll
        for (int j = 0; j < 8; j++)
#pragma unroll
            for (int r = 0; r < 4; r++) sacc[j][r] = 0.f;
#pragma unroll
        for (int ks = 0; ks < 12; ks++) {
            int kb = ks * 8;
            unsigned b[8][2];
#pragma unroll
            for (int j = 0; j < 8; j++) {
                int cn = j * 8 + grp;
                b[j][0] = __float_as_uint(Ks[cn * KS2 + kb + qid]);
                b[j][1] = __float_as_uint(Ks[cn * KS2 + kb + qid + 4]);
            }
#pragma unroll
            for (int j = 0; j < 8; j++)
                mma_tf32(sacc[j], qf[ks], b[j]);
        }

        // ---- register softmax stats ----
#pragma unroll
        for (int h = 0; h < 2; h++) {
            float vm = -1e30f;
#pragma unroll
            for (int j = 0; j < 8; j++)
#pragma unroll
                for (int u = 0; u < 2; u++) {
                    int c = t0 + j * 8 + qid * 2 + u;
                    if (c < NTOK) vm = fmaxf(vm, sacc[j][h * 2 + u] * scale);
                }
            vm = fmaxf(vm, __shfl_xor_sync(0xffffffffu, vm, 1));
            vm = fmaxf(vm, __shfl_xor_sync(0xffffffffu, vm, 2));
            float mn = fmaxf(mrow[h], vm);
            float al = __expf(mrow[h] - mn);
            mrow[h] = mn;
            float rs = 0.f;
#pragma unroll
            for (int j = 0; j < 8; j++)
#pragma unroll
                for (int u = 0; u < 2; u++) {
                    int c = t0 + j * 8 + qid * 2 + u;
                    float p = 0.f;
                    if (c < NTOK) p = __expf(sacc[j][h * 2 + u] * scale - mn);
                    sacc[j][h * 2 + u] = p;
                    rs += p;
                }
            rs += __shfl_xor_sync(0xffffffffu, rs, 1);
            rs += __shfl_xor_sync(0xffffffffu, rs, 2);
            lrow[h] = lrow[h] * al + rs;
#pragma unroll
            for (int j = 0; j < 12; j++) {
                oacc[j][h * 2]     *= al;
                oacc[j][h * 2 + 1] *= al;
            }
        }

        // ---- O += P @ V via per-warp P slab ----
#pragma unroll
        for (int hf = 0; hf < 2; hf++) {
            __syncwarp();
#pragma unroll
            for (int jj = 0; jj < 4; jj++)
#pragma unroll
                for (int u = 0; u < 2; u++) {
                    int cl = jj * 8 + qid * 2 + u;
                    Pw[cl * PSS2 + grp]     = to_tf32(sacc[hf * 4 + jj][u]);
                    Pw[cl * PSS2 + grp + 8] = to_tf32(sacc[hf * 4 + jj][2 + u]);
                }
            __syncwarp();
#pragma unroll
            for (int ks = 0; ks < 4; ks++) {
                int kb = ks * 8;
                unsigned a[4];
                a[0] = __float_as_uint(Pw[(kb + qid) * PSS2 + grp]);
                a[1] = __float_as_uint(Pw[(kb + qid) * PSS2 + grp + 8]);
                a[2] = __float_as_uint(Pw[(kb + qid + 4) * PSS2 + grp]);
                a[3] = __float_as_uint(Pw[(kb + qid + 4) * PSS2 + grp + 8]);
                int kv0 = hf * 32 + kb;
#pragma unroll
                for (int j = 0; j < 12; j++) {
                    int cn = j * 8 + grp;
                    unsigned b[2];
                    b[0] = __float_as_uint(Vs[(kv0 + qid) * VS2 + cn]);
                    b[1] = __float_as_uint(Vs[(kv0 + qid + 4) * VS2 + cn]);
                    mma_tf32(oacc[j], a, b);
                }
            }
        }
    }

#pragma unroll
    for (int h = 0; h < 2; h++) {
        int gq = wrow + grp + h * 8;
        if (gq >= NTOK) continue;
        float invl = 1.f / lrow[h];
        float* op = x2 + (size_t)bb * NTOK * CDIM + (size_t)gq * CDIM + hh * HD;
#pragma unroll
        for (int j = 0; j < 12; j++) {
            int cn = j * 8 + qid * 2;
            *(float2*)(op + cn) = make_float2(to_tf32(oacc[j][h * 2] * invl),
                                              to_tf32(oacc[j][h * 2 + 1] * invl));
        }
    }
}

// ---------------- pack QKV weights/bias (tf32 weights) ----------------
__global__ void pack_qkv_k(const float* __restrict__ qw, const float* __restrict__ kw,
                           const float* __restrict__ vw, const float* __restrict__ qb,
                           const float* __restrict__ kb, const float* __restrict__ vb,
                           float* __restrict__ w, float* __restrict__ bias)
{
    int idx = blockIdx.x * 256 + threadIdx.x;
    int tot = 3 * CDIM * CDIM / 4;
    if (idx < tot) {
        int e = idx * 4;
        int which = e / (CDIM * CDIM);
        int off = e - which * (CDIM * CDIM);
        const float* src = which == 0 ? qw : which == 1 ? kw : vw;
        float4 v = *(const float4*)(src + off);
        v.x = to_tf32(v.x); v.y = to_tf32(v.y); v.z = to_tf32(v.z); v.w = to_tf32(v.w);
        *(float4*)(w + e) = v;
    }
    if (idx < 3 * CDIM) {
        int which = idx / CDIM, off = idx % CDIM;
        bias[idx] = (which == 0 ? qb : which == 1 ? kb : vb)[off];
    }
}

// ---------------- pack branch weights (tf32) ----------------
__global__ void pack_branch_k(const float* __restrict__ lw, const float* __restrict__ lb,
                              const float* __restrict__ gw, const float* __restrict__ gb,
                              float* __restrict__ wkv2, float* __restrict__ bkv2,
                              float* __restrict__ wq2, float* __restrict__ bq2)
{
    int idx = blockIdx.x * 256 + threadIdx.x;
    const int W1 = 4 * CDIM * CDIM / 4;
    const int W2 = 2 * CDIM * CDIM / 4;
    if (idx < W1) {
        int e = idx * 4;
        int row = e / CDIM, col = e % CDIM;
        const float* src = row < 2 * CDIM
            ? lw + (size_t)(CDIM + row) * CDIM
            : gw + (size_t)(CDIM + row - 2 * CDIM) * CDIM;
        float4 v = *(const float4*)(src + col);
        v.x = to_tf32(v.x); v.y = to_tf32(v.y); v.z = to_tf32(v.z); v.w = to_tf32(v.w);
        *(float4*)(wkv2 + e) = v;
    } else if (idx < W1 + W2) {
        int e = (idx - W1) * 4;
        int row = e / CDIM, col = e % CDIM;
        const float* src = row < CDIM ? lw + (size_t)row * CDIM
                                      : gw + (size_t)(row - CDIM) * CDIM;
        float4 v = *(const float4*)(src + col);
        v.x = to_tf32(v.x); v.y = to_tf32(v.y); v.z = to_tf32(v.z); v.w = to_tf32(v.w);
        *(float4*)(wq2 + e) = v;
    }
    if (idx < 4 * CDIM)
        bkv2[idx] = idx < 2 * CDIM ? lb[CDIM + idx] : gb[CDIM + idx - 2 * CDIM];
    if (idx < 2 * CDIM)
        bq2[idx] = idx < CDIM ? lb[idx] : gb[idx - CDIM];
}

// ---------------- pack conv + out-proj weights (tf32) ----------------
__global__ void pack_misc_k(const float* __restrict__ convw,
                            const float* __restrict__ low, const float* __restrict__ gow,
                            float* __restrict__ wconv, float* __restrict__ wout)
{
    int idx = blockIdx.x * 256 + threadIdx.x;
    const int WC = CDIM * 512 / 4;
    const int WO = 2 * CDIM * CDIM / 4;
    if (idx < WC) {
        int e = idx * 4;
        float4 v = *(const float4*)(convw + e);
        v.x = to_tf32(v.x); v.y = to_tf32(v.y); v.z = to_tf32(v.z); v.w = to_tf32(v.w);
        *(float4*)(wconv + e) = v;
    } else if (idx < WC + WO) {
        int e = (idx - WC) * 4;
        const float* src = e < CDIM * CDIM ? low + e : gow + (e - CDIM * CDIM);
        float4 v = *(const float4*)src;
        v.x = to_tf32(v.x); v.y = to_tf32(v.y); v.z = to_tf32(v.z); v.w = to_tf32(v.w);
        *(float4*)(wout + e) = v;
    }
}

// ---------------- im2col patch gather (tf32 out) ----------------
__global__ void gather_k(const float* __restrict__ smri, float* __restrict__ pat) {
    int idx = blockIdx.x * 256 + threadIdx.x;
    if (idx >= BQ * NPATCH * 512 / 4) return;
    int e  = idx * 4;
    int kk = e & 511;
    int m  = e >> 9;
    int bb = m / NPATCH, p = m % NPATCH;
    int gx = p / (GD * GD), gy = (p / GD) % GD, gz = p % GD;
    int i = kk >> 6, j = (kk >> 3) & 7, kq = kk & 7;
    const float* src = smri + (((size_t)bb * IMG + gx * PSZ + i) * IMG + gy * PSZ + j) * IMG
                       + gz * PSZ + kq;
    float4 v = *(const float4*)src;
    v.x = to_tf32(v.x); v.y = to_tf32(v.y); v.z = to_tf32(v.z); v.w = to_tf32(v.w);
    *(float4*)(pat + e) = v;
}

// ---------------- LN(patch embed) + cls + pos_embed (tf32 out) ----------------
__global__ void ln_pos_k(const float* __restrict__ tmp, const float* __restrict__ g,
                         const float* __restrict__ b, const float* __restrict__ cls,
                         const float* __restrict__ pos, float* __restrict__ x)
{
    int bt = blockIdx.x;
    int bb = bt / NTOK, t = bt % NTOK;
    int tid = threadIdx.x;
    float* out = x + (size_t)bt * CDIM;
    const float* pp = pos + (size_t)t * CDIM;
    if (t == 0) {
        for (int c = tid; c < CDIM; c += 256) out[c] = to_tf32(cls[c] + pp[c]);
        return;
    }
    const float* row = tmp + ((size_t)bb * NPATCH + (t - 1)) * CDIM;
    __shared__ float red[256];
    float s = 0.f, s2 = 0.f;
    for (int c = tid; c < CDIM; c += 256) { float v = row[c]; s += v; s2 += v * v; }
    red[tid] = s; __syncthreads();
    for (int st = 128; st > 0; st >>= 1) { if (tid < st) red[tid] += red[tid + st]; __syncthreads(); }
    float mean = red[0] / CDIM; __syncthreads();
    red[tid] = s2; __syncthreads();
    for (int st = 128; st > 0; st >>= 1) { if (tid < st) red[tid] += red[tid + st]; __syncthreads(); }
    float var = red[0] / CDIM - mean * mean;
    float inv = rsqrtf(var + 1e-5f);
    for (int c = tid; c < CDIM; c += 256)
        out[c] = to_tf32((row[c] - mean) * inv * g[c] + b[c] + pp[c]);
}

// ---------------- CLS-query attention (tf32 oc out) ----------------
__global__ void cls_attn_k(const float* __restrict__ q0, const float* __restrict__ kv,
                           float* __restrict__ oc)
{
    int z = blockIdx.x;
    int br = z >> 4;
    int bb = (z >> 3) & 1;
    int hh = z & 7;
    __shared__ float sS[NTOK];
    __shared__ float sq[HD];
    __shared__ float red[128];
    int tid = threadIdx.x;
    for (int j = tid; j < HD; j += 128)
        sq[j] = q0[bb * 2 * CDIM + br * CDIM + hh * HD + j];
    __syncthreads();
    const float scale = 0.10206207261596577f;
    float mx = -1e30f;
    for (int t = tid; t < NTOK; t += 128) {
        const float* kr = kv + (size_t)(bb * NTOK + t) * (4 * CDIM) + br * 2 * CDIM + hh * HD;
        float s = 0.f;
        for (int j = 0; j < HD; j++) s += sq[j] * kr[j];
        s *= scale;
        sS[t] = s;
        mx = fmaxf(mx, s);
    }
    red[tid] = mx; __syncthreads();
    for (int st = 64; st > 0; st >>= 1) { if (tid < st) red[tid] = fmaxf(red[tid], red[tid + st]); __syncthreads(); }
    mx = red[0]; __syncthreads();
    float sm = 0.f;
    for (int t = tid; t < NTOK; t += 128) { float e = __expf(sS[t] - mx); sS[t] = e; sm += e; }
    red[tid] = sm; __syncthreads();
    for (int st = 64; st > 0; st >>= 1) { if (tid < st) red[tid] += red[tid + st]; __syncthreads(); }
    float inv = 1.f / red[0];
    __syncthreads();
    if (tid < HD) {
        float acc = 0.f;
        for (int t = 0; t < NTOK; t++)
            acc += sS[t] * kv[(size_t)(bb * NTOK + t) * (4 * CDIM) + br * 2 * CDIM + CDIM
                              + hh * HD + tid];
        oc[(br * BQ + bb) * CDIM + hh * HD + tid] = to_tf32(acc * inv);
    }
}

// ---------------- LN + head on CLS ----------------
__global__ void head_k(const float* __restrict__ fin, const float* __restrict__ g,
                       const float* __restrict__ b, const float* __restrict__ hw,
                       const float* __restrict__ hb, float* __restrict__ out)
{
    int bb = blockIdx.x;
    const float* row = fin + bb * CDIM;
    __shared__ float red[256];
    __shared__ float sn[CDIM];
    int tid = threadIdx.x;
    float s = 0.f, s2 = 0.f;
    for (int c = tid; c < CDIM; c += 256) { float v = row[c]; s += v; s2 += v * v; }
    red[tid] = s; __syncthreads();
    for (int st = 128; st > 0; st >>= 1) { if (tid < st) red[tid] += red[tid + st]; __syncthreads(); }
    float mean = red[0] / CDIM; __syncthreads();
    red[tid] = s2; __syncthreads();
    for (int st = 128; st > 0; st >>= 1) { if (tid < st) red[tid] += red[tid + st]; __syncthreads(); }
    float var = red[0] / CDIM - mean * mean;
    float inv = rsqrtf(var + 1e-5f);
    for (int c = tid; c < CDIM; c += 256) sn[c] = (row[c] - mean) * inv * g[c] + b[c];
    __syncthreads();
    if (tid < NCLS) {
        float acc = hb[tid];
        for (int c = 0; c < CDIM; c++) acc += sn[c] * hw[tid * CDIM + c];
        out[bb * NCLS + tid] = acc;
    }
}

// ---------------- host ----------------
static inline int cdiv(int a, int b) { return (a + b - 1) / b; }

static void gemm_nt(const float* A, const float* B, const float* bias, float* C,
                    int M, int Nn, int K, int lda, int ldb, int ldc,
                    float alphaC = 1.f, const float* alphaPtr = nullptr, int accum = 0,
                    int out_tf32 = 0)
{
    dim3 grid(cdiv(Nn, 128), cdiv(M, 128));
    gemm_k<<<grid, 256, GEMM_SMEM>>>(A, B, bias, C, M, Nn, K, lda, ldb, ldc,
                                     alphaC, alphaPtr, accum, out_tf32);
}

extern "C" void kernel_launch(void* const* d_in, const int* in_sizes, int n_in,
                              void* d_out, int out_size)
{
    const float* smri     = (const float*)d_in[0];
    const float* conv_w   = (const float*)d_in[2];
    const float* conv_b   = (const float*)d_in[3];
    const float* pe_ln_g  = (const float*)d_in[4];
    const float* pe_ln_b  = (const float*)d_in[5];
    const float* q_w      = (const float*)d_in[6];
    const float* q_b      = (const float*)d_in[7];
    const float* k_w      = (const float*)d_in[8];
    const float* k_b      = (const float*)d_in[9];
    const float* v_w      = (const float*)d_in[10];
    const float* v_b      = (const float*)d_in[11];
    const float* loc_in_w = (const float*)d_in[13];
    const float* loc_in_b = (const float*)d_in[14];
    const float* loc_out_w= (const float*)d_in[15];
    const float* loc_out_b= (const float*)d_in[16];
    const float* glob_in_w = (const float*)d_in[17];
    const float* glob_in_b = (const float*)d_in[18];
    const float* glob_out_w= (const float*)d_in[19];
    const float* glob_out_b= (const float*)d_in[20];
    const float* w_local  = (const float*)d_in[21];
    const float* w_global = (const float*)d_in[22];
    const float* cls_tok  = (const float*)d_in[23];
    const float* pos_emb  = (const float*)d_in[24];
    const float* head_ln_g= (const float*)d_in[25];
    const float* head_ln_b= (const float*)d_in[26];
    const float* head_w   = (const float*)d_in[27];
    const float* head_b   = (const float*)d_in[28];
    float* out = (float*)d_out;

    float *pat, *tmp, *x, *wconv, *wqkv, *bqkv, *qkv, *x2, *wkv2, *bkv2, *wq2, *bq2,
          *wout, *kv, *q0, *oc, *fin;
    cudaGetSymbolAddress((void**)&pat,   g_pat);
    cudaGetSymbolAddress((void**)&tmp,   g_tmp);
    cudaGetSymbolAddress((void**)&x,     g_x);
    cudaGetSymbolAddress((void**)&wconv, g_wconv);
    cudaGetSymbolAddress((void**)&wqkv,  g_wqkv);
    cudaGetSymbolAddress((void**)&bqkv,  g_bqkv);
    cudaGetSymbolAddress((void**)&qkv,   g_qkv);
    cudaGetSymbolAddress((void**)&x2,    g_x2);
    cudaGetSymbolAddress((void**)&wkv2,  g_wkv2);
    cudaGetSymbolAddress((void**)&bkv2,  g_bkv2);
    cudaGetSymbolAddress((void**)&wq2,   g_wq2);
    cudaGetSymbolAddress((void**)&bq2,   g_bq2);
    cudaGetSymbolAddress((void**)&wout,  g_wout);
    cudaGetSymbolAddress((void**)&kv,    g_kv);
    cudaGetSymbolAddress((void**)&q0,    g_q0);
    cudaGetSymbolAddress((void**)&oc,    g_oc);
    cudaGetSymbolAddress((void**)&fin,   g_fin);

    const size_t sT = (size_t)NTOK * CDIM;

    static int init_done = 0;
    if (!init_done) {
        cudaFuncSetAttribute(flash_k, cudaFuncAttributeMaxDynamicSharedMemorySize,
                             FLASH_FLOATS * 4);
        cudaFuncSetAttribute(gemm_k, cudaFuncAttributeMaxDynamicSharedMemorySize,
                             GEMM_SMEM);
        init_done = 1;
    }

    // 0) pack weights (all pre-rounded to tf32)
    pack_qkv_k<<<cdiv(3 * CDIM * CDIM / 4, 256), 256>>>(q_w, k_w, v_w, q_b, k_b, v_b,
                                                        wqkv, bqkv);
    pack_branch_k<<<cdiv(6 * CDIM * CDIM / 4, 256), 256>>>(loc_in_w, loc_in_b,
                                                           glob_in_w, glob_in_b,
                                                           wkv2, bkv2, wq2, bq2);
    pack_misc_k<<<cdiv((CDIM * 512 + 2 * CDIM * CDIM) / 4, 256), 256>>>(
        conv_w, loc_out_w, glob_out_w, wconv, wout);

    // 1) patch im2col (tf32) + embed GEMM
    gather_k<<<cdiv(BQ * NPATCH * 512 / 4, 256), 256>>>(smri, pat);
    gemm_nt(pat, wconv, conv_b, tmp, BQ * NPATCH, CDIM, 512, 512, 512, CDIM);

    // 2) LN + cls + pos (tf32 out)
    ln_pos_k<<<BQ * NTOK, 256>>>(tmp, pe_ln_g, pe_ln_b, cls_tok, pos_emb, x);

    // 3) fused QKV projection — output pre-rounded to tf32 (flash consumes raw bits)
    gemm_nt(x, wqkv, bqkv, qkv, BQ * NTOK, 3 * CDIM, CDIM, CDIM, CDIM, 3 * CDIM,
            1.f, nullptr, 0, /*out_tf32=*/1);

    // 4-6) FA2-style flash attention (region bias softmax-invariant -> dropped)
    flash_k<<<dim3(cdiv(NTOK, FQ), BQ * NHEAD), 128, FLASH_FLOATS * 4>>>(qkv, x2);

    // 7) branch KV + q0 projections, CLS attention, out-projections
    gemm_nt(x2, wkv2, bkv2, kv, BQ * NTOK, 4 * CDIM, CDIM, CDIM, CDIM, 4 * CDIM);
    gemm_nt(x2, wq2, bq2, q0, BQ, 2 * CDIM, CDIM, (int)sT, CDIM, 2 * CDIM);
    cls_attn_k<<<32, 128>>>(q0, kv, oc);
    gemm_nt(oc, wout, loc_out_b, fin, BQ, CDIM, CDIM, CDIM, CDIM, CDIM,
            1.f, w_local, 0);
    gemm_nt(oc + BQ * CDIM, wout + (size_t)CDIM * CDIM, glob_out_b, fin,
            BQ, CDIM, CDIM, CDIM, CDIM, CDIM, 1.f, w_global, 1);

    // 8) head on CLS
    head_k<<<BQ, 256>>>(fin, head_ln_g, head_ln_b, head_w, head_b, out);
}

// round 17
// speedup vs baseline: 1.9525x; 1.2687x over previous
#include <cuda_runtime.h>
#include <math.h>

#define IMG 96
#define PSZ 8
#define GD 12
#define CDIM 768
#define NHEAD 8
#define HD 96
#define NPATCH 1728
#define NTOK 1729
#define BQ 2
#define NCLS 3
#define NCH 32
#define CHSZ 55        // ceil(1729/32)

// ---------------- scratch (device globals) ----------------
__device__ float g_pat  [(size_t)BQ * NPATCH * 512];
__device__ float g_tmp  [(size_t)BQ * NPATCH * CDIM];
__device__ float g_x    [(size_t)BQ * NTOK * CDIM];
__device__ float g_wconv[(size_t)CDIM * 512];
__device__ float g_wqkv [(size_t)3 * CDIM * CDIM];
__device__ float g_bqkv [3 * CDIM];
__device__ float g_qkv  [(size_t)BQ * NTOK * 3 * CDIM];
__device__ float g_x2   [(size_t)BQ * NTOK * CDIM];
__device__ float g_wq2  [(size_t)2 * CDIM * CDIM];
__device__ float g_bq2  [2 * CDIM];
__device__ float g_wout [(size_t)2 * CDIM * CDIM];
__device__ float g_q0   [BQ * 2 * CDIM];
__device__ float g_U    [32 * CDIM];
__device__ float g_cb   [32];
__device__ float g_S2   [(size_t)32 * NTOK];
__device__ float g_ypart[(size_t)32 * NCH * CDIM];
__device__ float g_oc   [2 * BQ * CDIM];
__device__ float g_fin  [BQ * CDIM];

__device__ __forceinline__ float to_tf32(float x) {
    unsigned u;
    asm("cvt.rna.tf32.f32 %0, %1;" : "=r"(u) : "f"(x));
    return __uint_as_float(u);
}

__device__ __forceinline__ void mma_tf32(float* c, const unsigned* a, const unsigned* b) {
    asm("mma.sync.aligned.m16n8k8.row.col.f32.tf32.tf32.f32 "
        "{%0,%1,%2,%3}, {%4,%5,%6,%7}, {%8,%9}, {%0,%1,%2,%3};"
        : "+f"(c[0]), "+f"(c[1]), "+f"(c[2]), "+f"(c[3])
        : "r"(a[0]), "r"(a[1]), "r"(a[2]), "r"(a[3]), "r"(b[0]), "r"(b[1]));
}

__device__ __forceinline__ void cp_async16(float* dst, const float* src, int sbytes) {
    unsigned d = (unsigned)__cvta_generic_to_shared(dst);
    asm volatile("cp.async.cg.shared.global [%0], [%1], 16, %2;"
                 :: "r"(d), "l"(src), "r"(sbytes));
}

// ---- 128x128x32 NT GEMM, cp.async 3-stage pipeline (proven R16, unchanged) ----
#define GS 3
#define GSTR 36
#define GEMM_SMEM (GS * 128 * GSTR * 2 * 4)

__global__ void __launch_bounds__(256)
gemm_k(const float* __restrict__ A, const float* __restrict__ Bm,
       const float* __restrict__ bias, float* __restrict__ Cm,
       int M, int Nn, int K, int lda, int ldb, int ldc,
       float alphaC, const float* __restrict__ alphaPtr, int accum, int out_tf32)
{
    extern __shared__ float sh[];
    float* As = sh;
    float* Bs = sh + GS * 128 * GSTR;

    int tid = threadIdx.x;
    int m0 = blockIdx.y * 128, n0 = blockIdx.x * 128;

    int wid = tid >> 5, lane = tid & 31;
    int wm = (wid & 1) * 64, wn = (wid >> 1) * 32;
    int grp = lane >> 2, qid = lane & 3;

    float acc[4][4][4];
#pragma unroll
    for (int i = 0; i < 4; i++)
#pragma unroll
        for (int j = 0; j < 4; j++)
#pragma unroll
            for (int r = 0; r < 4; r++) acc[i][j][r] = 0.f;

    int ktiles = K / 32;

#define ISSUE_TILE(T) do {                                                    \
        int k0_ = (T) * 32;                                                   \
        int s_  = (T) % GS;                                                   \
        _Pragma("unroll")                                                     \
        for (int h_ = 0; h_ < 4; h_++) {                                      \
            int id_ = tid * 4 + h_;                                           \
            int r_ = id_ >> 3, kc_ = (id_ & 7) * 4;                           \
            int gm_ = m0 + r_;                                                \
            const float* ga_ = A + (size_t)(gm_ < M ? gm_ : 0) * lda + k0_ + kc_; \
            cp_async16(&As[(s_ * 128 + r_) * GSTR + kc_], ga_, gm_ < M ? 16 : 0); \
            int gn_ = n0 + r_;                                                \
            const float* gb_ = Bm + (size_t)(gn_ < Nn ? gn_ : 0) * ldb + k0_ + kc_; \
            cp_async16(&Bs[(s_ * 128 + r_) * GSTR + kc_], gb_, gn_ < Nn ? 16 : 0); \
        }                                                                     \
        asm volatile("cp.async.commit_group;");                               \
    } while (0)

    ISSUE_TILE(0);
    if (ktiles > 1) ISSUE_TILE(1);
    else asm volatile("cp.async.commit_group;");

    for (int t = 0; t < ktiles; t++) {
        asm volatile("cp.async.wait_group 1;");
        __syncthreads();
        int s = t % GS;
        const float* Ab = &As[(size_t)s * 128 * GSTR];
        const float* Bb = &Bs[(size_t)s * 128 * GSTR];
#pragma unroll
        for (int ks = 0; ks < 4; ks++) {
            int kb = ks * 8;
            unsigned a[4][4], b[4][2];
#pragma unroll
            for (int i = 0; i < 4; i++) {
                int rm = wm + i * 16 + grp;
                a[i][0] = __float_as_uint(Ab[rm * GSTR + kb + qid]);
                a[i][1] = __float_as_uint(Ab[(rm + 8) * GSTR + kb + qid]);
                a[i][2] = __float_as_uint(Ab[rm * GSTR + kb + qid + 4]);
                a[i][3] = __float_as_uint(Ab[(rm + 8) * GSTR + kb + qid + 4]);
            }
#pragma unroll
            for (int j = 0; j < 4; j++) {
                int cn = wn + j * 8 + grp;
                b[j][0] = __float_as_uint(Bb[cn * GSTR + kb + qid]);
                b[j][1] = __float_as_uint(Bb[cn * GSTR + kb + qid + 4]);
            }
#pragma unroll
            for (int i = 0; i < 4; i++)
#pragma unroll
                for (int j = 0; j < 4; j++)
                    mma_tf32(acc[i][j], a[i], b[j]);
        }
        if (t + 2 < ktiles) ISSUE_TILE(t + 2);
        else asm volatile("cp.async.commit_group;");
    }
#undef ISSUE_TILE

    float alpha = alphaC * (alphaPtr ? *alphaPtr : 1.f);
#pragma unroll
    for (int i = 0; i < 4; i++) {
#pragma unroll
        for (int j = 0; j < 4; j++) {
            int c0 = n0 + wn + j * 8 + qid * 2;
#pragma unroll
            for (int h = 0; h < 2; h++) {
                int r = m0 + wm + i * 16 + grp + h * 8;
                if (r >= M) continue;
                float v0 = acc[i][j][h * 2], v1 = acc[i][j][h * 2 + 1];
                if (bias) {
                    if (c0     < Nn) v0 += bias[c0];
                    if (c0 + 1 < Nn) v1 += bias[c0 + 1];
                }
                v0 *= alpha; v1 *= alpha;
                size_t off = (size_t)r * ldc + c0;
                if (out_tf32) { v0 = to_tf32(v0); v1 = to_tf32(v1); }
                if (c0 + 1 < Nn) {
                    if (accum) { v0 += Cm[off]; v1 += Cm[off + 1]; }
                    *(float2*)(Cm + off) = make_float2(v0, v1);
                } else if (c0 < Nn) {
                    if (accum) v0 += Cm[off];
                    Cm[off] = v0;
                }
            }
        }
    }
}

// ====== FA2-style flash (proven R16, unchanged) ======
#define FQ 64
#define FK 64
#define NKT 28
#define KS2 108
#define VS2 104
#define PSS2 24
#define OFF_KS 0
#define OFF_VS (64 * KS2)
#define OFF_PS (OFF_VS + 64 * VS2)
#define FLASH_FLOATS (OFF_PS + 4 * 32 * PSS2)

__global__ void __launch_bounds__(128, 3)
flash_k(const float* __restrict__ qkv, float* __restrict__ x2)
{
    extern __shared__ float sm[];
    float* Ks = sm + OFF_KS;
    float* Vs = sm + OFF_VS;

    int tid = threadIdx.x;
    int wid = tid >> 5, lane = tid & 31;
    int grp = lane >> 2, qid = lane & 3;
    float* Pw = sm + OFF_PS + wid * 32 * PSS2;

    int qb = blockIdx.x;
    int bb = blockIdx.y >> 3, hh = blockIdx.y & 7;
    const float scale = 0.10206207261596577f;
    size_t base = (size_t)bb * NTOK * (3 * CDIM) + (size_t)hh * HD;
    int wrow = qb * FQ + wid * 16;

    unsigned qf[12][4];
    {
        int r0 = wrow + grp, r1 = wrow + grp + 8;
        const float* q0p = qkv + base + (size_t)(r0 < NTOK ? r0 : 0) * (3 * CDIM);
        const float* q1p = qkv + base + (size_t)(r1 < NTOK ? r1 : 0) * (3 * CDIM);
        bool v0 = r0 < NTOK, v1 = r1 < NTOK;
#pragma unroll
        for (int ks = 0; ks < 12; ks++) {
            int c0 = ks * 8 + qid, c1 = c0 + 4;
            qf[ks][0] = __float_as_uint(v0 ? q0p[c0] : 0.f);
            qf[ks][1] = __float_as_uint(v1 ? q1p[c0] : 0.f);
            qf[ks][2] = __float_as_uint(v0 ? q0p[c1] : 0.f);
            qf[ks][3] = __float_as_uint(v1 ? q1p[c1] : 0.f);
        }
    }

    float mrow[2] = {-1e30f, -1e30f};
    float lrow[2] = {0.f, 0.f};
    float oacc[12][4];
#pragma unroll
    for (int j = 0; j < 12; j++)
#pragma unroll
        for (int r = 0; r < 4; r++) oacc[j][r] = 0.f;

    for (int t = 0; t < NKT; t++) {
        int t0 = t * FK;
        __syncthreads();
#pragma unroll
        for (int it = 0; it < 12; it++) {
            int idx = tid + it * 128;
            int r = idx / 24, d4 = (idx % 24) * 4;
            int gk = t0 + r;
            const float* rp = qkv + base + (size_t)(gk < NTOK ? gk : 0) * (3 * CDIM);
            int sz = gk < NTOK ? 16 : 0;
            cp_async16(&Ks[r * KS2 + d4], rp + CDIM + d4, sz);
            cp_async16(&Vs[r * VS2 + d4], rp + 2 * CDIM + d4, sz);
        }
        asm volatile("cp.async.commit_group;");
        asm volatile("cp.async.wait_group 0;");
        __syncthreads();

        float sacc[8][4];
#pragma unroll
        for (int j = 0; j < 8; j++)
#pragma unroll
            for (int r = 0; r < 4; r++) sacc[j][r] = 0.f;
#pragma unroll
        for (int ks = 0; ks < 12; ks++) {
            int kb = ks * 8;
            unsigned b[8][2];
#pragma unroll
            for (int j = 0; j < 8; j++) {
                int cn = j * 8 + grp;
                b[j][0] = __float_as_uint(Ks[cn * KS2 + kb + qid]);
                b[j][1] = __float_as_uint(Ks[cn * KS2 + kb + qid + 4]);
            }
#pragma unroll
            for (int j = 0; j < 8; j++)
                mma_tf32(sacc[j], qf[ks], b[j]);
        }

#pragma unroll
        for (int h = 0; h < 2; h++) {
            float vm = -1e30f;
#pragma unroll
            for (int j = 0; j < 8; j++)
#pragma unroll
                for (int u = 0; u < 2; u++) {
                    int c = t0 + j * 8 + qid * 2 + u;
                    if (c < NTOK) vm = fmaxf(vm, sacc[j][h * 2 + u] * scale);
                }
            vm = fmaxf(vm, __shfl_xor_sync(0xffffffffu, vm, 1));
            vm = fmaxf(vm, __shfl_xor_sync(0xffffffffu, vm, 2));
            float mn = fmaxf(mrow[h], vm);
            float al = __expf(mrow[h] - mn);
            mrow[h] = mn;
            float rs = 0.f;
#pragma unroll
            for (int j = 0; j < 8; j++)
#pragma unroll
                for (int u = 0; u < 2; u++) {
                    int c = t0 + j * 8 + qid * 2 + u;
                    float p = 0.f;
                    if (c < NTOK) p = __expf(sacc[j][h * 2 + u] * scale - mn);
                    sacc[j][h * 2 + u] = p;
                    rs += p;
                }
            rs += __shfl_xor_sync(0xffffffffu, rs, 1);
            rs += __shfl_xor_sync(0xffffffffu, rs, 2);
            lrow[h] = lrow[h] * al + rs;
#pragma unroll
            for (int j = 0; j < 12; j++) {
                oacc[j][h * 2]     *= al;
                oacc[j][h * 2 + 1] *= al;
            }
        }

#pragma unroll
        for (int hf = 0; hf < 2; hf++) {
            __syncwarp();
#pragma unroll
            for (int jj = 0; jj < 4; jj++)
#pragma unroll
                for (int u = 0; u < 2; u++) {
                    int cl = jj * 8 + qid * 2 + u;
                    Pw[cl * PSS2 + grp]     = to_tf32(sacc[hf * 4 + jj][u]);
                    Pw[cl * PSS2 + grp + 8] = to_tf32(sacc[hf * 4 + jj][2 + u]);
                }
            __syncwarp();
#pragma unroll
            for (int ks = 0; ks < 4; ks++) {
                int kb = ks * 8;
                unsigned a[4];
                a[0] = __float_as_uint(Pw[(kb + qid) * PSS2 + grp]);
                a[1] = __float_as_uint(Pw[(kb + qid) * PSS2 + grp + 8]);
                a[2] = __float_as_uint(Pw[(kb + qid + 4) * PSS2 + grp]);
                a[3] = __float_as_uint(Pw[(kb + qid + 4) * PSS2 + grp + 8]);
                int kv0 = hf * 32 + kb;
#pragma unroll
                for (int j = 0; j < 12; j++) {
                    int cn = j * 8 + grp;
                    unsigned b[2];
                    b[0] = __float_as_uint(Vs[(kv0 + qid) * VS2 + cn]);
                    b[1] = __float_as_uint(Vs[(kv0 + qid + 4) * VS2 + cn]);
                    mma_tf32(oacc[j], a, b);
                }
            }
        }
    }

#pragma unroll
    for (int h = 0; h < 2; h++) {
        int gq = wrow + grp + h * 8;
        if (gq >= NTOK) continue;
        float invl = 1.f / lrow[h];
        float* op = x2 + (size_t)bb * NTOK * CDIM + (size_t)gq * CDIM + hh * HD;
#pragma unroll
        for (int j = 0; j < 12; j++) {
            int cn = j * 8 + qid * 2;
            *(float2*)(op + cn) = make_float2(to_tf32(oacc[j][h * 2] * invl),
                                              to_tf32(oacc[j][h * 2 + 1] * invl));
        }
    }
}

// ---------------- pack QKV weights/bias (tf32) ----------------
__global__ void pack_qkv_k(const float* __restrict__ qw, const float* __restrict__ kw,
                           const float* __restrict__ vw, const float* __restrict__ qb,
                           const float* __restrict__ kb, const float* __restrict__ vb,
                           float* __restrict__ w, float* __restrict__ bias)
{
    int idx = blockIdx.x * 256 + threadIdx.x;
    int tot = 3 * CDIM * CDIM / 4;
    if (idx < tot) {
        int e = idx * 4;
        int which = e / (CDIM * CDIM);
        int off = e - which * (CDIM * CDIM);
        const float* src = which == 0 ? qw : which == 1 ? kw : vw;
        float4 v = *(const float4*)(src + off);
        v.x = to_tf32(v.x); v.y = to_tf32(v.y); v.z = to_tf32(v.z); v.w = to_tf32(v.w);
        *(float4*)(w + e) = v;
    }
    if (idx < 3 * CDIM) {
        int which = idx / CDIM, off = idx % CDIM;
        bias[idx] = (which == 0 ? qb : which == 1 ? kb : vb)[off];
    }
}

// ---------------- pack branch q weights (tf32) ----------------
__global__ void pack_q_k(const float* __restrict__ lw, const float* __restrict__ lb,
                         const float* __restrict__ gw, const float* __restrict__ gb,
                         float* __restrict__ wq2, float* __restrict__ bq2)
{
    int idx = blockIdx.x * 256 + threadIdx.x;
    const int W2 = 2 * CDIM * CDIM / 4;
    if (idx < W2) {
        int e = idx * 4;
        int row = e / CDIM, col = e % CDIM;
        const float* src = row < CDIM ? lw + (size_t)row * CDIM
                                      : gw + (size_t)(row - CDIM) * CDIM;
        float4 v = *(const float4*)(src + col);
        v.x = to_tf32(v.x); v.y = to_tf32(v.y); v.z = to_tf32(v.z); v.w = to_tf32(v.w);
        *(float4*)(wq2 + e) = v;
    }
    if (idx < 2 * CDIM)
        bq2[idx] = idx < CDIM ? lb[idx] : gb[idx - CDIM];
}

// ---------------- pack conv + out-proj weights (tf32) ----------------
__global__ void pack_misc_k(const float* __restrict__ convw,
                            const float* __restrict__ low, const float* __restrict__ gow,
                            float* __restrict__ wconv, float* __restrict__ wout)
{
    int idx = blockIdx.x * 256 + threadIdx.x;
    const int WC = CDIM * 512 / 4;
    const int WO = 2 * CDIM * CDIM / 4;
    if (idx < WC) {
        int e = idx * 4;
        float4 v = *(const float4*)(convw + e);
        v.x = to_tf32(v.x); v.y = to_tf32(v.y); v.z = to_tf32(v.z); v.w = to_tf32(v.w);
        *(float4*)(wconv + e) = v;
    } else if (idx < WC + WO) {
        int e = (idx - WC) * 4;
        const float* src = e < CDIM * CDIM ? low + e : gow + (e - CDIM * CDIM);
        float4 v = *(const float4*)src;
        v.x = to_tf32(v.x); v.y = to_tf32(v.y); v.z = to_tf32(v.z); v.w = to_tf32(v.w);
        *(float4*)(wout + e) = v;
    }
}

// ---------------- im2col patch gather (tf32 out) ----------------
__global__ void gather_k(const float* __restrict__ smri, float* __restrict__ pat) {
    int idx = blockIdx.x * 256 + threadIdx.x;
    if (idx >= BQ * NPATCH * 512 / 4) return;
    int e  = idx * 4;
    int kk = e & 511;
    int m  = e >> 9;
    int bb = m / NPATCH, p = m % NPATCH;
    int gx = p / (GD * GD), gy = (p / GD) % GD, gz = p % GD;
    int i = kk >> 6, j = (kk >> 3) & 7, kq = kk & 7;
    const float* src = smri + (((size_t)bb * IMG + gx * PSZ + i) * IMG + gy * PSZ + j) * IMG
                       + gz * PSZ + kq;
    float4 v = *(const float4*)src;
    v.x = to_tf32(v.x); v.y = to_tf32(v.y); v.z = to_tf32(v.z); v.w = to_tf32(v.w);
    *(float4*)(pat + e) = v;
}

// ---------------- LN(patch embed) + cls + pos_embed (tf32 out) ----------------
__global__ void ln_pos_k(const float* __restrict__ tmp, const float* __restrict__ g,
                         const float* __restrict__ b, const float* __restrict__ cls,
                         const float* __restrict__ pos, float* __restrict__ x)
{
    int bt = blockIdx.x;
    int bb = bt / NTOK, t = bt % NTOK;
    int tid = threadIdx.x;
    float* out = x + (size_t)bt * CDIM;
    const float* pp = pos + (size_t)t * CDIM;
    if (t == 0) {
        for (int c = tid; c < CDIM; c += 256) out[c] = to_tf32(cls[c] + pp[c]);
        return;
    }
    const float* row = tmp + ((size_t)bb * NPATCH + (t - 1)) * CDIM;
    __shared__ float red[256];
    float s = 0.f, s2 = 0.f;
    for (int c = tid; c < CDIM; c += 256) { float v = row[c]; s += v; s2 += v * v; }
    red[tid] = s; __syncthreads();
    for (int st = 128; st > 0; st >>= 1) { if (tid < st) red[tid] += red[tid + st]; __syncthreads(); }
    float mean = red[0] / CDIM; __syncthreads();
    red[tid] = s2; __syncthreads();
    for (int st = 128; st > 0; st >>= 1) { if (tid < st) red[tid] += red[tid + st]; __syncthreads(); }
    float var = red[0] / CDIM - mean * mean;
    float inv = rsqrtf(var + 1e-5f);
    for (int c = tid; c < CDIM; c += 256)
        out[c] = to_tf32((row[c] - mean) * inv * g[c] + b[c] + pp[c]);
}

// ======= branch attention via linearity: u = W_k^T q, s = u·x2, y = P^T x2 =======
// o index: o = br*16 + bb*8 + hh

// U[o][c] = sum_j q0[bb,br,hh,j] * W_k[hh*HD+j][c];  cb[o] = q0·b_k
__global__ void mk_u_k(const float* __restrict__ q0,
                       const float* __restrict__ lw, const float* __restrict__ lb,
                       const float* __restrict__ gw, const float* __restrict__ gb,
                       float* __restrict__ U, float* __restrict__ cb,
                       float* __restrict__ ypartzero)
{
    int o = blockIdx.x;
    int br = o >> 4, bb = (o >> 3) & 1, hh = o & 7;
    const float* W = (br ? gw : lw) + (size_t)CDIM * CDIM;  // K block rows
    const float* B = (br ? gb : lb) + CDIM;
    const float* q = q0 + bb * 2 * CDIM + br * CDIM + hh * HD;
    int tid = threadIdx.x;
    if (tid == 0) {
        float c = 0.f;
        for (int j = 0; j < HD; j++) c += q[j] * B[hh * HD + j];
        cb[o] = c;
    }
    for (int c = tid; c < CDIM; c += 256) {
        float acc = 0.f;
        for (int j = 0; j < HD; j++)
            acc += q[j] * W[(size_t)(hh * HD + j) * CDIM + c];
        U[o * CDIM + c] = acc;
    }
    // zero ypart slab for this o
    for (int i = tid; i < NCH * CDIM; i += 256)
        ypartzero[(size_t)o * NCH * CDIM + i] = 0.f;
}

// S2[o][t] = (U[o]·x2[bb,t] + cb[o]) * scale   (one block per (bb,t), warp per 2 outs)
__global__ void score_k(const float* __restrict__ x2, const float* __restrict__ U,
                        const float* __restrict__ cb, float* __restrict__ S2)
{
    int blk = blockIdx.x;
    int bb = blk / NTOK, t = blk % NTOK;
    const float* xr = x2 + (size_t)(bb * NTOK + t) * CDIM;
    int wid = threadIdx.x >> 5, lane = threadIdx.x & 31;
    const float scale = 0.10206207261596577f;
#pragma unroll
    for (int kk = 0; kk < 2; kk++) {
        int k = wid * 2 + kk;                      // 0..15
        int o = ((k >> 3) << 4) + bb * 8 + (k & 7);
        const float* u = U + o * CDIM;
        float acc = 0.f;
        for (int c = lane; c < CDIM; c += 32) acc += xr[c] * u[c];
#pragma unroll
        for (int off = 16; off; off >>= 1) acc += __shfl_xor_sync(0xffffffffu, acc, off);
        if (lane == 0) S2[(size_t)o * NTOK + t] = (acc + cb[o]) * scale;
    }
}

// softmax over t for each of 32 rows
__global__ void softmax32_k(float* __restrict__ S2)
{
    int o = blockIdx.x;
    float* p = S2 + (size_t)o * NTOK;
    __shared__ float red[256];
    int tid = threadIdx.x;
    float mx = -1e30f;
    for (int t = tid; t < NTOK; t += 256) mx = fmaxf(mx, p[t]);
    red[tid] = mx; __syncthreads();
    for (int s = 128; s; s >>= 1) { if (tid < s) red[tid] = fmaxf(red[tid], red[tid + s]); __syncthreads(); }
    mx = red[0]; __syncthreads();
    float sm = 0.f;
    for (int t = tid; t < NTOK; t += 256) { float e = __expf(p[t] - mx); p[t] = e; sm += e; }
    red[tid] = sm; __syncthreads();
    for (int s = 128; s; s >>= 1) { if (tid < s) red[tid] += red[tid + s]; __syncthreads(); }
    float inv = 1.f / red[0];
    for (int t = tid; t < NTOK; t += 256) p[t] *= inv;
}

// ypart[o][ch][c] = sum_{t in chunk} P[o][t] * x2[bb,t][c]   (block = (bb, ch))
__global__ void y_k(const float* __restrict__ x2, const float* __restrict__ S2,
                    float* __restrict__ ypart)
{
    int bb = blockIdx.x & 1, ch = blockIdx.x >> 1;
    int t0 = ch * CHSZ;
    int t1 = t0 + CHSZ; if (t1 > NTOK) t1 = NTOK;
    __shared__ float ps[16][CHSZ];
    int tid = threadIdx.x;
    for (int i = tid; i < 16 * CHSZ; i += 256) {
        int k = i / CHSZ, tt = i % CHSZ;
        int o = ((k >> 3) << 4) + bb * 8 + (k & 7);
        ps[k][tt] = (t0 + tt < t1) ? S2[(size_t)o * NTOK + t0 + tt] : 0.f;
    }
    __syncthreads();
    float acc[16][3];
#pragma unroll
    for (int k = 0; k < 16; k++)
#pragma unroll
        for (int u = 0; u < 3; u++) acc[k][u] = 0.f;
    for (int tt = 0; tt < t1 - t0; tt++) {
        const float* xr = x2 + (size_t)(bb * NTOK + t0 + tt) * CDIM;
        float xv0 = xr[tid], xv1 = xr[tid + 256], xv2 = xr[tid + 512];
#pragma unroll
        for (int k = 0; k < 16; k++) {
            float pv = ps[k][tt];
            acc[k][0] += pv * xv0;
            acc[k][1] += pv * xv1;
            acc[k][2] += pv * xv2;
        }
    }
#pragma unroll
    for (int k = 0; k < 16; k++) {
        int o = ((k >> 3) << 4) + bb * 8 + (k & 7);
        float* yp = ypart + ((size_t)o * NCH + ch) * CDIM;
        yp[tid] = acc[k][0];
        yp[tid + 256] = acc[k][1];
        yp[tid + 512] = acc[k][2];
    }
}

// oc[br,bb][hh*HD+j] = W_v[hh*HD+j]·y[o] + b_v[hh*HD+j]
__global__ void o_k(const float* __restrict__ ypart,
                    const float* __restrict__ lw, const float* __restrict__ lb,
                    const float* __restrict__ gw, const float* __restrict__ gb,
                    float* __restrict__ oc)
{
    int o = blockIdx.x;
    int br = o >> 4, bb = (o >> 3) & 1, hh = o & 7;
    __shared__ float ys[CDIM];
    int tid = threadIdx.x;
    for (int c = tid; c < CDIM; c += 256) {
        float s = 0.f;
        for (int ch = 0; ch < NCH; ch++)
            s += ypart[((size_t)o * NCH + ch) * CDIM + c];
        ys[c] = s;
    }
    __syncthreads();
    const float* W = (br ? gw : lw) + (size_t)2 * CDIM * CDIM;  // V block
    const float* B = (br ? gb : lb) + 2 * CDIM;
    if (tid < HD) {
        int row = hh * HD + tid;
        const float* wr = W + (size_t)row * CDIM;
        float acc = B[row];
        for (int c = 0; c < CDIM; c++) acc += wr[c] * ys[c];
        oc[(br * BQ + bb) * CDIM + hh * HD + tid] = to_tf32(acc);
    }
}

// ---------------- LN + head on CLS ----------------
__global__ void head_k(const float* __restrict__ fin, const float* __restrict__ g,
                       const float* __restrict__ b, const float* __restrict__ hw,
                       const float* __restrict__ hb, float* __restrict__ out)
{
    int bb = blockIdx.x;
    const float* row = fin + bb * CDIM;
    __shared__ float red[256];
    __shared__ float sn[CDIM];
    int tid = threadIdx.x;
    float s = 0.f, s2 = 0.f;
    for (int c = tid; c < CDIM; c += 256) { float v = row[c]; s += v; s2 += v * v; }
    red[tid] = s; __syncthreads();
    for (int st = 128; st > 0; st >>= 1) { if (tid < st) red[tid] += red[tid + st]; __syncthreads(); }
    float mean = red[0] / CDIM; __syncthreads();
    red[tid] = s2; __syncthreads();
    for (int st = 128; st > 0; st >>= 1) { if (tid < st) red[tid] += red[tid + st]; __syncthreads(); }
    float var = red[0] / CDIM - mean * mean;
    float inv = rsqrtf(var + 1e-5f);
    for (int c = tid; c < CDIM; c += 256) sn[c] = (row[c] - mean) * inv * g[c] + b[c];
    __syncthreads();
    if (tid < NCLS) {
        float acc = hb[tid];
        for (int c = 0; c < CDIM; c++) acc += sn[c] * hw[tid * CDIM + c];
        out[bb * NCLS + tid] = acc;
    }
}

// ---------------- host ----------------
static inline int cdiv(int a, int b) { return (a + b - 1) / b; }

static void gemm_nt(const float* A, const float* B, const float* bias, float* C,
                    int M, int Nn, int K, int lda, int ldb, int ldc,
                    float alphaC = 1.f, const float* alphaPtr = nullptr, int accum = 0,
                    int out_tf32 = 0)
{
    dim3 grid(cdiv(Nn, 128), cdiv(M, 128));
    gemm_k<<<grid, 256, GEMM_SMEM>>>(A, B, bias, C, M, Nn, K, lda, ldb, ldc,
                                     alphaC, alphaPtr, accum, out_tf32);
}

extern "C" void kernel_launch(void* const* d_in, const int* in_sizes, int n_in,
                              void* d_out, int out_size)
{
    const float* smri     = (const float*)d_in[0];
    const float* conv_w   = (const float*)d_in[2];
    const float* conv_b   = (const float*)d_in[3];
    const float* pe_ln_g  = (const float*)d_in[4];
    const float* pe_ln_b  = (const float*)d_in[5];
    const float* q_w      = (const float*)d_in[6];
    const float* q_b      = (const float*)d_in[7];
    const float* k_w      = (const float*)d_in[8];
    const float* k_b      = (const float*)d_in[9];
    const float* v_w      = (const float*)d_in[10];
    const float* v_b      = (const float*)d_in[11];
    const float* loc_in_w = (const float*)d_in[13];
    const float* loc_in_b = (const float*)d_in[14];
    const float* loc_out_w= (const float*)d_in[15];
    const float* loc_out_b= (const float*)d_in[16];
    const float* glob_in_w = (const float*)d_in[17];
    const float* glob_in_b = (const float*)d_in[18];
    const float* glob_out_w= (const float*)d_in[19];
    const float* glob_out_b= (const float*)d_in[20];
    const float* w_local  = (const float*)d_in[21];
    const float* w_global = (const float*)d_in[22];
    const float* cls_tok  = (const float*)d_in[23];
    const float* pos_emb  = (const float*)d_in[24];
    const float* head_ln_g= (const float*)d_in[25];
    const float* head_ln_b= (const float*)d_in[26];
    const float* head_w   = (const float*)d_in[27];
    const float* head_b   = (const float*)d_in[28];
    float* out = (float*)d_out;

    float *pat, *tmp, *x, *wconv, *wqkv, *bqkv, *qkv, *x2, *wq2, *bq2, *wout,
          *q0, *U, *cb, *S2, *ypart, *oc, *fin;
    cudaGetSymbolAddress((void**)&pat,   g_pat);
    cudaGetSymbolAddress((void**)&tmp,   g_tmp);
    cudaGetSymbolAddress((void**)&x,     g_x);
    cudaGetSymbolAddress((void**)&wconv, g_wconv);
    cudaGetSymbolAddress((void**)&wqkv,  g_wqkv);
    cudaGetSymbolAddress((void**)&bqkv,  g_bqkv);
    cudaGetSymbolAddress((void**)&qkv,   g_qkv);
    cudaGetSymbolAddress((void**)&x2,    g_x2);
    cudaGetSymbolAddress((void**)&wq2,   g_wq2);
    cudaGetSymbolAddress((void**)&bq2,   g_bq2);
    cudaGetSymbolAddress((void**)&wout,  g_wout);
    cudaGetSymbolAddress((void**)&q0,    g_q0);
    cudaGetSymbolAddress((void**)&U,     g_U);
    cudaGetSymbolAddress((void**)&cb,    g_cb);
    cudaGetSymbolAddress((void**)&S2,    g_S2);
    cudaGetSymbolAddress((void**)&ypart, g_ypart);
    cudaGetSymbolAddress((void**)&oc,    g_oc);
    cudaGetSymbolAddress((void**)&fin,   g_fin);

    const size_t sT = (size_t)NTOK * CDIM;

    static int init_done = 0;
    if (!init_done) {
        cudaFuncSetAttribute(flash_k, cudaFuncAttributeMaxDynamicSharedMemorySize,
                             FLASH_FLOATS * 4);
        cudaFuncSetAttribute(gemm_k, cudaFuncAttributeMaxDynamicSharedMemorySize,
                             GEMM_SMEM);
        init_done = 1;
    }

    // 0) pack weights
    pack_qkv_k<<<cdiv(3 * CDIM * CDIM / 4, 256), 256>>>(q_w, k_w, v_w, q_b, k_b, v_b,
                                                        wqkv, bqkv);
    pack_q_k<<<cdiv(2 * CDIM * CDIM / 4, 256), 256>>>(loc_in_w, loc_in_b,
                                                      glob_in_w, glob_in_b, wq2, bq2);
    pack_misc_k<<<cdiv((CDIM * 512 + 2 * CDIM * CDIM) / 4, 256), 256>>>(
        conv_w, loc_out_w, glob_out_w, wconv, wout);

    // 1) patch im2col (tf32) + embed GEMM
    gather_k<<<cdiv(BQ * NPATCH * 512 / 4, 256), 256>>>(smri, pat);
    gemm_nt(pat, wconv, conv_b, tmp, BQ * NPATCH, CDIM, 512, 512, 512, CDIM);

    // 2) LN + cls + pos (tf32 out)
    ln_pos_k<<<BQ * NTOK, 256>>>(tmp, pe_ln_g, pe_ln_b, cls_tok, pos_emb, x);

    // 3) fused QKV projection (tf32 out -> flash consumes raw bits)
    gemm_nt(x, wqkv, bqkv, qkv, BQ * NTOK, 3 * CDIM, CDIM, CDIM, CDIM, 3 * CDIM,
            1.f, nullptr, 0, 1);

    // 4-6) FA2 flash attention (region bias softmax-invariant -> dropped)
    flash_k<<<dim3(cdiv(NTOK, FQ), BQ * NHEAD), 128, FLASH_FLOATS * 4>>>(qkv, x2);

    // 7) branch attention via linearity (KV GEMM eliminated)
    gemm_nt(x2, wq2, bq2, q0, BQ, 2 * CDIM, CDIM, (int)sT, CDIM, 2 * CDIM);
    mk_u_k<<<32, 256>>>(q0, loc_in_w, loc_in_b, glob_in_w, glob_in_b, U, cb, ypart);
    score_k<<<BQ * NTOK, 256>>>(x2, U, cb, S2);
    softmax32_k<<<32, 256>>>(S2);
    y_k<<<2 * NCH, 256>>>(x2, S2, ypart);
    o_k<<<32, 256>>>(ypart, loc_in_w, loc_in_b, glob_in_w, glob_in_b, oc);

    // out-projections (weighted accumulate into fin)
    gemm_nt(oc, wout, loc_out_b, fin, BQ, CDIM, CDIM, CDIM, CDIM, CDIM,
            1.f, w_local, 0);
    gemm_nt(oc + BQ * CDIM, wout + (size_t)CDIM * CDIM, glob_out_b, fin,
            BQ, CDIM, CDIM, CDIM, CDIM, CDIM, 1.f, w_global, 1);

    // 8) head on CLS
    head_k<<<BQ, 256>>>(fin, head_ln_g, head_ln_b, head_w, head_b, out);
}